// round 1
// baseline (speedup 1.0000x reference)
#include <cuda_runtime.h>
#include <math.h>

#define NN 50000
#define EE 400000
#define GG 64
#define HC 256   // feature width of every layer (H*HID or HC)

// ---------------- scratch (static device globals; no allocations) ----------
__device__ float g_feat [NN * HC];   // layer input/output features
__device__ float g_h    [NN * HC];   // transformed features h = in @ W
__device__ float g_agg  [NN * HC];   // aggregation accumulator (also MLP y [N,32])
__device__ float g_alpha[EE * 8];    // edge logits -> p
__device__ float g_as   [NN * 8];
__device__ float g_ad   [NN * 8];
__device__ float g_m    [NN * 8];
__device__ float g_den  [NN * 8];
__device__ float g_Ve   [5 * 8];     // per-layer edge-attention projection
__device__ float g_pool [GG * 32];
__device__ float g_cnt  [GG];

// ---------------- helpers ---------------------------------------------------
__device__ __forceinline__ float atomicMaxFloat(float* addr, float val) {
    if (val >= 0.0f)
        return __int_as_float(atomicMax((int*)addr, __float_as_int(val)));
    else
        return __uint_as_float(atomicMin((unsigned int*)addr, __float_as_uint(val)));
}

__device__ __forceinline__ float elu1(float x) {
    return x > 0.0f ? x : expm1f(x);
}

// ---------------- GEMM: C[N,M] = A[N,K] @ B[K,M] (+bias)(+act) -------------
// act: 0 = none, 1 = exact GELU
#define BM 64
#define BN 64
#define BK 16
__global__ __launch_bounds__(256)
void gemm_k(const float* __restrict__ A, const float* __restrict__ B,
            float* __restrict__ C, int N, int K, int M,
            const float* __restrict__ bias, int act)
{
    __shared__ float As[BK][BM];
    __shared__ float Bs[BK][BN];
    int tid = threadIdx.x;
    int bm0 = blockIdx.x * BM;
    int bn0 = blockIdx.y * BN;
    int ty = tid >> 4, tx = tid & 15;

    int ar = tid >> 2, ak = (tid & 3) * 4;          // A tile load map
    int bk = tid >> 4, bc = (tid & 15) * 4;         // B tile load map

    float acc[4][4];
    #pragma unroll
    for (int i = 0; i < 4; i++)
        #pragma unroll
        for (int j = 0; j < 4; j++) acc[i][j] = 0.0f;

    for (int k0 = 0; k0 < K; k0 += BK) {
        float4 av = make_float4(0.f, 0.f, 0.f, 0.f);
        int arow = bm0 + ar;
        if (arow < N) av = *(const float4*)&A[(size_t)arow * K + k0 + ak];
        As[ak + 0][ar] = av.x; As[ak + 1][ar] = av.y;
        As[ak + 2][ar] = av.z; As[ak + 3][ar] = av.w;

        float4 bv = make_float4(0.f, 0.f, 0.f, 0.f);
        if (bn0 + bc < M) bv = *(const float4*)&B[(size_t)(k0 + bk) * M + bn0 + bc];
        *(float4*)&Bs[bk][bc] = bv;
        __syncthreads();

        #pragma unroll
        for (int k = 0; k < BK; k++) {
            float4 a4 = *(const float4*)&As[k][ty * 4];
            float4 b4 = *(const float4*)&Bs[k][tx * 4];
            float a[4] = {a4.x, a4.y, a4.z, a4.w};
            float b[4] = {b4.x, b4.y, b4.z, b4.w};
            #pragma unroll
            for (int i = 0; i < 4; i++)
                #pragma unroll
                for (int j = 0; j < 4; j++)
                    acc[i][j] = fmaf(a[i], b[j], acc[i][j]);
        }
        __syncthreads();
    }

    #pragma unroll
    for (int i = 0; i < 4; i++) {
        int r = bm0 + ty * 4 + i;
        if (r >= N) continue;
        #pragma unroll
        for (int j = 0; j < 4; j++) {
            int c = bn0 + tx * 4 + j;
            if (c >= M) continue;
            float v = acc[i][j];
            if (bias) v += bias[c];
            if (act == 1) v = 0.5f * v * (1.0f + erff(v * 0.70710678118654752f));
            C[(size_t)r * M + c] = v;
        }
    }
}

// ---------------- Ve[d,h] = sum_c We[d, h*C+c] * ae[h*C+c] ------------------
__global__ void ve_k(const float* __restrict__ We, const float* __restrict__ ae, int H)
{
    int tid = threadIdx.x;
    if (tid >= 5 * H) return;
    int d = tid / H, h = tid % H;
    int C = 256 / H;
    float s = 0.0f;
    for (int c = 0; c < C; c++) s += We[d * 256 + h * C + c] * ae[h * C + c];
    g_Ve[tid] = s;
}

// -------- per-node attention scores + init m/den ---------------------------
__global__ void node_att_k(const float* __restrict__ hf,
                           const float* __restrict__ att_s,
                           const float* __restrict__ att_d,
                           float* __restrict__ as_, float* __restrict__ ad_,
                           float* __restrict__ m, float* __restrict__ den,
                           int N, int H)
{
    int idx = blockIdx.x * blockDim.x + threadIdx.x;
    if (idx >= N * H) return;
    int C = 256 / H;
    int n = idx / H, hh = idx % H;
    const float4* hp = (const float4*)(hf + (size_t)n * 256 + hh * C);
    const float4* sp = (const float4*)(att_s + hh * C);
    const float4* dp = (const float4*)(att_d + hh * C);
    float ss = 0.0f, dd = 0.0f;
    for (int i = 0; i < C / 4; i++) {
        float4 v = hp[i], a = sp[i], b = dp[i];
        ss += v.x * a.x + v.y * a.y + v.z * a.z + v.w * a.w;
        dd += v.x * b.x + v.y * b.y + v.z * b.z + v.w * b.w;
    }
    as_[idx] = ss;
    ad_[idx] = dd;
    m[idx]   = -INFINITY;
    den[idx] = 0.0f;
}

// -------- zero a float buffer (float4 granularity) --------------------------
__global__ void zero_k(float* __restrict__ p, int n4)
{
    int i = blockIdx.x * blockDim.x + threadIdx.x;
    if (i < n4) ((float4*)p)[i] = make_float4(0.f, 0.f, 0.f, 0.f);
}

// -------- edge pass 1: alpha + segment max ----------------------------------
template <int H>
__global__ void edge_alpha_k(const int* __restrict__ src, const int* __restrict__ dst,
                             const float* __restrict__ ea,
                             const float* __restrict__ as_, const float* __restrict__ ad_,
                             float* __restrict__ alpha, float* __restrict__ m, int E)
{
    __shared__ float sVe[5 * H];
    if (threadIdx.x < 5 * H) sVe[threadIdx.x] = g_Ve[threadIdx.x];
    __syncthreads();
    int e = blockIdx.x * blockDim.x + threadIdx.x;
    if (e >= E) return;
    int s = src[e], d = dst[e];
    float eav[5];
    #pragma unroll
    for (int i = 0; i < 5; i++) eav[i] = ea[e * 5 + i];
    #pragma unroll
    for (int h = 0; h < H; h++) {
        float aeh = 0.0f;
        #pragma unroll
        for (int i = 0; i < 5; i++) aeh = fmaf(eav[i], sVe[i * H + h], aeh);
        float v = as_[s * H + h] + ad_[d * H + h] + aeh;
        v = v > 0.0f ? v : 0.2f * v;                 // leaky_relu 0.2
        alpha[e * H + h] = v;
        atomicMaxFloat(&m[d * H + h], v);
    }
}

// -------- edge pass 2: p = exp(alpha - m), segment sum -----------------------
template <int H>
__global__ void edge_p_k(const int* __restrict__ dst, float* __restrict__ alpha,
                         const float* __restrict__ m, float* __restrict__ den, int E)
{
    int e = blockIdx.x * blockDim.x + threadIdx.x;
    if (e >= E) return;
    int d = dst[e];
    #pragma unroll
    for (int h = 0; h < H; h++) {
        float pv = expf(alpha[e * H + h] - m[d * H + h]);
        alpha[e * H + h] = pv;
        atomicAdd(&den[d * H + h], pv);
    }
}

// -------- edge pass 3: weighted message aggregation (1 warp / edge) ---------
__global__ void edge_agg_k(const int* __restrict__ src, const int* __restrict__ dst,
                           const float* __restrict__ p, const float* __restrict__ den,
                           const float* __restrict__ hfeat, float* __restrict__ agg,
                           int E, int H)
{
    int gw = (blockIdx.x * blockDim.x + threadIdx.x) >> 5;
    int lane = threadIdx.x & 31;
    if (gw >= E) return;
    int s = src[gw], d = dst[gw];
    int c1 = lane * 4, c2 = 128 + lane * 4;
    int h1 = (c1 * H) >> 8, h2 = (c2 * H) >> 8;
    float w1 = p[gw * H + h1] / (den[d * H + h1] + 1e-16f);
    float w2 = p[gw * H + h2] / (den[d * H + h2] + 1e-16f);
    float4 v1 = *(const float4*)&hfeat[(size_t)s * 256 + c1];
    float4 v2 = *(const float4*)&hfeat[(size_t)s * 256 + c2];
    atomicAdd((float4*)&agg[(size_t)d * 256 + c1],
              make_float4(v1.x * w1, v1.y * w1, v1.z * w1, v1.w * w1));
    atomicAdd((float4*)&agg[(size_t)d * 256 + c2],
              make_float4(v2.x * w2, v2.y * w2, v2.z * w2, v2.w * w2));
}

// -------- node finish: out = elu(agg + bias) --------------------------------
__global__ void finish_k(const float* __restrict__ agg, const float* __restrict__ bias,
                         float* __restrict__ outf, int N)
{
    int i = blockIdx.x * blockDim.x + threadIdx.x;
    if (i >= N * 64) return;
    int c4 = i & 63;
    float4 v = ((const float4*)agg)[i];
    float4 b = ((const float4*)bias)[c4];
    v.x = elu1(v.x + b.x);
    v.y = elu1(v.y + b.y);
    v.z = elu1(v.z + b.z);
    v.w = elu1(v.w + b.w);
    ((float4*)outf)[i] = v;
}

// -------- pooling ------------------------------------------------------------
__global__ void pool_zero_k()
{
    int t = blockIdx.x * blockDim.x + threadIdx.x;
    if (t < GG * 32) g_pool[t] = 0.0f;
    if (t < GG)      g_cnt[t]  = 0.0f;
}

__global__ void pool_acc_k(const float* __restrict__ y, const int* __restrict__ batch, int N)
{
    int idx = blockIdx.x * blockDim.x + threadIdx.x;
    if (idx >= N * 8) return;
    int n = idx >> 3, q = idx & 7;
    int g = batch[n];
    float4 v = ((const float4*)(y + (size_t)n * 32))[q];
    atomicAdd((float4*)&g_pool[g * 32 + q * 4], v);
    if (q == 0) atomicAdd(&g_cnt[g], 1.0f);
}

__global__ void pool_fin_k(float* __restrict__ out)
{
    int t = blockIdx.x * blockDim.x + threadIdx.x;
    if (t < GG * 32) out[t] = g_pool[t] / fmaxf(g_cnt[t >> 5], 1.0f);
}

// ============================================================================
static void run_gat_layer(const float* in, int K,
                          const float* W, const float* as_att, const float* ad_att,
                          const float* We, const float* ae_att, const float* bias,
                          int H,
                          const int* src, const int* dst, const float* ea,
                          float* feat, float* h, float* agg, float* alpha,
                          float* as_, float* ad_, float* m, float* den)
{
    // 1. h = in @ W  [N,256]
    dim3 gg((NN + BM - 1) / BM, (HC + BN - 1) / BN);
    gemm_k<<<gg, 256>>>(in, W, h, NN, K, HC, nullptr, 0);
    // 2. node attention scores + init m/den
    node_att_k<<<(NN * H + 255) / 256, 256>>>(h, as_att, ad_att, as_, ad_, m, den, NN, H);
    // 3. zero aggregation buffer
    zero_k<<<(NN * HC / 4 + 255) / 256, 256>>>(agg, NN * HC / 4);
    // 4. edge-attr projection Ve
    ve_k<<<1, 64>>>(We, ae_att, H);
    // 5-6. edge softmax passes
    int eb = (EE + 255) / 256;
    if (H == 8) {
        edge_alpha_k<8><<<eb, 256>>>(src, dst, ea, as_, ad_, alpha, m, EE);
        edge_p_k<8><<<eb, 256>>>(dst, alpha, m, den, EE);
    } else {
        edge_alpha_k<1><<<eb, 256>>>(src, dst, ea, as_, ad_, alpha, m, EE);
        edge_p_k<1><<<eb, 256>>>(dst, alpha, m, den, EE);
    }
    // 7. weighted aggregation (1 warp per edge)
    edge_agg_k<<<(EE * 32 + 255) / 256, 256>>>(src, dst, alpha, den, h, agg, EE, H);
    // 8. bias + elu -> feat
    finish_k<<<(NN * 64 + 255) / 256, 256>>>(agg, bias, feat, NN);
}

extern "C" void kernel_launch(void* const* d_in, const int* in_sizes, int n_in,
                              void* d_out, int out_size)
{
    const float* x     = (const float*)d_in[0];
    const int*   ei    = (const int*)  d_in[1];
    const float* ea    = (const float*)d_in[2];
    const int*   batch = (const int*)  d_in[3];
    const float* W1  = (const float*)d_in[4];
    const float* as1 = (const float*)d_in[5];
    const float* ad1 = (const float*)d_in[6];
    const float* We1 = (const float*)d_in[7];
    const float* ae1 = (const float*)d_in[8];
    const float* b1  = (const float*)d_in[9];
    const float* W2  = (const float*)d_in[10];
    const float* as2 = (const float*)d_in[11];
    const float* ad2 = (const float*)d_in[12];
    const float* We2 = (const float*)d_in[13];
    const float* ae2 = (const float*)d_in[14];
    const float* b2  = (const float*)d_in[15];
    const float* W3  = (const float*)d_in[16];
    const float* as3 = (const float*)d_in[17];
    const float* ad3 = (const float*)d_in[18];
    const float* We3 = (const float*)d_in[19];
    const float* ae3 = (const float*)d_in[20];
    const float* b3  = (const float*)d_in[21];
    const float* fcW1 = (const float*)d_in[22];
    const float* fcb1 = (const float*)d_in[23];
    const float* fcW2 = (const float*)d_in[24];
    const float* fcb2 = (const float*)d_in[25];

    const int* src = ei;
    const int* dst = ei + EE;

    float *feat, *h, *agg, *alpha, *as_, *ad_, *m, *den;
    cudaGetSymbolAddress((void**)&feat,  g_feat);
    cudaGetSymbolAddress((void**)&h,     g_h);
    cudaGetSymbolAddress((void**)&agg,   g_agg);
    cudaGetSymbolAddress((void**)&alpha, g_alpha);
    cudaGetSymbolAddress((void**)&as_,   g_as);
    cudaGetSymbolAddress((void**)&ad_,   g_ad);
    cudaGetSymbolAddress((void**)&m,     g_m);
    cudaGetSymbolAddress((void**)&den,   g_den);

    // --- 3 GAT layers (ELU between) ---
    run_gat_layer(x,    128, W1, as1, ad1, We1, ae1, b1, 8, src, dst, ea,
                  feat, h, agg, alpha, as_, ad_, m, den);
    run_gat_layer(feat, 256, W2, as2, ad2, We2, ae2, b2, 8, src, dst, ea,
                  feat, h, agg, alpha, as_, ad_, m, den);
    run_gat_layer(feat, 256, W3, as3, ad3, We3, ae3, b3, 1, src, dst, ea,
                  feat, h, agg, alpha, as_, ad_, m, den);

    // --- MLP head: gelu(feat@fcW1 + fcb1) @ fcW2 + fcb2 ---
    dim3 g1((NN + BM - 1) / BM, (256 + BN - 1) / BN);
    gemm_k<<<g1, 256>>>(feat, fcW1, h, NN, 256, 256, fcb1, 1);
    dim3 g2((NN + BM - 1) / BM, 1);
    gemm_k<<<g2, 256>>>(h, fcW2, agg, NN, 256, 32, fcb2, 0);

    // --- global mean pool over batch ids ---
    pool_zero_k<<<(GG * 32 + 255) / 256, 256>>>();
    pool_acc_k<<<(NN * 8 + 255) / 256, 256>>>(agg, batch, NN);
    pool_fin_k<<<(GG * 32 + 255) / 256, 256>>>((float*)d_out);
}

// round 3
// speedup vs baseline: 1.0956x; 1.0956x over previous
#include <cuda_runtime.h>
#include <math.h>
#include <stdint.h>

#define NN 50000
#define EE 400000
#define GG 64
#define HC 256

// ---------------- scratch (static device globals) ---------------------------
__device__ float g_feat [NN * HC];
__device__ float g_h    [NN * HC];
__device__ float g_agg  [NN * HC];
__device__ float g_alpha[EE * 8];
__device__ float g_as   [NN * 8];
__device__ float g_ad   [NN * 8];
__device__ float g_m    [NN * 8];
__device__ float g_den  [NN * 8];
__device__ float g_Ve   [5 * 8];
__device__ float g_pool [GG * 32];
__device__ float g_cnt  [GG];
__device__ float g_bt   [256 * 256];   // transposed weights [ncols, K]

// ---------------- helpers ---------------------------------------------------
__device__ __forceinline__ float atomicMaxFloat(float* addr, float val) {
    if (val >= 0.0f)
        return __int_as_float(atomicMax((int*)addr, __float_as_int(val)));
    else
        return __uint_as_float(atomicMin((unsigned int*)addr, __float_as_uint(val)));
}
__device__ __forceinline__ float elu1(float x) { return x > 0.0f ? x : expm1f(x); }

__device__ __forceinline__ float tf32hi(float x) {
    uint32_t u;
    asm("cvt.rna.tf32.f32 %0, %1;" : "=r"(u) : "f"(x));
    return __uint_as_float(u);
}

__device__ __forceinline__ void mma_tf32(float* d, const uint32_t* a,
                                         uint32_t b0, uint32_t b1) {
    asm volatile(
        "mma.sync.aligned.m16n8k8.row.col.f32.tf32.tf32.f32 "
        "{%0,%1,%2,%3}, {%4,%5,%6,%7}, {%8,%9}, {%0,%1,%2,%3};"
        : "+f"(d[0]), "+f"(d[1]), "+f"(d[2]), "+f"(d[3])
        : "r"(a[0]), "r"(a[1]), "r"(a[2]), "r"(a[3]), "r"(b0), "r"(b1));
}

// ---------------- warp-MMA tf32 GEMM: C[N,ncols] = A[N,K] @ Bt^T -------------
// Bt is [ncols, K] row-major. 3xTF32 split for fp32-level precision.
// CTA tile 128x128, 8 warps (2x4), each warp 64x32. K chunks of 16, dbl-buffer.
#define KC 16
#define SB 20                       // padded smem row stride (floats)
#define ATILE (128 * SB)            // floats per (sub)tile
#define BUFW (4 * ATILE)            // Ahi, Alo, Bhi, Blo

__global__ void __launch_bounds__(256, 1)
mma_gemm_k(const float* __restrict__ A, const float* __restrict__ Bt,
           float* __restrict__ C, int Nrows, int K, int ncols,
           const float* __restrict__ bias, int act)
{
    extern __shared__ float sm[];
    const int tid = threadIdx.x;
    const int lane = tid & 31, wid = tid >> 5;
    const int wr = wid >> 2, wc = wid & 3;     // warp row (0..1), warp col (0..3)
    const int tg = lane >> 2, tig = lane & 3;  // group id, thread-in-group
    const int m0 = blockIdx.x * 128, n0 = blockIdx.y * 128;

    float acc[4][4][4];
    #pragma unroll
    for (int i = 0; i < 4; i++)
        #pragma unroll
        for (int j = 0; j < 4; j++)
            #pragma unroll
            for (int q = 0; q < 4; q++) acc[i][j][q] = 0.0f;

    const int nc = K / KC;
    float4 aReg[2], bReg[2];

    // ---- stage chunk c's global data into registers ----
    auto loadG = [&](int c) {
        const int k0 = c * KC;
        #pragma unroll
        for (int i = 0; i < 2; i++) {
            int idx = tid + i * 256;            // 0..511
            int r = idx >> 2, c4 = (idx & 3) * 4;
            int grow = m0 + r;
            aReg[i] = (grow < Nrows) ? *(const float4*)&A[(size_t)grow * K + k0 + c4]
                                     : make_float4(0.f, 0.f, 0.f, 0.f);
            int gn = n0 + r;
            bReg[i] = (gn < ncols) ? *(const float4*)&Bt[(size_t)gn * K + k0 + c4]
                                   : make_float4(0.f, 0.f, 0.f, 0.f);
        }
    };
    // ---- split + store staged registers into smem buffer ----
    auto storeS = [&](int buf) {
        float* base = sm + buf * BUFW;
        #pragma unroll
        for (int i = 0; i < 2; i++) {
            int idx = tid + i * 256;
            int r = idx >> 2, c4 = (idx & 3) * 4;
            float* ah = base + r * SB + c4;
            float* al = ah + ATILE;
            float* bh = ah + 2 * ATILE;
            float* bl = ah + 3 * ATILE;
            const float* av = (const float*)&aReg[i];
            const float* bv = (const float*)&bReg[i];
            #pragma unroll
            for (int q = 0; q < 4; q++) {
                float h = tf32hi(av[q]);
                ah[q] = h; al[q] = av[q] - h;
                h = tf32hi(bv[q]);
                bh[q] = h; bl[q] = bv[q] - h;
            }
        }
    };
    // ---- MMA over one smem chunk ----
    auto compute = [&](int buf) {
        const float* base = sm + buf * BUFW;
        const float* Ah = base;
        const float* Al = base + ATILE;
        const float* Bh = base + 2 * ATILE;
        const float* Bl = base + 3 * ATILE;
        #pragma unroll
        for (int ks = 0; ks < KC / 8; ks++) {
            const int col = ks * 8 + tig;
            uint32_t ah[4][4], al[4][4];
            #pragma unroll
            for (int i = 0; i < 4; i++) {
                int row = wr * 64 + i * 16 + tg;
                ah[i][0] = __float_as_uint(Ah[row * SB + col]);
                ah[i][1] = __float_as_uint(Ah[(row + 8) * SB + col]);
                ah[i][2] = __float_as_uint(Ah[row * SB + col + 4]);
                ah[i][3] = __float_as_uint(Ah[(row + 8) * SB + col + 4]);
                al[i][0] = __float_as_uint(Al[row * SB + col]);
                al[i][1] = __float_as_uint(Al[(row + 8) * SB + col]);
                al[i][2] = __float_as_uint(Al[row * SB + col + 4]);
                al[i][3] = __float_as_uint(Al[(row + 8) * SB + col + 4]);
            }
            #pragma unroll
            for (int j = 0; j < 4; j++) {
                int nrow = wc * 32 + j * 8 + tg;
                uint32_t bh0 = __float_as_uint(Bh[nrow * SB + col]);
                uint32_t bh1 = __float_as_uint(Bh[nrow * SB + col + 4]);
                uint32_t bl0 = __float_as_uint(Bl[nrow * SB + col]);
                uint32_t bl1 = __float_as_uint(Bl[nrow * SB + col + 4]);
                #pragma unroll
                for (int i = 0; i < 4; i++) {
                    mma_tf32(acc[i][j], ah[i], bh0, bh1);
                    mma_tf32(acc[i][j], ah[i], bl0, bl1);
                    mma_tf32(acc[i][j], al[i], bh0, bh1);
                }
            }
        }
    };

    loadG(0); storeS(0);
    __syncthreads();
    for (int c = 0; c < nc; c++) {
        if (c + 1 < nc) loadG(c + 1);
        compute(c & 1);
        if (c + 1 < nc) storeS((c + 1) & 1);
        __syncthreads();
    }

    // ---- epilogue ----
    #pragma unroll
    for (int i = 0; i < 4; i++) {
        int row = m0 + wr * 64 + i * 16 + tg;
        #pragma unroll
        for (int j = 0; j < 4; j++) {
            int col = n0 + wc * 32 + j * 8 + tig * 2;
            if (col >= ncols) continue;
            #pragma unroll
            for (int half = 0; half < 2; half++) {
                int r = row + half * 8;
                if (r >= Nrows) continue;
                float v0 = acc[i][j][half * 2 + 0];
                float v1 = acc[i][j][half * 2 + 1];
                if (bias) { v0 += bias[col]; v1 += bias[col + 1]; }
                if (act == 1) {
                    v0 = 0.5f * v0 * (1.0f + erff(v0 * 0.70710678118654752f));
                    v1 = 0.5f * v1 * (1.0f + erff(v1 * 0.70710678118654752f));
                }
                *(float2*)&C[(size_t)r * ncols + col] = make_float2(v0, v1);
            }
        }
    }
}

// ---------------- weight transpose: W[K,M] -> Bt[M,K] ------------------------
__global__ void transpose_k(const float* __restrict__ W, float* __restrict__ Bt,
                            int K, int M)
{
    __shared__ float t[32][33];
    int m0 = blockIdx.x * 32, k0 = blockIdx.y * 32;
    for (int i = threadIdx.y; i < 32; i += 8) {
        int k = k0 + i, m = m0 + threadIdx.x;
        t[i][threadIdx.x] = (k < K && m < M) ? W[(size_t)k * M + m] : 0.f;
    }
    __syncthreads();
    for (int i = threadIdx.y; i < 32; i += 8) {
        int m = m0 + i, k = k0 + threadIdx.x;
        if (m < M && k < K) Bt[(size_t)m * K + k] = t[threadIdx.x][i];
    }
}

// ---------------- GAT edge/node kernels (unchanged from passing R1) ---------
__global__ void ve_k(const float* __restrict__ We, const float* __restrict__ ae, int H)
{
    int tid = threadIdx.x;
    if (tid >= 5 * H) return;
    int d = tid / H, h = tid % H;
    int C = 256 / H;
    float s = 0.0f;
    for (int c = 0; c < C; c++) s += We[d * 256 + h * C + c] * ae[h * C + c];
    g_Ve[tid] = s;
}

__global__ void node_att_k(const float* __restrict__ hf,
                           const float* __restrict__ att_s,
                           const float* __restrict__ att_d,
                           float* __restrict__ as_, float* __restrict__ ad_,
                           float* __restrict__ m, float* __restrict__ den,
                           int N, int H)
{
    int idx = blockIdx.x * blockDim.x + threadIdx.x;
    if (idx >= N * H) return;
    int C = 256 / H;
    int n = idx / H, hh = idx % H;
    const float4* hp = (const float4*)(hf + (size_t)n * 256 + hh * C);
    const float4* sp = (const float4*)(att_s + hh * C);
    const float4* dp = (const float4*)(att_d + hh * C);
    float ss = 0.0f, dd = 0.0f;
    for (int i = 0; i < C / 4; i++) {
        float4 v = hp[i], a = sp[i], b = dp[i];
        ss += v.x * a.x + v.y * a.y + v.z * a.z + v.w * a.w;
        dd += v.x * b.x + v.y * b.y + v.z * b.z + v.w * b.w;
    }
    as_[idx] = ss;
    ad_[idx] = dd;
    m[idx]   = -INFINITY;
    den[idx] = 0.0f;
}

__global__ void zero_k(float* __restrict__ p, int n4)
{
    int i = blockIdx.x * blockDim.x + threadIdx.x;
    if (i < n4) ((float4*)p)[i] = make_float4(0.f, 0.f, 0.f, 0.f);
}

template <int H>
__global__ void edge_alpha_k(const int* __restrict__ src, const int* __restrict__ dst,
                             const float* __restrict__ ea,
                             const float* __restrict__ as_, const float* __restrict__ ad_,
                             float* __restrict__ alpha, float* __restrict__ m, int E)
{
    __shared__ float sVe[5 * H];
    if (threadIdx.x < 5 * H) sVe[threadIdx.x] = g_Ve[threadIdx.x];
    __syncthreads();
    int e = blockIdx.x * blockDim.x + threadIdx.x;
    if (e >= E) return;
    int s = src[e], d = dst[e];
    float eav[5];
    #pragma unroll
    for (int i = 0; i < 5; i++) eav[i] = ea[e * 5 + i];
    #pragma unroll
    for (int h = 0; h < H; h++) {
        float aeh = 0.0f;
        #pragma unroll
        for (int i = 0; i < 5; i++) aeh = fmaf(eav[i], sVe[i * H + h], aeh);
        float v = as_[s * H + h] + ad_[d * H + h] + aeh;
        v = v > 0.0f ? v : 0.2f * v;
        alpha[e * H + h] = v;
        atomicMaxFloat(&m[d * H + h], v);
    }
}

template <int H>
__global__ void edge_p_k(const int* __restrict__ dst, float* __restrict__ alpha,
                         const float* __restrict__ m, float* __restrict__ den, int E)
{
    int e = blockIdx.x * blockDim.x + threadIdx.x;
    if (e >= E) return;
    int d = dst[e];
    #pragma unroll
    for (int h = 0; h < H; h++) {
        float pv = expf(alpha[e * H + h] - m[d * H + h]);
        alpha[e * H + h] = pv;
        atomicAdd(&den[d * H + h], pv);
    }
}

__global__ void edge_agg_k(const int* __restrict__ src, const int* __restrict__ dst,
                           const float* __restrict__ p, const float* __restrict__ den,
                           const float* __restrict__ hfeat, float* __restrict__ agg,
                           int E, int H)
{
    int gw = (blockIdx.x * blockDim.x + threadIdx.x) >> 5;
    int lane = threadIdx.x & 31;
    if (gw >= E) return;
    int s = src[gw], d = dst[gw];
    int c1 = lane * 4, c2 = 128 + lane * 4;
    int h1 = (c1 * H) >> 8, h2 = (c2 * H) >> 8;
    float w1 = p[gw * H + h1] / (den[d * H + h1] + 1e-16f);
    float w2 = p[gw * H + h2] / (den[d * H + h2] + 1e-16f);
    float4 v1 = *(const float4*)&hfeat[(size_t)s * 256 + c1];
    float4 v2 = *(const float4*)&hfeat[(size_t)s * 256 + c2];
    atomicAdd((float4*)&agg[(size_t)d * 256 + c1],
              make_float4(v1.x * w1, v1.y * w1, v1.z * w1, v1.w * w1));
    atomicAdd((float4*)&agg[(size_t)d * 256 + c2],
              make_float4(v2.x * w2, v2.y * w2, v2.z * w2, v2.w * w2));
}

__global__ void finish_k(const float* __restrict__ agg, const float* __restrict__ bias,
                         float* __restrict__ outf, int N)
{
    int i = blockIdx.x * blockDim.x + threadIdx.x;
    if (i >= N * 64) return;
    int c4 = i & 63;
    float4 v = ((const float4*)agg)[i];
    float4 b = ((const float4*)bias)[c4];
    v.x = elu1(v.x + b.x);
    v.y = elu1(v.y + b.y);
    v.z = elu1(v.z + b.z);
    v.w = elu1(v.w + b.w);
    ((float4*)outf)[i] = v;
}

__global__ void pool_zero_k()
{
    int t = blockIdx.x * blockDim.x + threadIdx.x;
    if (t < GG * 32) g_pool[t] = 0.0f;
    if (t < GG)      g_cnt[t]  = 0.0f;
}

__global__ void pool_acc_k(const float* __restrict__ y, const int* __restrict__ batch, int N)
{
    int idx = blockIdx.x * blockDim.x + threadIdx.x;
    if (idx >= N * 8) return;
    int n = idx >> 3, q = idx & 7;
    int g = batch[n];
    float4 v = ((const float4*)(y + (size_t)n * 32))[q];
    atomicAdd((float4*)&g_pool[g * 32 + q * 4], v);
    if (q == 0) atomicAdd(&g_cnt[g], 1.0f);
}

__global__ void pool_fin_k(float* __restrict__ out)
{
    int t = blockIdx.x * blockDim.x + threadIdx.x;
    if (t < GG * 32) out[t] = g_pool[t] / fmaxf(g_cnt[t >> 5], 1.0f);
}

// ============================================================================
static void launch_gemm(const float* A, const float* W, float* C,
                        int n, int K, int ncols, const float* bias, int act, float* bt)
{
    transpose_k<<<dim3((ncols + 31) / 32, (K + 31) / 32), dim3(32, 8)>>>(W, bt, K, ncols);
    dim3 grid((n + 127) / 128, (ncols + 127) / 128);
    mma_gemm_k<<<grid, 256, 2 * BUFW * sizeof(float)>>>(A, bt, C, n, K, ncols, bias, act);
}

static void run_gat_layer(const float* in, int K,
                          const float* W, const float* as_att, const float* ad_att,
                          const float* We, const float* ae_att, const float* bias,
                          int H,
                          const int* src, const int* dst, const float* ea,
                          float* feat, float* h, float* agg, float* alpha,
                          float* as_, float* ad_, float* m, float* den, float* bt)
{
    launch_gemm(in, W, h, NN, K, HC, nullptr, 0, bt);
    node_att_k<<<(NN * H + 255) / 256, 256>>>(h, as_att, ad_att, as_, ad_, m, den, NN, H);
    zero_k<<<(NN * HC / 4 + 255) / 256, 256>>>(agg, NN * HC / 4);
    ve_k<<<1, 64>>>(We, ae_att, H);
    int eb = (EE + 255) / 256;
    if (H == 8) {
        edge_alpha_k<8><<<eb, 256>>>(src, dst, ea, as_, ad_, alpha, m, EE);
        edge_p_k<8><<<eb, 256>>>(dst, alpha, m, den, EE);
    } else {
        edge_alpha_k<1><<<eb, 256>>>(src, dst, ea, as_, ad_, alpha, m, EE);
        edge_p_k<1><<<eb, 256>>>(dst, alpha, m, den, EE);
    }
    edge_agg_k<<<(EE * 32 + 255) / 256, 256>>>(src, dst, alpha, den, h, agg, EE, H);
    finish_k<<<(NN * 64 + 255) / 256, 256>>>(agg, bias, feat, NN);
}

extern "C" void kernel_launch(void* const* d_in, const int* in_sizes, int n_in,
                              void* d_out, int out_size)
{
    const float* x     = (const float*)d_in[0];
    const int*   ei    = (const int*)  d_in[1];
    const float* ea    = (const float*)d_in[2];
    const int*   batch = (const int*)  d_in[3];
    const float* W1  = (const float*)d_in[4];
    const float* as1 = (const float*)d_in[5];
    const float* ad1 = (const float*)d_in[6];
    const float* We1 = (const float*)d_in[7];
    const float* ae1 = (const float*)d_in[8];
    const float* b1  = (const float*)d_in[9];
    const float* W2  = (const float*)d_in[10];
    const float* as2 = (const float*)d_in[11];
    const float* ad2 = (const float*)d_in[12];
    const float* We2 = (const float*)d_in[13];
    const float* ae2 = (const float*)d_in[14];
    const float* b2  = (const float*)d_in[15];
    const float* W3  = (const float*)d_in[16];
    const float* as3 = (const float*)d_in[17];
    const float* ad3 = (const float*)d_in[18];
    const float* We3 = (const float*)d_in[19];
    const float* ae3 = (const float*)d_in[20];
    const float* b3  = (const float*)d_in[21];
    const float* fcW1 = (const float*)d_in[22];
    const float* fcb1 = (const float*)d_in[23];
    const float* fcW2 = (const float*)d_in[24];
    const float* fcb2 = (const float*)d_in[25];

    const int* src = ei;
    const int* dst = ei + EE;

    float *feat, *h, *agg, *alpha, *as_, *ad_, *m, *den, *bt;
    cudaGetSymbolAddress((void**)&feat,  g_feat);
    cudaGetSymbolAddress((void**)&h,     g_h);
    cudaGetSymbolAddress((void**)&agg,   g_agg);
    cudaGetSymbolAddress((void**)&alpha, g_alpha);
    cudaGetSymbolAddress((void**)&as_,   g_as);
    cudaGetSymbolAddress((void**)&ad_,   g_ad);
    cudaGetSymbolAddress((void**)&m,     g_m);
    cudaGetSymbolAddress((void**)&den,   g_den);
    cudaGetSymbolAddress((void**)&bt,    g_bt);

    cudaFuncSetAttribute(mma_gemm_k, cudaFuncAttributeMaxDynamicSharedMemorySize,
                         2 * BUFW * sizeof(float));

    run_gat_layer(x,    128, W1, as1, ad1, We1, ae1, b1, 8, src, dst, ea,
                  feat, h, agg, alpha, as_, ad_, m, den, bt);
    run_gat_layer(feat, 256, W2, as2, ad2, We2, ae2, b2, 8, src, dst, ea,
                  feat, h, agg, alpha, as_, ad_, m, den, bt);
    run_gat_layer(feat, 256, W3, as3, ad3, We3, ae3, b3, 1, src, dst, ea,
                  feat, h, agg, alpha, as_, ad_, m, den, bt);

    // MLP head
    launch_gemm(feat, fcW1, h, NN, 256, 256, fcb1, 1, bt);
    launch_gemm(h, fcW2, agg, NN, 256, 32, fcb2, 0, bt);

    // global mean pool
    pool_zero_k<<<(GG * 32 + 255) / 256, 256>>>();
    pool_acc_k<<<(NN * 8 + 255) / 256, 256>>>(agg, batch, NN);
    pool_fin_k<<<(GG * 32 + 255) / 256, 256>>>((float*)d_out);
}

// round 4
// speedup vs baseline: 1.3513x; 1.2335x over previous
#include <cuda_runtime.h>
#include <math.h>
#include <stdint.h>

#define NN 50000
#define EE 400000
#define GG 64
#define HC 256

// ---------------- scratch (static device globals) ---------------------------
__device__ float g_feat [NN * HC];
__device__ float g_h    [NN * HC];
__device__ float g_agg  [NN * HC];
__device__ float g_as   [NN * 8];
__device__ float g_ad   [NN * 8];
__device__ float g_Ve   [5 * 8];
__device__ float g_pool [GG * 32];
__device__ float g_cnt  [GG];
__device__ float g_bt   [256 * 256];
// CSR scratch
__device__ int g_deg [NN];
__device__ int g_rs  [NN];
__device__ int g_wp  [NN];
__device__ int g_part[128];
__device__ int g_csrc[EE];
__device__ int g_ceid[EE];

// ---------------- helpers ---------------------------------------------------
__device__ __forceinline__ float elu1(float x) { return x > 0.0f ? x : expm1f(x); }

__device__ __forceinline__ float tf32hi(float x) {
    uint32_t u;
    asm("cvt.rna.tf32.f32 %0, %1;" : "=r"(u) : "f"(x));
    return __uint_as_float(u);
}

__device__ __forceinline__ void mma_tf32(float* d, const uint32_t* a,
                                         uint32_t b0, uint32_t b1) {
    asm volatile(
        "mma.sync.aligned.m16n8k8.row.col.f32.tf32.tf32.f32 "
        "{%0,%1,%2,%3}, {%4,%5,%6,%7}, {%8,%9}, {%0,%1,%2,%3};"
        : "+f"(d[0]), "+f"(d[1]), "+f"(d[2]), "+f"(d[3])
        : "r"(a[0]), "r"(a[1]), "r"(a[2]), "r"(a[3]), "r"(b0), "r"(b1));
}

// ---------------- warp-MMA tf32 GEMM (3xTF32), 128x128 CTA tile -------------
#define KC 16
#define SB 20
#define ATILE (128 * SB)
#define BUFW (4 * ATILE)

__global__ void __launch_bounds__(256, 1)
mma_gemm_k(const float* __restrict__ A, const float* __restrict__ Bt,
           float* __restrict__ C, int Nrows, int K, int ncols,
           const float* __restrict__ bias, int act)
{
    extern __shared__ float sm[];
    const int tid = threadIdx.x;
    const int lane = tid & 31, wid = tid >> 5;
    const int wr = wid >> 2, wc = wid & 3;
    const int tg = lane >> 2, tig = lane & 3;
    const int m0 = blockIdx.x * 128, n0 = blockIdx.y * 128;

    float acc[4][4][4];
    #pragma unroll
    for (int i = 0; i < 4; i++)
        #pragma unroll
        for (int j = 0; j < 4; j++)
            #pragma unroll
            for (int q = 0; q < 4; q++) acc[i][j][q] = 0.0f;

    const int nc = K / KC;
    float4 aReg[2], bReg[2];

    auto loadG = [&](int c) {
        const int k0 = c * KC;
        #pragma unroll
        for (int i = 0; i < 2; i++) {
            int idx = tid + i * 256;
            int r = idx >> 2, c4 = (idx & 3) * 4;
            int grow = m0 + r;
            aReg[i] = (grow < Nrows) ? *(const float4*)&A[(size_t)grow * K + k0 + c4]
                                     : make_float4(0.f, 0.f, 0.f, 0.f);
            int gn = n0 + r;
            bReg[i] = (gn < ncols) ? *(const float4*)&Bt[(size_t)gn * K + k0 + c4]
                                   : make_float4(0.f, 0.f, 0.f, 0.f);
        }
    };
    auto storeS = [&](int buf) {
        float* base = sm + buf * BUFW;
        #pragma unroll
        for (int i = 0; i < 2; i++) {
            int idx = tid + i * 256;
            int r = idx >> 2, c4 = (idx & 3) * 4;
            float* ah = base + r * SB + c4;
            float* al = ah + ATILE;
            float* bh = ah + 2 * ATILE;
            float* bl = ah + 3 * ATILE;
            const float* av = (const float*)&aReg[i];
            const float* bv = (const float*)&bReg[i];
            #pragma unroll
            for (int q = 0; q < 4; q++) {
                float h = tf32hi(av[q]);
                ah[q] = h; al[q] = av[q] - h;
                h = tf32hi(bv[q]);
                bh[q] = h; bl[q] = bv[q] - h;
            }
        }
    };
    auto compute = [&](int buf) {
        const float* base = sm + buf * BUFW;
        const float* Ah = base;
        const float* Al = base + ATILE;
        const float* Bh = base + 2 * ATILE;
        const float* Bl = base + 3 * ATILE;
        #pragma unroll
        for (int ks = 0; ks < KC / 8; ks++) {
            const int col = ks * 8 + tig;
            uint32_t ah[4][4], al[4][4];
            #pragma unroll
            for (int i = 0; i < 4; i++) {
                int row = wr * 64 + i * 16 + tg;
                ah[i][0] = __float_as_uint(Ah[row * SB + col]);
                ah[i][1] = __float_as_uint(Ah[(row + 8) * SB + col]);
                ah[i][2] = __float_as_uint(Ah[row * SB + col + 4]);
                ah[i][3] = __float_as_uint(Ah[(row + 8) * SB + col + 4]);
                al[i][0] = __float_as_uint(Al[row * SB + col]);
                al[i][1] = __float_as_uint(Al[(row + 8) * SB + col]);
                al[i][2] = __float_as_uint(Al[row * SB + col + 4]);
                al[i][3] = __float_as_uint(Al[(row + 8) * SB + col + 4]);
            }
            #pragma unroll
            for (int j = 0; j < 4; j++) {
                int nrow = wc * 32 + j * 8 + tg;
                uint32_t bh0 = __float_as_uint(Bh[nrow * SB + col]);
                uint32_t bh1 = __float_as_uint(Bh[nrow * SB + col + 4]);
                uint32_t bl0 = __float_as_uint(Bl[nrow * SB + col]);
                uint32_t bl1 = __float_as_uint(Bl[nrow * SB + col + 4]);
                #pragma unroll
                for (int i = 0; i < 4; i++) {
                    mma_tf32(acc[i][j], ah[i], bh0, bh1);
                    mma_tf32(acc[i][j], ah[i], bl0, bl1);
                    mma_tf32(acc[i][j], al[i], bh0, bh1);
                }
            }
        }
    };

    loadG(0); storeS(0);
    __syncthreads();
    for (int c = 0; c < nc; c++) {
        if (c + 1 < nc) loadG(c + 1);
        compute(c & 1);
        if (c + 1 < nc) storeS((c + 1) & 1);
        __syncthreads();
    }

    #pragma unroll
    for (int i = 0; i < 4; i++) {
        int row = m0 + wr * 64 + i * 16 + tg;
        #pragma unroll
        for (int j = 0; j < 4; j++) {
            int col = n0 + wc * 32 + j * 8 + tig * 2;
            if (col >= ncols) continue;
            #pragma unroll
            for (int half = 0; half < 2; half++) {
                int r = row + half * 8;
                if (r >= Nrows) continue;
                float v0 = acc[i][j][half * 2 + 0];
                float v1 = acc[i][j][half * 2 + 1];
                if (bias) { v0 += bias[col]; v1 += bias[col + 1]; }
                if (act == 1) {
                    v0 = 0.5f * v0 * (1.0f + erff(v0 * 0.70710678118654752f));
                    v1 = 0.5f * v1 * (1.0f + erff(v1 * 0.70710678118654752f));
                }
                *(float2*)&C[(size_t)r * ncols + col] = make_float2(v0, v1);
            }
        }
    }
}

__global__ void transpose_k(const float* __restrict__ W, float* __restrict__ Bt,
                            int K, int M)
{
    __shared__ float t[32][33];
    int m0 = blockIdx.x * 32, k0 = blockIdx.y * 32;
    for (int i = threadIdx.y; i < 32; i += 8) {
        int k = k0 + i, m = m0 + threadIdx.x;
        t[i][threadIdx.x] = (k < K && m < M) ? W[(size_t)k * M + m] : 0.f;
    }
    __syncthreads();
    for (int i = threadIdx.y; i < 32; i += 8) {
        int m = m0 + i, k = k0 + threadIdx.x;
        if (m < M && k < K) Bt[(size_t)m * K + k] = t[threadIdx.x][i];
    }
}

// ---------------- CSR build --------------------------------------------------
__global__ void deg_zero_k()
{
    int i = blockIdx.x * blockDim.x + threadIdx.x;
    if (i < NN) g_deg[i] = 0;
}
__global__ void hist_k(const int* __restrict__ dst)
{
    int e = blockIdx.x * blockDim.x + threadIdx.x;
    if (e < EE) atomicAdd(&g_deg[dst[e]], 1);
}
__global__ void scan1_k()
{
    __shared__ int s[512];
    int tid = threadIdx.x;
    int i = blockIdx.x * 512 + tid;
    int v = (i < NN) ? g_deg[i] : 0;
    s[tid] = v;
    __syncthreads();
    for (int off = 1; off < 512; off <<= 1) {
        int t = (tid >= off) ? s[tid - off] : 0;
        __syncthreads();
        s[tid] += t;
        __syncthreads();
    }
    if (i < NN) g_rs[i] = s[tid] - v;
    if (tid == 511) g_part[blockIdx.x] = s[511];
}
__global__ void scan2_k(int nb)
{
    __shared__ int s[128];
    int tid = threadIdx.x;
    int v = (tid < nb) ? g_part[tid] : 0;
    s[tid] = v;
    __syncthreads();
    for (int off = 1; off < 128; off <<= 1) {
        int t = (tid >= off) ? s[tid - off] : 0;
        __syncthreads();
        s[tid] += t;
        __syncthreads();
    }
    if (tid < nb) g_part[tid] = s[tid] - v;
}
__global__ void scan3_k()
{
    int i = blockIdx.x * blockDim.x + threadIdx.x;
    if (i >= NN) return;
    int r = g_rs[i] + g_part[i >> 9];
    g_rs[i] = r;
    g_wp[i] = r;
}
__global__ void scatter_k(const int* __restrict__ src, const int* __restrict__ dst)
{
    int e = blockIdx.x * blockDim.x + threadIdx.x;
    if (e >= EE) return;
    int d = dst[e];
    int pos = atomicAdd(&g_wp[d], 1);
    g_csrc[pos] = src[e];
    g_ceid[pos] = e;
}

// ---------------- per-layer small kernels ------------------------------------
__global__ void ve_k(const float* __restrict__ We, const float* __restrict__ ae, int H)
{
    int tid = threadIdx.x;
    if (tid >= 5 * H) return;
    int d = tid / H, h = tid % H;
    int C = 256 / H;
    float s = 0.0f;
    for (int c = 0; c < C; c++) s += We[d * 256 + h * C + c] * ae[h * C + c];
    g_Ve[tid] = s;
}

__global__ void node_att_k(const float* __restrict__ hf,
                           const float* __restrict__ att_s,
                           const float* __restrict__ att_d,
                           float* __restrict__ as_, float* __restrict__ ad_,
                           int N, int H)
{
    int idx = blockIdx.x * blockDim.x + threadIdx.x;
    if (idx >= N * H) return;
    int C = 256 / H;
    int n = idx / H, hh = idx % H;
    const float4* hp = (const float4*)(hf + (size_t)n * 256 + hh * C);
    const float4* sp = (const float4*)(att_s + hh * C);
    const float4* dp = (const float4*)(att_d + hh * C);
    float ss = 0.0f, dd = 0.0f;
    for (int i = 0; i < C / 4; i++) {
        float4 v = hp[i], a = sp[i], b = dp[i];
        ss += v.x * a.x + v.y * a.y + v.z * a.z + v.w * a.w;
        dd += v.x * b.x + v.y * b.y + v.z * b.z + v.w * b.w;
    }
    as_[idx] = ss;
    ad_[idx] = dd;
}

// ---------------- fused edge softmax + aggregation: one warp per dst --------
template <int H>
__global__ void __launch_bounds__(256)
gat_edge_k(const float* __restrict__ ea,
           const float* __restrict__ as_, const float* __restrict__ ad_,
           const float* __restrict__ hfeat, const float* __restrict__ bias,
           float* __restrict__ outf)
{
    int w = (blockIdx.x * blockDim.x + threadIdx.x) >> 5;
    if (w >= NN) return;
    int lane = threadIdx.x & 31;
    const int head = (H == 8) ? (lane >> 2) : 0;
    const int col0 = lane * 8;

    float ve[5];
    #pragma unroll
    for (int i = 0; i < 5; i++) ve[i] = g_Ve[i * H + head];
    const float adv = ad_[w * H + head];
    const int r0 = g_rs[w], dg = g_deg[w];

    // pass A: row max of leaky-relu logits (per head; dup x4 lanes)
    float mx = -INFINITY;
    for (int j = 0; j < dg; j++) {
        int s = g_csrc[r0 + j];
        int e = g_ceid[r0 + j];
        float a = as_[s * H + head] + adv;
        #pragma unroll
        for (int i = 0; i < 5; i++) a = fmaf(ea[e * 5 + i], ve[i], a);
        a = a > 0.0f ? a : 0.2f * a;
        mx = fmaxf(mx, a);
    }

    // pass B: unnormalized softmax-weighted feature accumulation
    float den = 0.0f;
    float acc[8];
    #pragma unroll
    for (int q = 0; q < 8; q++) acc[q] = 0.0f;

    for (int j = 0; j < dg; j++) {
        int s = g_csrc[r0 + j];
        int e = g_ceid[r0 + j];
        float a = as_[s * H + head] + adv;
        #pragma unroll
        for (int i = 0; i < 5; i++) a = fmaf(ea[e * 5 + i], ve[i], a);
        a = a > 0.0f ? a : 0.2f * a;
        float p = expf(a - mx);
        den += p;
        const float4* hp = (const float4*)(hfeat + (size_t)s * 256 + col0);
        float4 v0 = hp[0], v1 = hp[1];
        acc[0] = fmaf(p, v0.x, acc[0]); acc[1] = fmaf(p, v0.y, acc[1]);
        acc[2] = fmaf(p, v0.z, acc[2]); acc[3] = fmaf(p, v0.w, acc[3]);
        acc[4] = fmaf(p, v1.x, acc[4]); acc[5] = fmaf(p, v1.y, acc[5]);
        acc[6] = fmaf(p, v1.z, acc[6]); acc[7] = fmaf(p, v1.w, acc[7]);
    }

    float inv = 1.0f / (den + 1e-16f);
    float4 o0, o1;
    float* op = (float*)&o0;
    #pragma unroll
    for (int q = 0; q < 4; q++) op[q] = elu1(acc[q] * inv + bias[col0 + q]);
    op = (float*)&o1;
    #pragma unroll
    for (int q = 0; q < 4; q++) op[q] = elu1(acc[4 + q] * inv + bias[col0 + 4 + q]);
    *(float4*)&outf[(size_t)w * 256 + col0]     = o0;
    *(float4*)&outf[(size_t)w * 256 + col0 + 4] = o1;
}

// ---------------- pooling -----------------------------------------------------
__global__ void pool_zero_k()
{
    int t = blockIdx.x * blockDim.x + threadIdx.x;
    if (t < GG * 32) g_pool[t] = 0.0f;
    if (t < GG)      g_cnt[t]  = 0.0f;
}
__global__ void pool_acc_k(const float* __restrict__ y, const int* __restrict__ batch, int N)
{
    int idx = blockIdx.x * blockDim.x + threadIdx.x;
    if (idx >= N * 8) return;
    int n = idx >> 3, q = idx & 7;
    int g = batch[n];
    float4 v = ((const float4*)(y + (size_t)n * 32))[q];
    atomicAdd((float4*)&g_pool[g * 32 + q * 4], v);
    if (q == 0) atomicAdd(&g_cnt[g], 1.0f);
}
__global__ void pool_fin_k(float* __restrict__ out)
{
    int t = blockIdx.x * blockDim.x + threadIdx.x;
    if (t < GG * 32) out[t] = g_pool[t] / fmaxf(g_cnt[t >> 5], 1.0f);
}

// ============================================================================
static void launch_gemm(const float* A, const float* W, float* C,
                        int n, int K, int ncols, const float* bias, int act, float* bt)
{
    transpose_k<<<dim3((ncols + 31) / 32, (K + 31) / 32), dim3(32, 8)>>>(W, bt, K, ncols);
    dim3 grid((n + 127) / 128, (ncols + 127) / 128);
    mma_gemm_k<<<grid, 256, 2 * BUFW * sizeof(float)>>>(A, bt, C, n, K, ncols, bias, act);
}

static void run_gat_layer(const float* in, int K,
                          const float* W, const float* as_att, const float* ad_att,
                          const float* We, const float* ae_att, const float* bias,
                          int H, const float* ea,
                          float* feat, float* h, float* as_, float* ad_, float* bt)
{
    launch_gemm(in, W, h, NN, K, HC, nullptr, 0, bt);
    ve_k<<<1, 64>>>(We, ae_att, H);
    node_att_k<<<(NN * H + 255) / 256, 256>>>(h, as_att, ad_att, as_, ad_, NN, H);
    int gb = (NN * 32 + 255) / 256;
    if (H == 8)
        gat_edge_k<8><<<gb, 256>>>(ea, as_, ad_, h, bias, feat);
    else
        gat_edge_k<1><<<gb, 256>>>(ea, as_, ad_, h, bias, feat);
}

extern "C" void kernel_launch(void* const* d_in, const int* in_sizes, int n_in,
                              void* d_out, int out_size)
{
    const float* x     = (const float*)d_in[0];
    const int*   ei    = (const int*)  d_in[1];
    const float* ea    = (const float*)d_in[2];
    const int*   batch = (const int*)  d_in[3];
    const float* W1  = (const float*)d_in[4];
    const float* as1 = (const float*)d_in[5];
    const float* ad1 = (const float*)d_in[6];
    const float* We1 = (const float*)d_in[7];
    const float* ae1 = (const float*)d_in[8];
    const float* b1  = (const float*)d_in[9];
    const float* W2  = (const float*)d_in[10];
    const float* as2 = (const float*)d_in[11];
    const float* ad2 = (const float*)d_in[12];
    const float* We2 = (const float*)d_in[13];
    const float* ae2 = (const float*)d_in[14];
    const float* b2  = (const float*)d_in[15];
    const float* W3  = (const float*)d_in[16];
    const float* as3 = (const float*)d_in[17];
    const float* ad3 = (const float*)d_in[18];
    const float* We3 = (const float*)d_in[19];
    const float* ae3 = (const float*)d_in[20];
    const float* b3  = (const float*)d_in[21];
    const float* fcW1 = (const float*)d_in[22];
    const float* fcb1 = (const float*)d_in[23];
    const float* fcW2 = (const float*)d_in[24];
    const float* fcb2 = (const float*)d_in[25];

    const int* src = ei;
    const int* dst = ei + EE;

    float *feat, *h, *agg, *as_, *ad_, *bt;
    cudaGetSymbolAddress((void**)&feat, g_feat);
    cudaGetSymbolAddress((void**)&h,    g_h);
    cudaGetSymbolAddress((void**)&agg,  g_agg);
    cudaGetSymbolAddress((void**)&as_,  g_as);
    cudaGetSymbolAddress((void**)&ad_,  g_ad);
    cudaGetSymbolAddress((void**)&bt,   g_bt);

    cudaFuncSetAttribute(mma_gemm_k, cudaFuncAttributeMaxDynamicSharedMemorySize,
                         2 * BUFW * sizeof(float));

    // ---- CSR build (once; reused by all 3 layers) ----
    deg_zero_k<<<(NN + 255) / 256, 256>>>();
    hist_k<<<(EE + 255) / 256, 256>>>(dst);
    int nb = (NN + 511) / 512;
    scan1_k<<<nb, 512>>>();
    scan2_k<<<1, 128>>>(nb);
    scan3_k<<<(NN + 255) / 256, 256>>>();
    scatter_k<<<(EE + 255) / 256, 256>>>(src, dst);

    // ---- 3 GAT layers ----
    run_gat_layer(x,    128, W1, as1, ad1, We1, ae1, b1, 8, ea, feat, h, as_, ad_, bt);
    run_gat_layer(feat, 256, W2, as2, ad2, We2, ae2, b2, 8, ea, feat, h, as_, ad_, bt);
    run_gat_layer(feat, 256, W3, as3, ad3, We3, ae3, b3, 1, ea, feat, h, as_, ad_, bt);

    // ---- MLP head ----
    launch_gemm(feat, fcW1, h, NN, 256, 256, fcb1, 1, bt);
    launch_gemm(h, fcW2, agg, NN, 256, 32, fcb2, 0, bt);

    // ---- global mean pool ----
    pool_zero_k<<<(GG * 32 + 255) / 256, 256>>>();
    pool_acc_k<<<(NN * 8 + 255) / 256, 256>>>(agg, batch, NN);
    pool_fin_k<<<(GG * 32 + 255) / 256, 256>>>((float*)d_out);
}

// round 6
// speedup vs baseline: 1.6932x; 1.2530x over previous
#include <cuda_runtime.h>
#include <cuda_bf16.h>
#include <math.h>
#include <stdint.h>

#define NN 50000
#define EE 400000
#define GG 64
#define HC 256

// ---------------- scratch (static device globals) ---------------------------
__device__ float g_feat [NN * HC];
__device__ float g_h    [NN * HC];
__device__ float g_agg  [NN * HC];
__device__ float g_as   [NN * 8];
__device__ float g_ad   [NN * 8];
__device__ float g_Ve   [5 * 8];
__device__ float g_pool [GG * 32];
__device__ float g_cnt  [GG];
__device__ float g_bt   [256 * 256];
// CSR
__device__ int   g_deg [NN];
__device__ int   g_rs  [NN];
__device__ int   g_wp  [NN];
__device__ int   g_part[128];
__device__ int   g_csrc[EE];
__device__ float g_cea [EE * 5];

// ---------------- helpers ---------------------------------------------------
__device__ __forceinline__ float elu1(float x) { return x > 0.0f ? x : expm1f(x); }

// pack two floats into bf16x2 (arg order: hi elem first in PTX, lo second)
__device__ __forceinline__ uint32_t bfpack(float lo_e, float hi_e) {
    uint32_t r;
    asm("cvt.rn.bf16x2.f32 %0, %1, %2;" : "=r"(r) : "f"(hi_e), "f"(lo_e));
    return r;
}
// round float to bf16 precision and back (self-contained PTX)
__device__ __forceinline__ float bfround(float x) {
    uint16_t b;
    asm("cvt.rn.bf16.f32 %0, %1;" : "=h"(b) : "f"(x));
    float r;
    asm("cvt.f32.bf16 %0, %1;" : "=f"(r) : "h"(b));
    return r;
}

__device__ __forceinline__ void mma_bf16(float* d, const uint32_t* a,
                                         uint32_t b0, uint32_t b1) {
    asm volatile(
        "mma.sync.aligned.m16n8k16.row.col.f32.bf16.bf16.f32 "
        "{%0,%1,%2,%3}, {%4,%5,%6,%7}, {%8,%9}, {%0,%1,%2,%3};"
        : "+f"(d[0]), "+f"(d[1]), "+f"(d[2]), "+f"(d[3])
        : "r"(a[0]), "r"(a[1]), "r"(a[2]), "r"(a[3]), "r"(b0), "r"(b1));
}

// ---------------- warp-MMA 3xBF16 GEMM, 128x128 CTA tile, K chunks of 16 ----
#define S32 12                       // padded uint32 row stride (8 pairs + pad)
#define TILE32 (128 * S32)
#define BUF32 (4 * TILE32)           // Ahi, Alo, Bhi, Blo

__global__ void __launch_bounds__(256, 1)
mma_gemm_k(const float* __restrict__ A, const float* __restrict__ Bt,
           float* __restrict__ C, int Nrows, int K, int ncols,
           const float* __restrict__ bias, int act)
{
    extern __shared__ uint32_t sm32[];
    const int tid = threadIdx.x;
    const int lane = tid & 31, wid = tid >> 5;
    const int wr = wid >> 2, wc = wid & 3;
    const int tg = lane >> 2, tig = lane & 3;
    const int m0 = blockIdx.x * 128, n0 = blockIdx.y * 128;

    float acc[4][4][4];
    #pragma unroll
    for (int i = 0; i < 4; i++)
        #pragma unroll
        for (int j = 0; j < 4; j++)
            #pragma unroll
            for (int q = 0; q < 4; q++) acc[i][j][q] = 0.0f;

    const int nc = K / 16;
    float4 aReg[2], bReg[2];

    auto loadG = [&](int c) {
        const int k0 = c * 16;
        #pragma unroll
        for (int i = 0; i < 2; i++) {
            int idx = tid + i * 256;
            int r = idx >> 2, c4 = (idx & 3) * 4;
            int grow = m0 + r;
            aReg[i] = (grow < Nrows) ? *(const float4*)&A[(size_t)grow * K + k0 + c4]
                                     : make_float4(0.f, 0.f, 0.f, 0.f);
            int gn = n0 + r;
            bReg[i] = (gn < ncols) ? *(const float4*)&Bt[(size_t)gn * K + k0 + c4]
                                   : make_float4(0.f, 0.f, 0.f, 0.f);
        }
    };
    auto storeS = [&](int buf) {
        uint32_t* base = sm32 + buf * BUF32;
        #pragma unroll
        for (int i = 0; i < 2; i++) {
            int idx = tid + i * 256;
            int r = idx >> 2, p32 = (idx & 3) * 2;   // uint32 pair index 0,2,4,6
            const float* av = (const float*)&aReg[i];
            const float* bv = (const float*)&bReg[i];
            float hx0 = bfround(av[0]), hx1 = bfround(av[1]);
            float hx2 = bfround(av[2]), hx3 = bfround(av[3]);
            uint2 ahi = make_uint2(bfpack(hx0, hx1), bfpack(hx2, hx3));
            uint2 alo = make_uint2(bfpack(av[0] - hx0, av[1] - hx1),
                                   bfpack(av[2] - hx2, av[3] - hx3));
            hx0 = bfround(bv[0]); hx1 = bfround(bv[1]);
            hx2 = bfround(bv[2]); hx3 = bfround(bv[3]);
            uint2 bhi = make_uint2(bfpack(hx0, hx1), bfpack(hx2, hx3));
            uint2 blo = make_uint2(bfpack(bv[0] - hx0, bv[1] - hx1),
                                   bfpack(bv[2] - hx2, bv[3] - hx3));
            int o = r * S32 + p32;
            *(uint2*)(base + o)              = ahi;
            *(uint2*)(base + TILE32 + o)     = alo;
            *(uint2*)(base + 2 * TILE32 + o) = bhi;
            *(uint2*)(base + 3 * TILE32 + o) = blo;
        }
    };
    auto compute = [&](int buf) {
        const uint32_t* base = sm32 + buf * BUF32;
        const uint32_t* Ah = base;
        const uint32_t* Al = base + TILE32;
        const uint32_t* Bh = base + 2 * TILE32;
        const uint32_t* Bl = base + 3 * TILE32;
        uint32_t ah[4][4], al[4][4];
        #pragma unroll
        for (int i = 0; i < 4; i++) {
            int row = wr * 64 + i * 16 + tg;
            ah[i][0] = Ah[row * S32 + tig];
            ah[i][1] = Ah[(row + 8) * S32 + tig];
            ah[i][2] = Ah[row * S32 + 4 + tig];
            ah[i][3] = Ah[(row + 8) * S32 + 4 + tig];
            al[i][0] = Al[row * S32 + tig];
            al[i][1] = Al[(row + 8) * S32 + tig];
            al[i][2] = Al[row * S32 + 4 + tig];
            al[i][3] = Al[(row + 8) * S32 + 4 + tig];
        }
        #pragma unroll
        for (int j = 0; j < 4; j++) {
            int nr = wc * 32 + j * 8 + tg;
            uint32_t bh0 = Bh[nr * S32 + tig];
            uint32_t bh1 = Bh[nr * S32 + 4 + tig];
            uint32_t bl0 = Bl[nr * S32 + tig];
            uint32_t bl1 = Bl[nr * S32 + 4 + tig];
            #pragma unroll
            for (int i = 0; i < 4; i++) {
                mma_bf16(acc[i][j], ah[i], bh0, bh1);
                mma_bf16(acc[i][j], ah[i], bl0, bl1);
                mma_bf16(acc[i][j], al[i], bh0, bh1);
            }
        }
    };

    loadG(0); storeS(0);
    __syncthreads();
    for (int c = 0; c < nc; c++) {
        if (c + 1 < nc) loadG(c + 1);
        compute(c & 1);
        if (c + 1 < nc) storeS((c + 1) & 1);
        __syncthreads();
    }

    #pragma unroll
    for (int i = 0; i < 4; i++) {
        int row = m0 + wr * 64 + i * 16 + tg;
        #pragma unroll
        for (int j = 0; j < 4; j++) {
            int col = n0 + wc * 32 + j * 8 + tig * 2;
            if (col >= ncols) continue;
            #pragma unroll
            for (int half = 0; half < 2; half++) {
                int r = row + half * 8;
                if (r >= Nrows) continue;
                float v0 = acc[i][j][half * 2 + 0];
                float v1 = acc[i][j][half * 2 + 1];
                if (bias) { v0 += bias[col]; v1 += bias[col + 1]; }
                if (act == 1) {
                    v0 = 0.5f * v0 * (1.0f + erff(v0 * 0.70710678118654752f));
                    v1 = 0.5f * v1 * (1.0f + erff(v1 * 0.70710678118654752f));
                }
                *(float2*)&C[(size_t)r * ncols + col] = make_float2(v0, v1);
            }
        }
    }
}

__global__ void transpose_k(const float* __restrict__ W, float* __restrict__ Bt,
                            int K, int M)
{
    __shared__ float t[32][33];
    int m0 = blockIdx.x * 32, k0 = blockIdx.y * 32;
    for (int i = threadIdx.y; i < 32; i += 8) {
        int k = k0 + i, m = m0 + threadIdx.x;
        t[i][threadIdx.x] = (k < K && m < M) ? W[(size_t)k * M + m] : 0.f;
    }
    __syncthreads();
    for (int i = threadIdx.y; i < 32; i += 8) {
        int m = m0 + i, k = k0 + threadIdx.x;
        if (m < M && k < K) Bt[(size_t)m * K + k] = t[threadIdx.x][i];
    }
}

// ---------------- CSR build --------------------------------------------------
__global__ void deg_zero_k()
{
    int i = blockIdx.x * blockDim.x + threadIdx.x;
    if (i < NN) g_deg[i] = 0;
}
__global__ void hist_k(const int* __restrict__ dst)
{
    int e = blockIdx.x * blockDim.x + threadIdx.x;
    if (e < EE) atomicAdd(&g_deg[dst[e]], 1);
}
__global__ void scan1_k()
{
    __shared__ int s[512];
    int tid = threadIdx.x;
    int i = blockIdx.x * 512 + tid;
    int v = (i < NN) ? g_deg[i] : 0;
    s[tid] = v;
    __syncthreads();
    for (int off = 1; off < 512; off <<= 1) {
        int t = (tid >= off) ? s[tid - off] : 0;
        __syncthreads();
        s[tid] += t;
        __syncthreads();
    }
    if (i < NN) g_rs[i] = s[tid] - v;
    if (tid == 511) g_part[blockIdx.x] = s[511];
}
__global__ void scan2_k(int nb)
{
    __shared__ int s[128];
    int tid = threadIdx.x;
    int v = (tid < nb) ? g_part[tid] : 0;
    s[tid] = v;
    __syncthreads();
    for (int off = 1; off < 128; off <<= 1) {
        int t = (tid >= off) ? s[tid - off] : 0;
        __syncthreads();
        s[tid] += t;
        __syncthreads();
    }
    if (tid < nb) g_part[tid] = s[tid] - v;
}
__global__ void scan3_k()
{
    int i = blockIdx.x * blockDim.x + threadIdx.x;
    if (i >= NN) return;
    int r = g_rs[i] + g_part[i >> 9];
    g_rs[i] = r;
    g_wp[i] = r;
}
__global__ void scatter_k(const int* __restrict__ src, const int* __restrict__ dst,
                          const float* __restrict__ ea)
{
    int e = blockIdx.x * blockDim.x + threadIdx.x;
    if (e >= EE) return;
    int d = dst[e];
    int pos = atomicAdd(&g_wp[d], 1);
    g_csrc[pos] = src[e];
    #pragma unroll
    for (int i = 0; i < 5; i++) g_cea[(size_t)pos * 5 + i] = ea[(size_t)e * 5 + i];
}

// ---------------- per-layer small kernels ------------------------------------
__global__ void ve_k(const float* __restrict__ We, const float* __restrict__ ae, int H)
{
    int tid = threadIdx.x;
    if (tid >= 5 * H) return;
    int d = tid / H, h = tid % H;
    int C = 256 / H;
    float s = 0.0f;
    for (int c = 0; c < C; c++) s += We[d * 256 + h * C + c] * ae[h * C + c];
    g_Ve[tid] = s;
}

__global__ void node_att_k(const float* __restrict__ hf,
                           const float* __restrict__ att_s,
                           const float* __restrict__ att_d,
                           float* __restrict__ as_, float* __restrict__ ad_,
                           int N, int H)
{
    int idx = blockIdx.x * blockDim.x + threadIdx.x;
    if (idx >= N * H) return;
    int C = 256 / H;
    int n = idx / H, hh = idx % H;
    const float4* hp = (const float4*)(hf + (size_t)n * 256 + hh * C);
    const float4* sp = (const float4*)(att_s + hh * C);
    const float4* dp = (const float4*)(att_d + hh * C);
    float ss = 0.0f, dd = 0.0f;
    for (int i = 0; i < C / 4; i++) {
        float4 v = hp[i], a = sp[i], b = dp[i];
        ss += v.x * a.x + v.y * a.y + v.z * a.z + v.w * a.w;
        dd += v.x * b.x + v.y * b.y + v.z * b.z + v.w * b.w;
    }
    as_[idx] = ss;
    ad_[idx] = dd;
}

// ---------------- fused single-pass edge softmax + aggregation ---------------
// One warp per dst node; exp computed once per (edge, head) via quad batching.
template <int H>
__global__ void __launch_bounds__(256)
gat_edge_k(const float* __restrict__ as_, const float* __restrict__ ad_,
           const float* __restrict__ hfeat, const float* __restrict__ bias,
           float* __restrict__ outf)
{
    int w = (blockIdx.x * blockDim.x + threadIdx.x) >> 5;
    if (w >= NN) return;
    int lane = threadIdx.x & 31;
    const int head = (H == 8) ? (lane >> 2) : 0;
    const int tig = lane & 3;
    const int col0 = lane * 8;

    float ve[5];
    #pragma unroll
    for (int i = 0; i < 5; i++) ve[i] = g_Ve[i * H + head];
    const float adv = ad_[w * H + head];
    const int r0 = g_rs[w], dg = g_deg[w];

    float den = 0.0f;
    float acc[8];
    #pragma unroll
    for (int q = 0; q < 8; q++) acc[q] = 0.0f;

    int j = 0;
    for (; j + 4 <= dg; j += 4) {
        int je = r0 + j + tig;
        int sq = g_csrc[je];
        const float* ce = g_cea + (size_t)je * 5;
        float a = as_[sq * H + head] + adv;
        #pragma unroll
        for (int i = 0; i < 5; i++) a = fmaf(ce[i], ve[i], a);
        a = a > 0.0f ? a : 0.2f * a;
        float pq = __expf(a);
        #pragma unroll
        for (int q = 0; q < 4; q++) {
            float p = __shfl_sync(0xffffffffu, pq, (lane & ~3) | q);
            int s   = __shfl_sync(0xffffffffu, sq, q);
            den += p;
            const float4* hp = (const float4*)(hfeat + (size_t)s * 256 + col0);
            float4 v0 = hp[0], v1 = hp[1];
            acc[0] = fmaf(p, v0.x, acc[0]); acc[1] = fmaf(p, v0.y, acc[1]);
            acc[2] = fmaf(p, v0.z, acc[2]); acc[3] = fmaf(p, v0.w, acc[3]);
            acc[4] = fmaf(p, v1.x, acc[4]); acc[5] = fmaf(p, v1.y, acc[5]);
            acc[6] = fmaf(p, v1.z, acc[6]); acc[7] = fmaf(p, v1.w, acc[7]);
        }
    }
    for (; j < dg; j++) {
        int je = r0 + j;
        int s = g_csrc[je];
        const float* ce = g_cea + (size_t)je * 5;
        float a = as_[s * H + head] + adv;
        #pragma unroll
        for (int i = 0; i < 5; i++) a = fmaf(ce[i], ve[i], a);
        a = a > 0.0f ? a : 0.2f * a;
        float p = __expf(a);
        den += p;
        const float4* hp = (const float4*)(hfeat + (size_t)s * 256 + col0);
        float4 v0 = hp[0], v1 = hp[1];
        acc[0] = fmaf(p, v0.x, acc[0]); acc[1] = fmaf(p, v0.y, acc[1]);
        acc[2] = fmaf(p, v0.z, acc[2]); acc[3] = fmaf(p, v0.w, acc[3]);
        acc[4] = fmaf(p, v1.x, acc[4]); acc[5] = fmaf(p, v1.y, acc[5]);
        acc[6] = fmaf(p, v1.z, acc[6]); acc[7] = fmaf(p, v1.w, acc[7]);
    }

    float inv = 1.0f / (den + 1e-16f);
    float4 o0, o1;
    float* op = (float*)&o0;
    #pragma unroll
    for (int q = 0; q < 4; q++) op[q] = elu1(acc[q] * inv + bias[col0 + q]);
    op = (float*)&o1;
    #pragma unroll
    for (int q = 0; q < 4; q++) op[q] = elu1(acc[4 + q] * inv + bias[col0 + 4 + q]);
    *(float4*)&outf[(size_t)w * 256 + col0]     = o0;
    *(float4*)&outf[(size_t)w * 256 + col0 + 4] = o1;
}

// ---------------- pooling -----------------------------------------------------
__global__ void pool_zero_k()
{
    int t = blockIdx.x * blockDim.x + threadIdx.x;
    if (t < GG * 32) g_pool[t] = 0.0f;
    if (t < GG)      g_cnt[t]  = 0.0f;
}
__global__ void pool_acc_k(const float* __restrict__ y, const int* __restrict__ batch, int N)
{
    int idx = blockIdx.x * blockDim.x + threadIdx.x;
    if (idx >= N * 8) return;
    int n = idx >> 3, q = idx & 7;
    int g = batch[n];
    float4 v = ((const float4*)(y + (size_t)n * 32))[q];
    atomicAdd((float4*)&g_pool[g * 32 + q * 4], v);
    if (q == 0) atomicAdd(&g_cnt[g], 1.0f);
}
__global__ void pool_fin_k(float* __restrict__ out)
{
    int t = blockIdx.x * blockDim.x + threadIdx.x;
    if (t < GG * 32) out[t] = g_pool[t] / fmaxf(g_cnt[t >> 5], 1.0f);
}

// ============================================================================
static void launch_gemm(const float* A, const float* W, float* C,
                        int n, int K, int ncols, const float* bias, int act, float* bt)
{
    transpose_k<<<dim3((ncols + 31) / 32, (K + 31) / 32), dim3(32, 8)>>>(W, bt, K, ncols);
    dim3 grid((n + 127) / 128, (ncols + 127) / 128);
    mma_gemm_k<<<grid, 256, 2 * BUF32 * sizeof(uint32_t)>>>(A, bt, C, n, K, ncols, bias, act);
}

static void run_gat_layer(const float* in, int K,
                          const float* W, const float* as_att, const float* ad_att,
                          const float* We, const float* ae_att, const float* bias,
                          int H,
                          float* feat, float* h, float* as_, float* ad_, float* bt)
{
    launch_gemm(in, W, h, NN, K, HC, nullptr, 0, bt);
    ve_k<<<1, 64>>>(We, ae_att, H);
    node_att_k<<<(NN * H + 255) / 256, 256>>>(h, as_att, ad_att, as_, ad_, NN, H);
    int gb = (NN * 32 + 255) / 256;
    if (H == 8)
        gat_edge_k<8><<<gb, 256>>>(as_, ad_, h, bias, feat);
    else
        gat_edge_k<1><<<gb, 256>>>(as_, ad_, h, bias, feat);
}

extern "C" void kernel_launch(void* const* d_in, const int* in_sizes, int n_in,
                              void* d_out, int out_size)
{
    const float* x     = (const float*)d_in[0];
    const int*   ei    = (const int*)  d_in[1];
    const float* ea    = (const float*)d_in[2];
    const int*   batch = (const int*)  d_in[3];
    const float* W1  = (const float*)d_in[4];
    const float* as1 = (const float*)d_in[5];
    const float* ad1 = (const float*)d_in[6];
    const float* We1 = (const float*)d_in[7];
    const float* ae1 = (const float*)d_in[8];
    const float* b1  = (const float*)d_in[9];
    const float* W2  = (const float*)d_in[10];
    const float* as2 = (const float*)d_in[11];
    const float* ad2 = (const float*)d_in[12];
    const float* We2 = (const float*)d_in[13];
    const float* ae2 = (const float*)d_in[14];
    const float* b2  = (const float*)d_in[15];
    const float* W3  = (const float*)d_in[16];
    const float* as3 = (const float*)d_in[17];
    const float* ad3 = (const float*)d_in[18];
    const float* We3 = (const float*)d_in[19];
    const float* ae3 = (const float*)d_in[20];
    const float* b3  = (const float*)d_in[21];
    const float* fcW1 = (const float*)d_in[22];
    const float* fcb1 = (const float*)d_in[23];
    const float* fcW2 = (const float*)d_in[24];
    const float* fcb2 = (const float*)d_in[25];

    const int* src = ei;
    const int* dst = ei + EE;

    float *feat, *h, *agg, *as_, *ad_, *bt;
    cudaGetSymbolAddress((void**)&feat, g_feat);
    cudaGetSymbolAddress((void**)&h,    g_h);
    cudaGetSymbolAddress((void**)&agg,  g_agg);
    cudaGetSymbolAddress((void**)&as_,  g_as);
    cudaGetSymbolAddress((void**)&ad_,  g_ad);
    cudaGetSymbolAddress((void**)&bt,   g_bt);

    cudaFuncSetAttribute(mma_gemm_k, cudaFuncAttributeMaxDynamicSharedMemorySize,
                         2 * BUF32 * sizeof(uint32_t));

    // ---- CSR build (once; reused by all 3 layers) ----
    deg_zero_k<<<(NN + 255) / 256, 256>>>();
    hist_k<<<(EE + 255) / 256, 256>>>(dst);
    int nb = (NN + 511) / 512;
    scan1_k<<<nb, 512>>>();
    scan2_k<<<1, 128>>>(nb);
    scan3_k<<<(NN + 255) / 256, 256>>>();
    scatter_k<<<(EE + 255) / 256, 256>>>(src, dst, ea);

    // ---- 3 GAT layers ----
    run_gat_layer(x,    128, W1, as1, ad1, We1, ae1, b1, 8, feat, h, as_, ad_, bt);
    run_gat_layer(feat, 256, W2, as2, ad2, We2, ae2, b2, 8, feat, h, as_, ad_, bt);
    run_gat_layer(feat, 256, W3, as3, ad3, We3, ae3, b3, 1, feat, h, as_, ad_, bt);

    // ---- MLP head ----
    launch_gemm(feat, fcW1, h, NN, 256, 256, fcb1, 1, bt);
    launch_gemm(h, fcW2, agg, NN, 256, 32, fcb2, 0, bt);

    // ---- global mean pool ----
    pool_zero_k<<<(GG * 32 + 255) / 256, 256>>>();
    pool_acc_k<<<(NN * 8 + 255) / 256, 256>>>(agg, batch, NN);
    pool_fin_k<<<(GG * 32 + 255) / 256, 256>>>((float*)d_out);
}

// round 7
// speedup vs baseline: 1.7928x; 1.0588x over previous
#include <cuda_runtime.h>
#include <cuda_bf16.h>
#include <math.h>
#include <stdint.h>

#define NN 50000
#define EE 400000
#define GG 64
#define HC 256

// ---------------- scratch (static device globals) ---------------------------
__device__ float g_feat [NN * HC];
__device__ float g_h    [NN * HC];
__device__ float g_agg  [NN * HC];
__device__ float g_as   [NN * 8];
__device__ float g_ad   [NN * 8];
__device__ float g_Ve   [5 * 8];
__device__ float g_pool [GG * 32];
__device__ float g_cnt  [GG];
__device__ float g_bt   [256 * 256];
// CSR
__device__ int   g_deg [NN];
__device__ int   g_rs  [NN];
__device__ int   g_wp  [NN];
__device__ int   g_part[128];
__device__ int   g_csrc[EE];
__device__ float g_cea [EE * 5];

// ---------------- helpers ---------------------------------------------------
__device__ __forceinline__ float elu1(float x) { return x > 0.0f ? x : expm1f(x); }

__device__ __forceinline__ uint32_t bfpack(float lo_e, float hi_e) {
    uint32_t r;
    asm("cvt.rn.bf16x2.f32 %0, %1, %2;" : "=r"(r) : "f"(hi_e), "f"(lo_e));
    return r;
}
__device__ __forceinline__ float bfround(float x) {
    uint16_t b;
    asm("cvt.rn.bf16.f32 %0, %1;" : "=h"(b) : "f"(x));
    float r;
    asm("cvt.f32.bf16 %0, %1;" : "=f"(r) : "h"(b));
    return r;
}

__device__ __forceinline__ void mma_bf16(float* d, const uint32_t* a,
                                         uint32_t b0, uint32_t b1) {
    asm volatile(
        "mma.sync.aligned.m16n8k16.row.col.f32.bf16.bf16.f32 "
        "{%0,%1,%2,%3}, {%4,%5,%6,%7}, {%8,%9}, {%0,%1,%2,%3};"
        : "+f"(d[0]), "+f"(d[1]), "+f"(d[2]), "+f"(d[3])
        : "r"(a[0]), "r"(a[1]), "r"(a[2]), "r"(a[3]), "r"(b0), "r"(b1));
}

#define LDSM4(r, addr) \
    asm volatile("ldmatrix.sync.aligned.m8n8.x4.shared.b16 {%0,%1,%2,%3}, [%4];" \
        : "=r"((r)[0]), "=r"((r)[1]), "=r"((r)[2]), "=r"((r)[3]) : "r"(addr))

// ---------------- warp-MMA 3xBF16 GEMM, 128x128 CTA tile, K chunks of 16 ----
#define S32 12                       // padded uint32 row stride
#define TILE32 (128 * S32)
#define BUF32 (4 * TILE32)           // Ahi, Alo, Bhi, Blo

__global__ void __launch_bounds__(256, 1)
mma_gemm_k(const float* __restrict__ A, const float* __restrict__ Bt,
           float* __restrict__ C, int Nrows, int K, int ncols,
           const float* __restrict__ bias, int act)
{
    extern __shared__ uint32_t sm32[];
    uint32_t sbase;
    asm("{ .reg .u64 t; cvta.to.shared.u64 t, %1; cvt.u32.u64 %0, t; }"
        : "=r"(sbase) : "l"(sm32));

    const int tid = threadIdx.x;
    const int lane = tid & 31, wid = tid >> 5;
    const int wr = wid >> 2, wc = wid & 3;
    const int tg = lane >> 2, tig = lane & 3;
    const int m0 = blockIdx.x * 128, n0 = blockIdx.y * 128;

    // ldmatrix lane addressing
    const int lr = lane & 7, seg = lane >> 3;
    // A: tiles [r0-7,k0-7],[r8-15,k0-7],[r0-7,k8-15],[r8-15,k8-15]
    const uint32_t aoff = (uint32_t)((wr * 64 + lr + (seg & 1) * 8) * S32) * 4
                        + (uint32_t)(seg >> 1) * 16;
    // B: tiles [j0,k0-7],[j0,k8-15],[j1,k0-7],[j1,k8-15]
    const uint32_t boff = (uint32_t)((wc * 32 + (seg >> 1) * 8 + lr) * S32) * 4
                        + (uint32_t)(seg & 1) * 16;

    float acc[4][4][4];
    #pragma unroll
    for (int i = 0; i < 4; i++)
        #pragma unroll
        for (int j = 0; j < 4; j++)
            #pragma unroll
            for (int q = 0; q < 4; q++) acc[i][j][q] = 0.0f;

    const int nc = K / 16;
    float4 aReg[2], bReg[2];

    auto loadG = [&](int c) {
        const int k0 = c * 16;
        #pragma unroll
        for (int i = 0; i < 2; i++) {
            int idx = tid + i * 256;
            int r = idx >> 2, c4 = (idx & 3) * 4;
            int grow = m0 + r;
            aReg[i] = (grow < Nrows) ? *(const float4*)&A[(size_t)grow * K + k0 + c4]
                                     : make_float4(0.f, 0.f, 0.f, 0.f);
            int gn = n0 + r;
            bReg[i] = (gn < ncols) ? *(const float4*)&Bt[(size_t)gn * K + k0 + c4]
                                   : make_float4(0.f, 0.f, 0.f, 0.f);
        }
    };
    auto storeS = [&](int buf) {
        uint32_t* base = sm32 + buf * BUF32;
        #pragma unroll
        for (int i = 0; i < 2; i++) {
            int idx = tid + i * 256;
            int r = idx >> 2, p32 = (idx & 3) * 2;
            const float* av = (const float*)&aReg[i];
            const float* bv = (const float*)&bReg[i];
            float hx0 = bfround(av[0]), hx1 = bfround(av[1]);
            float hx2 = bfround(av[2]), hx3 = bfround(av[3]);
            uint2 ahi = make_uint2(bfpack(hx0, hx1), bfpack(hx2, hx3));
            uint2 alo = make_uint2(bfpack(av[0] - hx0, av[1] - hx1),
                                   bfpack(av[2] - hx2, av[3] - hx3));
            hx0 = bfround(bv[0]); hx1 = bfround(bv[1]);
            hx2 = bfround(bv[2]); hx3 = bfround(bv[3]);
            uint2 bhi = make_uint2(bfpack(hx0, hx1), bfpack(hx2, hx3));
            uint2 blo = make_uint2(bfpack(bv[0] - hx0, bv[1] - hx1),
                                   bfpack(bv[2] - hx2, bv[3] - hx3));
            int o = r * S32 + p32;
            *(uint2*)(base + o)              = ahi;
            *(uint2*)(base + TILE32 + o)     = alo;
            *(uint2*)(base + 2 * TILE32 + o) = bhi;
            *(uint2*)(base + 3 * TILE32 + o) = blo;
        }
    };
    auto compute = [&](int buf) {
        const uint32_t bb = sbase + (uint32_t)buf * BUF32 * 4;
        const uint32_t a_h = bb + aoff;
        const uint32_t a_l = a_h + TILE32 * 4;
        const uint32_t b_h = bb + 2 * TILE32 * 4 + boff;
        const uint32_t b_l = b_h + TILE32 * 4;

        uint32_t ah[4][4], al[4][4], bh[4][2], bl[4][2];
        #pragma unroll
        for (int i = 0; i < 4; i++) {
            LDSM4(ah[i], a_h + (uint32_t)(i * 16 * S32) * 4);
            LDSM4(al[i], a_l + (uint32_t)(i * 16 * S32) * 4);
        }
        #pragma unroll
        for (int jp = 0; jp < 2; jp++) {
            uint32_t t[4];
            LDSM4(t, b_h + (uint32_t)(jp * 16 * S32) * 4);
            bh[jp * 2][0] = t[0]; bh[jp * 2][1] = t[1];
            bh[jp * 2 + 1][0] = t[2]; bh[jp * 2 + 1][1] = t[3];
            LDSM4(t, b_l + (uint32_t)(jp * 16 * S32) * 4);
            bl[jp * 2][0] = t[0]; bl[jp * 2][1] = t[1];
            bl[jp * 2 + 1][0] = t[2]; bl[jp * 2 + 1][1] = t[3];
        }
        #pragma unroll
        for (int j = 0; j < 4; j++)
            #pragma unroll
            for (int i = 0; i < 4; i++) {
                mma_bf16(acc[i][j], ah[i], bh[j][0], bh[j][1]);
                mma_bf16(acc[i][j], ah[i], bl[j][0], bl[j][1]);
                mma_bf16(acc[i][j], al[i], bh[j][0], bh[j][1]);
            }
    };

    loadG(0); storeS(0);
    __syncthreads();
    for (int c = 0; c < nc; c++) {
        if (c + 1 < nc) loadG(c + 1);
        compute(c & 1);
        if (c + 1 < nc) storeS((c + 1) & 1);
        __syncthreads();
    }

    #pragma unroll
    for (int i = 0; i < 4; i++) {
        int row = m0 + wr * 64 + i * 16 + tg;
        #pragma unroll
        for (int j = 0; j < 4; j++) {
            int col = n0 + wc * 32 + j * 8 + tig * 2;
            if (col >= ncols) continue;
            #pragma unroll
            for (int half = 0; half < 2; half++) {
                int r = row + half * 8;
                if (r >= Nrows) continue;
                float v0 = acc[i][j][half * 2 + 0];
                float v1 = acc[i][j][half * 2 + 1];
                if (bias) { v0 += bias[col]; v1 += bias[col + 1]; }
                if (act == 1) {
                    v0 = 0.5f * v0 * (1.0f + erff(v0 * 0.70710678118654752f));
                    v1 = 0.5f * v1 * (1.0f + erff(v1 * 0.70710678118654752f));
                }
                *(float2*)&C[(size_t)r * ncols + col] = make_float2(v0, v1);
            }
        }
    }
}

__global__ void transpose_k(const float* __restrict__ W, float* __restrict__ Bt,
                            int K, int M)
{
    __shared__ float t[32][33];
    int m0 = blockIdx.x * 32, k0 = blockIdx.y * 32;
    for (int i = threadIdx.y; i < 32; i += 8) {
        int k = k0 + i, m = m0 + threadIdx.x;
        t[i][threadIdx.x] = (k < K && m < M) ? W[(size_t)k * M + m] : 0.f;
    }
    __syncthreads();
    for (int i = threadIdx.y; i < 32; i += 8) {
        int m = m0 + i, k = k0 + threadIdx.x;
        if (m < M && k < K) Bt[(size_t)m * K + k] = t[threadIdx.x][i];
    }
}

// ---------------- CSR build --------------------------------------------------
__global__ void deg_zero_k()
{
    int i = blockIdx.x * blockDim.x + threadIdx.x;
    if (i < NN) g_deg[i] = 0;
}
__global__ void hist_k(const int* __restrict__ dst)
{
    int e = blockIdx.x * blockDim.x + threadIdx.x;
    if (e < EE) atomicAdd(&g_deg[dst[e]], 1);
}
__global__ void scan1_k()
{
    __shared__ int s[512];
    int tid = threadIdx.x;
    int i = blockIdx.x * 512 + tid;
    int v = (i < NN) ? g_deg[i] : 0;
    s[tid] = v;
    __syncthreads();
    for (int off = 1; off < 512; off <<= 1) {
        int t = (tid >= off) ? s[tid - off] : 0;
        __syncthreads();
        s[tid] += t;
        __syncthreads();
    }
    if (i < NN) g_rs[i] = s[tid] - v;
    if (tid == 511) g_part[blockIdx.x] = s[511];
}
__global__ void scan2_k(int nb)
{
    __shared__ int s[128];
    int tid = threadIdx.x;
    int v = (tid < nb) ? g_part[tid] : 0;
    s[tid] = v;
    __syncthreads();
    for (int off = 1; off < 128; off <<= 1) {
        int t = (tid >= off) ? s[tid - off] : 0;
        __syncthreads();
        s[tid] += t;
        __syncthreads();
    }
    if (tid < nb) g_part[tid] = s[tid] - v;
}
__global__ void scan3_k()
{
    int i = blockIdx.x * blockDim.x + threadIdx.x;
    if (i >= NN) return;
    int r = g_rs[i] + g_part[i >> 9];
    g_rs[i] = r;
    g_wp[i] = r;
}
__global__ void scatter_k(const int* __restrict__ src, const int* __restrict__ dst,
                          const float* __restrict__ ea)
{
    int e = blockIdx.x * blockDim.x + threadIdx.x;
    if (e >= EE) return;
    int d = dst[e];
    int pos = atomicAdd(&g_wp[d], 1);
    g_csrc[pos] = src[e];
    #pragma unroll
    for (int i = 0; i < 5; i++) g_cea[(size_t)pos * 5 + i] = ea[(size_t)e * 5 + i];
}

// ---------------- per-layer small kernels ------------------------------------
__global__ void ve_k(const float* __restrict__ We, const float* __restrict__ ae, int H)
{
    int tid = threadIdx.x;
    if (tid >= 5 * H) return;
    int d = tid / H, h = tid % H;
    int C = 256 / H;
    float s = 0.0f;
    for (int c = 0; c < C; c++) s += We[d * 256 + h * C + c] * ae[h * C + c];
    g_Ve[tid] = s;
}

__global__ void node_att_k(const float* __restrict__ hf,
                           const float* __restrict__ att_s,
                           const float* __restrict__ att_d,
                           float* __restrict__ as_, float* __restrict__ ad_,
                           int N, int H)
{
    int idx = blockIdx.x * blockDim.x + threadIdx.x;
    if (idx >= N * H) return;
    int C = 256 / H;
    int n = idx / H, hh = idx % H;
    const float4* hp = (const float4*)(hf + (size_t)n * 256 + hh * C);
    const float4* sp = (const float4*)(att_s + hh * C);
    const float4* dp = (const float4*)(att_d + hh * C);
    float ss = 0.0f, dd = 0.0f;
    for (int i = 0; i < C / 4; i++) {
        float4 v = hp[i], a = sp[i], b = dp[i];
        ss += v.x * a.x + v.y * a.y + v.z * a.z + v.w * a.w;
        dd += v.x * b.x + v.y * b.y + v.z * b.z + v.w * b.w;
    }
    as_[idx] = ss;
    ad_[idx] = dd;
}

// ---------------- fused single-pass edge softmax + aggregation ---------------
template <int H>
__global__ void __launch_bounds__(256)
gat_edge_k(const float* __restrict__ as_, const float* __restrict__ ad_,
           const float* __restrict__ hfeat, const float* __restrict__ bias,
           float* __restrict__ outf)
{
    int w = (blockIdx.x * blockDim.x + threadIdx.x) >> 5;
    if (w >= NN) return;
    int lane = threadIdx.x & 31;
    const int head = (H == 8) ? (lane >> 2) : 0;
    const int tig = lane & 3;
    const int col0 = lane * 8;

    float ve[5];
    #pragma unroll
    for (int i = 0; i < 5; i++) ve[i] = g_Ve[i * H + head];
    const float adv = ad_[w * H + head];
    const int r0 = g_rs[w], dg = g_deg[w];

    float den = 0.0f;
    float acc[8];
    #pragma unroll
    for (int q = 0; q < 8; q++) acc[q] = 0.0f;

    for (int j = 0; j < dg; j += 4) {
        int jj = j + tig;
        bool valid = jj < dg;
        int je = r0 + (valid ? jj : 0);
        int sq = g_csrc[je];
        const float* ce = g_cea + (size_t)je * 5;
        float a = as_[sq * H + head] + adv;
        #pragma unroll
        for (int i = 0; i < 5; i++) a = fmaf(ce[i], ve[i], a);
        a = a > 0.0f ? a : 0.2f * a;
        float pq = valid ? __expf(a) : 0.0f;
        #pragma unroll
        for (int q = 0; q < 4; q++) {
            float p = __shfl_sync(0xffffffffu, pq, (lane & ~3) | q);
            int s   = __shfl_sync(0xffffffffu, sq, q);
            if (p != 0.0f) {
                den += p;
                const float4* hp = (const float4*)(hfeat + (size_t)s * 256 + col0);
                float4 v0 = hp[0], v1 = hp[1];
                acc[0] = fmaf(p, v0.x, acc[0]); acc[1] = fmaf(p, v0.y, acc[1]);
                acc[2] = fmaf(p, v0.z, acc[2]); acc[3] = fmaf(p, v0.w, acc[3]);
                acc[4] = fmaf(p, v1.x, acc[4]); acc[5] = fmaf(p, v1.y, acc[5]);
                acc[6] = fmaf(p, v1.z, acc[6]); acc[7] = fmaf(p, v1.w, acc[7]);
            }
        }
    }

    float inv = 1.0f / (den + 1e-16f);
    float4 o0, o1;
    float* op = (float*)&o0;
    #pragma unroll
    for (int q = 0; q < 4; q++) op[q] = elu1(acc[q] * inv + bias[col0 + q]);
    op = (float*)&o1;
    #pragma unroll
    for (int q = 0; q < 4; q++) op[q] = elu1(acc[4 + q] * inv + bias[col0 + 4 + q]);
    *(float4*)&outf[(size_t)w * 256 + col0]     = o0;
    *(float4*)&outf[(size_t)w * 256 + col0 + 4] = o1;
}

// ---------------- pooling -----------------------------------------------------
__global__ void pool_zero_k()
{
    int t = blockIdx.x * blockDim.x + threadIdx.x;
    if (t < GG * 32) g_pool[t] = 0.0f;
    if (t < GG)      g_cnt[t]  = 0.0f;
}
__global__ void pool_acc_k(const float* __restrict__ y, const int* __restrict__ batch, int N)
{
    int idx = blockIdx.x * blockDim.x + threadIdx.x;
    if (idx >= N * 8) return;
    int n = idx >> 3, q = idx & 7;
    int g = batch[n];
    float4 v = ((const float4*)(y + (size_t)n * 32))[q];
    atomicAdd((float4*)&g_pool[g * 32 + q * 4], v);
    if (q == 0) atomicAdd(&g_cnt[g], 1.0f);
}
__global__ void pool_fin_k(float* __restrict__ out)
{
    int t = blockIdx.x * blockDim.x + threadIdx.x;
    if (t < GG * 32) out[t] = g_pool[t] / fmaxf(g_cnt[t >> 5], 1.0f);
}

// ============================================================================
static void launch_gemm(const float* A, const float* W, float* C,
                        int n, int K, int ncols, const float* bias, int act, float* bt)
{
    transpose_k<<<dim3((ncols + 31) / 32, (K + 31) / 32), dim3(32, 8)>>>(W, bt, K, ncols);
    dim3 grid((n + 127) / 128, (ncols + 127) / 128);
    mma_gemm_k<<<grid, 256, 2 * BUF32 * sizeof(uint32_t)>>>(A, bt, C, n, K, ncols, bias, act);
}

static void run_gat_layer(const float* in, int K,
                          const float* W, const float* as_att, const float* ad_att,
                          const float* We, const float* ae_att, const float* bias,
                          int H,
                          float* feat, float* h, float* as_, float* ad_, float* bt)
{
    launch_gemm(in, W, h, NN, K, HC, nullptr, 0, bt);
    ve_k<<<1, 64>>>(We, ae_att, H);
    node_att_k<<<(NN * H + 255) / 256, 256>>>(h, as_att, ad_att, as_, ad_, NN, H);
    int gb = (NN * 32 + 255) / 256;
    if (H == 8)
        gat_edge_k<8><<<gb, 256>>>(as_, ad_, h, bias, feat);
    else
        gat_edge_k<1><<<gb, 256>>>(as_, ad_, h, bias, feat);
}

extern "C" void kernel_launch(void* const* d_in, const int* in_sizes, int n_in,
                              void* d_out, int out_size)
{
    const float* x     = (const float*)d_in[0];
    const int*   ei    = (const int*)  d_in[1];
    const float* ea    = (const float*)d_in[2];
    const int*   batch = (const int*)  d_in[3];
    const float* W1  = (const float*)d_in[4];
    const float* as1 = (const float*)d_in[5];
    const float* ad1 = (const float*)d_in[6];
    const float* We1 = (const float*)d_in[7];
    const float* ae1 = (const float*)d_in[8];
    const float* b1  = (const float*)d_in[9];
    const float* W2  = (const float*)d_in[10];
    const float* as2 = (const float*)d_in[11];
    const float* ad2 = (const float*)d_in[12];
    const float* We2 = (const float*)d_in[13];
    const float* ae2 = (const float*)d_in[14];
    const float* b2  = (const float*)d_in[15];
    const float* W3  = (const float*)d_in[16];
    const float* as3 = (const float*)d_in[17];
    const float* ad3 = (const float*)d_in[18];
    const float* We3 = (const float*)d_in[19];
    const float* ae3 = (const float*)d_in[20];
    const float* b3  = (const float*)d_in[21];
    const float* fcW1 = (const float*)d_in[22];
    const float* fcb1 = (const float*)d_in[23];
    const float* fcW2 = (const float*)d_in[24];
    const float* fcb2 = (const float*)d_in[25];

    const int* src = ei;
    const int* dst = ei + EE;

    float *feat, *h, *agg, *as_, *ad_, *bt;
    cudaGetSymbolAddress((void**)&feat, g_feat);
    cudaGetSymbolAddress((void**)&h,    g_h);
    cudaGetSymbolAddress((void**)&agg,  g_agg);
    cudaGetSymbolAddress((void**)&as_,  g_as);
    cudaGetSymbolAddress((void**)&ad_,  g_ad);
    cudaGetSymbolAddress((void**)&bt,   g_bt);

    cudaFuncSetAttribute(mma_gemm_k, cudaFuncAttributeMaxDynamicSharedMemorySize,
                         2 * BUF32 * sizeof(uint32_t));

    // ---- CSR build (once; reused by all 3 layers) ----
    deg_zero_k<<<(NN + 255) / 256, 256>>>();
    hist_k<<<(EE + 255) / 256, 256>>>(dst);
    int nb = (NN + 511) / 512;
    scan1_k<<<nb, 512>>>();
    scan2_k<<<1, 128>>>(nb);
    scan3_k<<<(NN + 255) / 256, 256>>>();
    scatter_k<<<(EE + 255) / 256, 256>>>(src, dst, ea);

    // ---- 3 GAT layers ----
    run_gat_layer(x,    128, W1, as1, ad1, We1, ae1, b1, 8, feat, h, as_, ad_, bt);
    run_gat_layer(feat, 256, W2, as2, ad2, We2, ae2, b2, 8, feat, h, as_, ad_, bt);
    run_gat_layer(feat, 256, W3, as3, ad3, We3, ae3, b3, 1, feat, h, as_, ad_, bt);

    // ---- MLP head ----
    launch_gemm(feat, fcW1, h, NN, 256, 256, fcb1, 1, bt);
    launch_gemm(h, fcW2, agg, NN, 256, 32, fcb2, 0, bt);

    // ---- global mean pool ----
    pool_zero_k<<<(GG * 32 + 255) / 256, 256>>>();
    pool_acc_k<<<(NN * 8 + 255) / 256, 256>>>(agg, batch, NN);
    pool_fin_k<<<(GG * 32 + 255) / 256, 256>>>((float*)d_out);
}

// round 8
// speedup vs baseline: 1.8481x; 1.0309x over previous
#include <cuda_runtime.h>
#include <cuda_bf16.h>
#include <math.h>
#include <stdint.h>

#define NN 50000
#define EE 400000
#define GG 64
#define HC 256

// ---------------- scratch (static device globals) ---------------------------
__device__ float g_feat [NN * HC];
__device__ float g_h    [NN * HC];
__device__ float g_agg  [NN * HC];
__device__ float g_as   [NN * 8];
__device__ float g_ad   [NN * 8];
__device__ float g_VeAll[96];              // 40 + 40 + 5 (padded)
__device__ float g_pool [GG * 32];
__device__ float g_cnt  [GG];
__device__ float g_btall[5 * 256 * 256];   // 5 transposed weight slabs
// CSR
__device__ int   g_deg [NN];
__device__ int   g_rs  [NN];
__device__ int   g_wp  [NN];
__device__ int   g_part[128];
__device__ int   g_csrc[EE];
__device__ float g_cea [EE * 5];

// ---------------- helpers ---------------------------------------------------
__device__ __forceinline__ float elu1(float x) { return x > 0.0f ? x : expm1f(x); }

__device__ __forceinline__ uint32_t bfpack(float lo_e, float hi_e) {
    uint32_t r;
    asm("cvt.rn.bf16x2.f32 %0, %1, %2;" : "=r"(r) : "f"(hi_e), "f"(lo_e));
    return r;
}
__device__ __forceinline__ float bfround(float x) {
    uint16_t b;
    asm("cvt.rn.bf16.f32 %0, %1;" : "=h"(b) : "f"(x));
    float r;
    asm("cvt.f32.bf16 %0, %1;" : "=f"(r) : "h"(b));
    return r;
}

__device__ __forceinline__ void mma_bf16(float* d, const uint32_t* a,
                                         uint32_t b0, uint32_t b1) {
    asm volatile(
        "mma.sync.aligned.m16n8k16.row.col.f32.bf16.bf16.f32 "
        "{%0,%1,%2,%3}, {%4,%5,%6,%7}, {%8,%9}, {%0,%1,%2,%3};"
        : "+f"(d[0]), "+f"(d[1]), "+f"(d[2]), "+f"(d[3])
        : "r"(a[0]), "r"(a[1]), "r"(a[2]), "r"(a[3]), "r"(b0), "r"(b1));
}

#define LDSM4(r, addr) \
    asm volatile("ldmatrix.sync.aligned.m8n8.x4.shared.b16 {%0,%1,%2,%3}, [%4];" \
        : "=r"((r)[0]), "=r"((r)[1]), "=r"((r)[2]), "=r"((r)[3]) : "r"(addr))

// ---------------- warp-MMA 3xBF16 GEMM, 128x128 CTA tile, K chunks of 16 ----
#define S32 12
#define TILE32 (128 * S32)
#define BUF32 (4 * TILE32)

__global__ void __launch_bounds__(256, 2)
mma_gemm_k(const float* __restrict__ A, const float* __restrict__ Bt,
           float* __restrict__ C, int Nrows, int K, int ncols,
           const float* __restrict__ bias, int act)
{
    extern __shared__ uint32_t sm32[];
    uint32_t sbase;
    asm("{ .reg .u64 t; cvta.to.shared.u64 t, %1; cvt.u32.u64 %0, t; }"
        : "=r"(sbase) : "l"(sm32));

    const int tid = threadIdx.x;
    const int lane = tid & 31, wid = tid >> 5;
    const int wr = wid >> 2, wc = wid & 3;
    const int tg = lane >> 2, tig = lane & 3;
    const int m0 = blockIdx.x * 128, n0 = blockIdx.y * 128;
    // warp-uniform: number of active 8-col j blocks for this warp column
    const int jcnt = max(0, min(4, (ncols - n0 - wc * 32 + 7) >> 3));

    const int lr = lane & 7, seg = lane >> 3;
    const uint32_t aoff = (uint32_t)((wr * 64 + lr + (seg & 1) * 8) * S32) * 4
                        + (uint32_t)(seg >> 1) * 16;
    const uint32_t boff = (uint32_t)((wc * 32 + (seg >> 1) * 8 + lr) * S32) * 4
                        + (uint32_t)(seg & 1) * 16;

    float acc[4][4][4];
    #pragma unroll
    for (int i = 0; i < 4; i++)
        #pragma unroll
        for (int j = 0; j < 4; j++)
            #pragma unroll
            for (int q = 0; q < 4; q++) acc[i][j][q] = 0.0f;

    const int nc = K / 16;
    float4 aReg[2], bReg[2];

    auto loadG = [&](int c) {
        const int k0 = c * 16;
        #pragma unroll
        for (int i = 0; i < 2; i++) {
            int idx = tid + i * 256;
            int r = idx >> 2, c4 = (idx & 3) * 4;
            int grow = m0 + r;
            aReg[i] = (grow < Nrows) ? *(const float4*)&A[(size_t)grow * K + k0 + c4]
                                     : make_float4(0.f, 0.f, 0.f, 0.f);
            int gn = n0 + r;
            bReg[i] = (gn < ncols) ? *(const float4*)&Bt[(size_t)gn * K + k0 + c4]
                                   : make_float4(0.f, 0.f, 0.f, 0.f);
        }
    };
    auto storeS = [&](int buf) {
        uint32_t* base = sm32 + buf * BUF32;
        #pragma unroll
        for (int i = 0; i < 2; i++) {
            int idx = tid + i * 256;
            int r = idx >> 2, p32 = (idx & 3) * 2;
            const float* av = (const float*)&aReg[i];
            const float* bv = (const float*)&bReg[i];
            float hx0 = bfround(av[0]), hx1 = bfround(av[1]);
            float hx2 = bfround(av[2]), hx3 = bfround(av[3]);
            uint2 ahi = make_uint2(bfpack(hx0, hx1), bfpack(hx2, hx3));
            uint2 alo = make_uint2(bfpack(av[0] - hx0, av[1] - hx1),
                                   bfpack(av[2] - hx2, av[3] - hx3));
            hx0 = bfround(bv[0]); hx1 = bfround(bv[1]);
            hx2 = bfround(bv[2]); hx3 = bfround(bv[3]);
            uint2 bhi = make_uint2(bfpack(hx0, hx1), bfpack(hx2, hx3));
            uint2 blo = make_uint2(bfpack(bv[0] - hx0, bv[1] - hx1),
                                   bfpack(bv[2] - hx2, bv[3] - hx3));
            int o = r * S32 + p32;
            *(uint2*)(base + o)              = ahi;
            *(uint2*)(base + TILE32 + o)     = alo;
            *(uint2*)(base + 2 * TILE32 + o) = bhi;
            *(uint2*)(base + 3 * TILE32 + o) = blo;
        }
    };
    auto compute = [&](int buf) {
        const uint32_t bb = sbase + (uint32_t)buf * BUF32 * 4;
        const uint32_t a_h = bb + aoff;
        const uint32_t a_l = a_h + TILE32 * 4;
        const uint32_t b_h = bb + 2 * TILE32 * 4 + boff;
        const uint32_t b_l = b_h + TILE32 * 4;

        uint32_t ah[4][4], al[4][4], bh[4][2], bl[4][2];
        #pragma unroll
        for (int i = 0; i < 4; i++) {
            LDSM4(ah[i], a_h + (uint32_t)(i * 16 * S32) * 4);
            LDSM4(al[i], a_l + (uint32_t)(i * 16 * S32) * 4);
        }
        #pragma unroll
        for (int jp = 0; jp < 2; jp++) {
            uint32_t t[4];
            LDSM4(t, b_h + (uint32_t)(jp * 16 * S32) * 4);
            bh[jp * 2][0] = t[0]; bh[jp * 2][1] = t[1];
            bh[jp * 2 + 1][0] = t[2]; bh[jp * 2 + 1][1] = t[3];
            LDSM4(t, b_l + (uint32_t)(jp * 16 * S32) * 4);
            bl[jp * 2][0] = t[0]; bl[jp * 2][1] = t[1];
            bl[jp * 2 + 1][0] = t[2]; bl[jp * 2 + 1][1] = t[3];
        }
        #pragma unroll
        for (int j = 0; j < 4; j++) {
            if (j >= jcnt) break;           // warp-uniform skip (narrow GEMMs)
            #pragma unroll
            for (int i = 0; i < 4; i++) {
                mma_bf16(acc[i][j], ah[i], bh[j][0], bh[j][1]);
                mma_bf16(acc[i][j], ah[i], bl[j][0], bl[j][1]);
                mma_bf16(acc[i][j], al[i], bh[j][0], bh[j][1]);
            }
        }
    };

    loadG(0); storeS(0);
    __syncthreads();
    for (int c = 0; c < nc; c++) {
        if (c + 1 < nc) loadG(c + 1);
        compute(c & 1);
        if (c + 1 < nc) storeS((c + 1) & 1);
        __syncthreads();
    }

    #pragma unroll
    for (int i = 0; i < 4; i++) {
        int row = m0 + wr * 64 + i * 16 + tg;
        #pragma unroll
        for (int j = 0; j < 4; j++) {
            int col = n0 + wc * 32 + j * 8 + tig * 2;
            if (col >= ncols) continue;
            #pragma unroll
            for (int half = 0; half < 2; half++) {
                int r = row + half * 8;
                if (r >= Nrows) continue;
                float v0 = acc[i][j][half * 2 + 0];
                float v1 = acc[i][j][half * 2 + 1];
                if (bias) { v0 += bias[col]; v1 += bias[col + 1]; }
                if (act == 1) {
                    v0 = 0.5f * v0 * (1.0f + erff(v0 * 0.70710678118654752f));
                    v1 = 0.5f * v1 * (1.0f + erff(v1 * 0.70710678118654752f));
                }
                *(float2*)&C[(size_t)r * ncols + col] = make_float2(v0, v1);
            }
        }
    }
}

// ---------------- batched weight transpose (all 5 at once) -------------------
__global__ void transpose_all_k(const float* __restrict__ W1, const float* __restrict__ W2,
                                const float* __restrict__ W3, const float* __restrict__ f1,
                                const float* __restrict__ f2)
{
    __shared__ float t[32][33];
    int z = blockIdx.z;
    const float* W = (z == 0) ? W1 : (z == 1) ? W2 : (z == 2) ? W3 : (z == 3) ? f1 : f2;
    int K = (z == 0) ? 128 : 256;
    int M = (z == 4) ? 32 : 256;
    float* Bt = g_btall + z * 65536;
    int m0 = blockIdx.x * 32, k0 = blockIdx.y * 32;
    if (m0 >= M || k0 >= K) return;
    for (int i = threadIdx.y; i < 32; i += 8) {
        int k = k0 + i, m = m0 + threadIdx.x;
        t[i][threadIdx.x] = (k < K && m < M) ? W[(size_t)k * M + m] : 0.f;
    }
    __syncthreads();
    for (int i = threadIdx.y; i < 32; i += 8) {
        int m = m0 + i, k = k0 + threadIdx.x;
        if (m < M && k < K) Bt[(size_t)m * K + k] = t[threadIdx.x][i];
    }
}

// ---------------- batched Ve (all 3 layers) -----------------------------------
__global__ void ve_all_k(const float* __restrict__ We1, const float* __restrict__ ae1,
                         const float* __restrict__ We2, const float* __restrict__ ae2,
                         const float* __restrict__ We3, const float* __restrict__ ae3)
{
    int tid = threadIdx.x;
    const float* We; const float* ae; int H, base, loc;
    if (tid < 40)      { We = We1; ae = ae1; H = 8; base = 0;  loc = tid; }
    else if (tid < 80) { We = We2; ae = ae2; H = 8; base = 40; loc = tid - 40; }
    else if (tid < 85) { We = We3; ae = ae3; H = 1; base = 80; loc = tid - 80; }
    else return;
    int d = loc / H, h = loc % H;
    int C = 256 / H;
    float s = 0.0f;
    for (int c = 0; c < C; c++) s += We[d * 256 + h * C + c] * ae[h * C + c];
    g_VeAll[base + loc] = s;
}

// ---------------- CSR build --------------------------------------------------
__global__ void deg_zero_k()
{
    int i = blockIdx.x * blockDim.x + threadIdx.x;
    if (i < NN) g_deg[i] = 0;
}
__global__ void hist_k(const int* __restrict__ dst)
{
    int e = blockIdx.x * blockDim.x + threadIdx.x;
    if (e < EE) atomicAdd(&g_deg[dst[e]], 1);
}
__global__ void scan1_k()
{
    __shared__ int s[512];
    int tid = threadIdx.x;
    int i = blockIdx.x * 512 + tid;
    int v = (i < NN) ? g_deg[i] : 0;
    s[tid] = v;
    __syncthreads();
    for (int off = 1; off < 512; off <<= 1) {
        int t = (tid >= off) ? s[tid - off] : 0;
        __syncthreads();
        s[tid] += t;
        __syncthreads();
    }
    if (i < NN) g_rs[i] = s[tid] - v;
    if (tid == 511) g_part[blockIdx.x] = s[511];
}
__global__ void scan2_k(int nb)
{
    __shared__ int s[128];
    int tid = threadIdx.x;
    int v = (tid < nb) ? g_part[tid] : 0;
    s[tid] = v;
    __syncthreads();
    for (int off = 1; off < 128; off <<= 1) {
        int t = (tid >= off) ? s[tid - off] : 0;
        __syncthreads();
        s[tid] += t;
        __syncthreads();
    }
    if (tid < nb) g_part[tid] = s[tid] - v;
}
__global__ void scan3_k()
{
    int i = blockIdx.x * blockDim.x + threadIdx.x;
    if (i >= NN) return;
    int r = g_rs[i] + g_part[i >> 9];
    g_rs[i] = r;
    g_wp[i] = r;
}
__global__ void scatter_k(const int* __restrict__ src, const int* __restrict__ dst,
                          const float* __restrict__ ea)
{
    int e = blockIdx.x * blockDim.x + threadIdx.x;
    if (e >= EE) return;
    int d = dst[e];
    int pos = atomicAdd(&g_wp[d], 1);
    g_csrc[pos] = src[e];
    #pragma unroll
    for (int i = 0; i < 5; i++) g_cea[(size_t)pos * 5 + i] = ea[(size_t)e * 5 + i];
}

// ---------------- node attention scores --------------------------------------
__global__ void node_att_k(const float* __restrict__ hf,
                           const float* __restrict__ att_s,
                           const float* __restrict__ att_d,
                           float* __restrict__ as_, float* __restrict__ ad_,
                           int N, int H)
{
    int idx = blockIdx.x * blockDim.x + threadIdx.x;
    if (idx >= N * H) return;
    int C = 256 / H;
    int n = idx / H, hh = idx % H;
    const float4* hp = (const float4*)(hf + (size_t)n * 256 + hh * C);
    const float4* sp = (const float4*)(att_s + hh * C);
    const float4* dp = (const float4*)(att_d + hh * C);
    float ss = 0.0f, dd = 0.0f;
    for (int i = 0; i < C / 4; i++) {
        float4 v = hp[i], a = sp[i], b = dp[i];
        ss += v.x * a.x + v.y * a.y + v.z * a.z + v.w * a.w;
        dd += v.x * b.x + v.y * b.y + v.z * b.z + v.w * b.w;
    }
    as_[idx] = ss;
    ad_[idx] = dd;
}

// ---------------- fused single-pass edge softmax + aggregation ---------------
template <int H>
__global__ void __launch_bounds__(256)
gat_edge_k(const float* __restrict__ as_, const float* __restrict__ ad_,
           const float* __restrict__ hfeat, const float* __restrict__ bias,
           float* __restrict__ outf, int veBase)
{
    int w = (blockIdx.x * blockDim.x + threadIdx.x) >> 5;
    if (w >= NN) return;
    int lane = threadIdx.x & 31;
    const int head = (H == 8) ? (lane >> 2) : 0;
    const int tig = lane & 3;
    const int col0 = lane * 8;

    float ve[5];
    #pragma unroll
    for (int i = 0; i < 5; i++) ve[i] = g_VeAll[veBase + i * H + head];
    const float adv = ad_[w * H + head];
    const int r0 = g_rs[w], dg = g_deg[w];

    float den = 0.0f;
    float acc[8];
    #pragma unroll
    for (int q = 0; q < 8; q++) acc[q] = 0.0f;

    for (int j = 0; j < dg; j += 4) {
        int jj = j + tig;
        bool valid = jj < dg;
        int je = r0 + (valid ? jj : 0);
        int sq = g_csrc[je];
        const float* ce = g_cea + (size_t)je * 5;
        float a = as_[sq * H + head] + adv;
        #pragma unroll
        for (int i = 0; i < 5; i++) a = fmaf(ce[i], ve[i], a);
        a = a > 0.0f ? a : 0.2f * a;
        float pq = valid ? __expf(a) : 0.0f;
        #pragma unroll
        for (int q = 0; q < 4; q++) {
            float p = __shfl_sync(0xffffffffu, pq, (lane & ~3) | q);
            int s   = __shfl_sync(0xffffffffu, sq, q);
            if (p != 0.0f) {
                den += p;
                const float4* hp = (const float4*)(hfeat + (size_t)s * 256 + col0);
                float4 v0 = hp[0], v1 = hp[1];
                acc[0] = fmaf(p, v0.x, acc[0]); acc[1] = fmaf(p, v0.y, acc[1]);
                acc[2] = fmaf(p, v0.z, acc[2]); acc[3] = fmaf(p, v0.w, acc[3]);
                acc[4] = fmaf(p, v1.x, acc[4]); acc[5] = fmaf(p, v1.y, acc[5]);
                acc[6] = fmaf(p, v1.z, acc[6]); acc[7] = fmaf(p, v1.w, acc[7]);
            }
        }
    }

    float inv = 1.0f / (den + 1e-16f);
    float4 o0, o1;
    float* op = (float*)&o0;
    #pragma unroll
    for (int q = 0; q < 4; q++) op[q] = elu1(acc[q] * inv + bias[col0 + q]);
    op = (float*)&o1;
    #pragma unroll
    for (int q = 0; q < 4; q++) op[q] = elu1(acc[4 + q] * inv + bias[col0 + 4 + q]);
    *(float4*)&outf[(size_t)w * 256 + col0]     = o0;
    *(float4*)&outf[(size_t)w * 256 + col0 + 4] = o1;
}

// ---------------- pooling -----------------------------------------------------
__global__ void pool_zero_k()
{
    int t = blockIdx.x * blockDim.x + threadIdx.x;
    if (t < GG * 32) g_pool[t] = 0.0f;
    if (t < GG)      g_cnt[t]  = 0.0f;
}
__global__ void pool_acc_k(const float* __restrict__ y, const int* __restrict__ batch, int N)
{
    int idx = blockIdx.x * blockDim.x + threadIdx.x;
    if (idx >= N * 8) return;
    int n = idx >> 3, q = idx & 7;
    int g = batch[n];
    float4 v = ((const float4*)(y + (size_t)n * 32))[q];
    atomicAdd((float4*)&g_pool[g * 32 + q * 4], v);
    if (q == 0) atomicAdd(&g_cnt[g], 1.0f);
}
__global__ void pool_fin_k(float* __restrict__ out)
{
    int t = blockIdx.x * blockDim.x + threadIdx.x;
    if (t < GG * 32) out[t] = g_pool[t] / fmaxf(g_cnt[t >> 5], 1.0f);
}

// ============================================================================
static void launch_gemm(const float* A, const float* bt, float* C,
                        int n, int K, int ncols, const float* bias, int act)
{
    dim3 grid((n + 127) / 128, (ncols + 127) / 128);
    mma_gemm_k<<<grid, 256, 2 * BUF32 * sizeof(uint32_t)>>>(A, bt, C, n, K, ncols, bias, act);
}

static void run_gat_layer(const float* in, int K, const float* bt,
                          const float* as_att, const float* ad_att, const float* bias,
                          int H, int veBase,
                          float* feat, float* h, float* as_, float* ad_)
{
    launch_gemm(in, bt, h, NN, K, HC, nullptr, 0);
    node_att_k<<<(NN * H + 255) / 256, 256>>>(h, as_att, ad_att, as_, ad_, NN, H);
    int gb = (NN * 32 + 255) / 256;
    if (H == 8)
        gat_edge_k<8><<<gb, 256>>>(as_, ad_, h, bias, feat, veBase);
    else
        gat_edge_k<1><<<gb, 256>>>(as_, ad_, h, bias, feat, veBase);
}

extern "C" void kernel_launch(void* const* d_in, const int* in_sizes, int n_in,
                              void* d_out, int out_size)
{
    const float* x     = (const float*)d_in[0];
    const int*   ei    = (const int*)  d_in[1];
    const float* ea    = (const float*)d_in[2];
    const int*   batch = (const int*)  d_in[3];
    const float* W1  = (const float*)d_in[4];
    const float* as1 = (const float*)d_in[5];
    const float* ad1 = (const float*)d_in[6];
    const float* We1 = (const float*)d_in[7];
    const float* ae1 = (const float*)d_in[8];
    const float* b1  = (const float*)d_in[9];
    const float* W2  = (const float*)d_in[10];
    const float* as2 = (const float*)d_in[11];
    const float* ad2 = (const float*)d_in[12];
    const float* We2 = (const float*)d_in[13];
    const float* ae2 = (const float*)d_in[14];
    const float* b2  = (const float*)d_in[15];
    const float* W3  = (const float*)d_in[16];
    const float* as3 = (const float*)d_in[17];
    const float* ad3 = (const float*)d_in[18];
    const float* We3 = (const float*)d_in[19];
    const float* ae3 = (const float*)d_in[20];
    const float* b3  = (const float*)d_in[21];
    const float* fcW1 = (const float*)d_in[22];
    const float* fcb1 = (const float*)d_in[23];
    const float* fcW2 = (const float*)d_in[24];
    const float* fcb2 = (const float*)d_in[25];

    const int* src = ei;
    const int* dst = ei + EE;

    float *feat, *h, *agg, *as_, *ad_, *btall;
    cudaGetSymbolAddress((void**)&feat,  g_feat);
    cudaGetSymbolAddress((void**)&h,     g_h);
    cudaGetSymbolAddress((void**)&agg,   g_agg);
    cudaGetSymbolAddress((void**)&as_,   g_as);
    cudaGetSymbolAddress((void**)&ad_,   g_ad);
    cudaGetSymbolAddress((void**)&btall, g_btall);

    cudaFuncSetAttribute(mma_gemm_k, cudaFuncAttributeMaxDynamicSharedMemorySize,
                         2 * BUF32 * sizeof(uint32_t));

    // ---- upfront: batched transposes + Ve ----
    transpose_all_k<<<dim3(8, 8, 5), dim3(32, 8)>>>(W1, W2, W3, fcW1, fcW2);
    ve_all_k<<<1, 96>>>(We1, ae1, We2, ae2, We3, ae3);

    // ---- CSR build ----
    deg_zero_k<<<(NN + 255) / 256, 256>>>();
    hist_k<<<(EE + 255) / 256, 256>>>(dst);
    int nb = (NN + 511) / 512;
    scan1_k<<<nb, 512>>>();
    scan2_k<<<1, 128>>>(nb);
    scan3_k<<<(NN + 255) / 256, 256>>>();
    scatter_k<<<(EE + 255) / 256, 256>>>(src, dst, ea);

    // ---- 3 GAT layers ----
    run_gat_layer(x,    128, btall,               as1, ad1, b1, 8, 0,  feat, h, as_, ad_);
    run_gat_layer(feat, 256, btall + 1 * 65536,   as2, ad2, b2, 8, 40, feat, h, as_, ad_);
    run_gat_layer(feat, 256, btall + 2 * 65536,   as3, ad3, b3, 1, 80, feat, h, as_, ad_);

    // ---- MLP head ----
    launch_gemm(feat, btall + 3 * 65536, h, NN, 256, 256, fcb1, 1);
    launch_gemm(h,    btall + 4 * 65536, agg, NN, 256, 32, fcb2, 0);

    // ---- global mean pool ----
    pool_zero_k<<<(GG * 32 + 255) / 256, 256>>>();
    pool_acc_k<<<(NN * 8 + 255) / 256, 256>>>(agg, batch, NN);
    pool_fin_k<<<(GG * 32 + 255) / 256, 256>>>((float*)d_out);
}

// round 9
// speedup vs baseline: 2.1289x; 1.1519x over previous
#include <cuda_runtime.h>
#include <cuda_bf16.h>
#include <math.h>
#include <stdint.h>

#define NN 50000
#define EE 400000
#define GG 64
#define HC 256

// ---------------- scratch (static device globals) ---------------------------
__device__ float g_feat [NN * HC];
__device__ float g_h    [NN * HC];
__device__ float g_agg  [NN * HC];
__device__ float g_as   [NN * 8];
__device__ float g_ad   [NN * 8];
__device__ float g_VeAll[96];
__device__ float g_pool [GG * 32];
__device__ float g_cnt  [GG];
__device__ float g_btall[5 * 256 * 256];
// CSR
__device__ int   g_deg [NN];
__device__ int   g_rs  [NN];
__device__ int   g_wp  [NN];
__device__ int   g_part[128];
__device__ int   g_csrc[EE];
__device__ float g_cea [EE * 5];

// ---------------- helpers ---------------------------------------------------
__device__ __forceinline__ float elu1(float x) { return x > 0.0f ? x : expm1f(x); }

__device__ __forceinline__ uint32_t bfpack(float lo_e, float hi_e) {
    uint32_t r;
    asm("cvt.rn.bf16x2.f32 %0, %1, %2;" : "=r"(r) : "f"(hi_e), "f"(lo_e));
    return r;
}
__device__ __forceinline__ float bfround(float x) {
    uint16_t b;
    asm("cvt.rn.bf16.f32 %0, %1;" : "=h"(b) : "f"(x));
    float r;
    asm("cvt.f32.bf16 %0, %1;" : "=f"(r) : "h"(b));
    return r;
}

__device__ __forceinline__ void mma_bf16(float* d, const uint32_t* a,
                                         uint32_t b0, uint32_t b1) {
    asm volatile(
        "mma.sync.aligned.m16n8k16.row.col.f32.bf16.bf16.f32 "
        "{%0,%1,%2,%3}, {%4,%5,%6,%7}, {%8,%9}, {%0,%1,%2,%3};"
        : "+f"(d[0]), "+f"(d[1]), "+f"(d[2]), "+f"(d[3])
        : "r"(a[0]), "r"(a[1]), "r"(a[2]), "r"(a[3]), "r"(b0), "r"(b1));
}

#define LDSM4(r, addr) \
    asm volatile("ldmatrix.sync.aligned.m8n8.x4.shared.b16 {%0,%1,%2,%3}, [%4];" \
        : "=r"((r)[0]), "=r"((r)[1]), "=r"((r)[2]), "=r"((r)[3]) : "r"(addr))

// ---------------- warp-MMA 3xBF16 GEMM, 128x128 CTA tile, K chunks of 16 ----
// Optional fused node-attention epilogue: as/ad partial dots via quad reduce +
// atomicAdd (as_out != nullptr). att buffers must be pre-zeroed.
#define S32 12
#define TILE32 (128 * S32)
#define BUF32 (4 * TILE32)

__global__ void __launch_bounds__(256, 2)
mma_gemm_k(const float* __restrict__ A, const float* __restrict__ Bt,
           float* __restrict__ C, int Nrows, int K, int ncols,
           const float* __restrict__ bias, int act,
           const float* __restrict__ att_s, const float* __restrict__ att_d,
           float* __restrict__ as_out, float* __restrict__ ad_out, int H)
{
    extern __shared__ uint32_t sm32[];
    uint32_t sbase;
    asm("{ .reg .u64 t; cvta.to.shared.u64 t, %1; cvt.u32.u64 %0, t; }"
        : "=r"(sbase) : "l"(sm32));

    const int tid = threadIdx.x;
    const int lane = tid & 31, wid = tid >> 5;
    const int wr = wid >> 2, wc = wid & 3;
    const int tg = lane >> 2, tig = lane & 3;
    const int m0 = blockIdx.x * 128, n0 = blockIdx.y * 128;
    const int jcnt = max(0, min(4, (ncols - n0 - wc * 32 + 7) >> 3));

    const int lr = lane & 7, seg = lane >> 3;
    const uint32_t aoff = (uint32_t)((wr * 64 + lr + (seg & 1) * 8) * S32) * 4
                        + (uint32_t)(seg >> 1) * 16;
    const uint32_t boff = (uint32_t)((wc * 32 + (seg >> 1) * 8 + lr) * S32) * 4
                        + (uint32_t)(seg & 1) * 16;

    float acc[4][4][4];
    #pragma unroll
    for (int i = 0; i < 4; i++)
        #pragma unroll
        for (int j = 0; j < 4; j++)
            #pragma unroll
            for (int q = 0; q < 4; q++) acc[i][j][q] = 0.0f;

    const int nc = K / 16;
    float4 aReg[2], bReg[2];

    auto loadG = [&](int c) {
        const int k0 = c * 16;
        #pragma unroll
        for (int i = 0; i < 2; i++) {
            int idx = tid + i * 256;
            int r = idx >> 2, c4 = (idx & 3) * 4;
            int grow = m0 + r;
            aReg[i] = (grow < Nrows) ? *(const float4*)&A[(size_t)grow * K + k0 + c4]
                                     : make_float4(0.f, 0.f, 0.f, 0.f);
            int gn = n0 + r;
            bReg[i] = (gn < ncols) ? *(const float4*)&Bt[(size_t)gn * K + k0 + c4]
                                   : make_float4(0.f, 0.f, 0.f, 0.f);
        }
    };
    auto storeS = [&](int buf) {
        uint32_t* base = sm32 + buf * BUF32;
        #pragma unroll
        for (int i = 0; i < 2; i++) {
            int idx = tid + i * 256;
            int r = idx >> 2, p32 = (idx & 3) * 2;
            const float* av = (const float*)&aReg[i];
            const float* bv = (const float*)&bReg[i];
            float hx0 = bfround(av[0]), hx1 = bfround(av[1]);
            float hx2 = bfround(av[2]), hx3 = bfround(av[3]);
            uint2 ahi = make_uint2(bfpack(hx0, hx1), bfpack(hx2, hx3));
            uint2 alo = make_uint2(bfpack(av[0] - hx0, av[1] - hx1),
                                   bfpack(av[2] - hx2, av[3] - hx3));
            hx0 = bfround(bv[0]); hx1 = bfround(bv[1]);
            hx2 = bfround(bv[2]); hx3 = bfround(bv[3]);
            uint2 bhi = make_uint2(bfpack(hx0, hx1), bfpack(hx2, hx3));
            uint2 blo = make_uint2(bfpack(bv[0] - hx0, bv[1] - hx1),
                                   bfpack(bv[2] - hx2, bv[3] - hx3));
            int o = r * S32 + p32;
            *(uint2*)(base + o)              = ahi;
            *(uint2*)(base + TILE32 + o)     = alo;
            *(uint2*)(base + 2 * TILE32 + o) = bhi;
            *(uint2*)(base + 3 * TILE32 + o) = blo;
        }
    };
    auto compute = [&](int buf) {
        const uint32_t bb = sbase + (uint32_t)buf * BUF32 * 4;
        const uint32_t a_h = bb + aoff;
        const uint32_t a_l = a_h + TILE32 * 4;
        const uint32_t b_h = bb + 2 * TILE32 * 4 + boff;
        const uint32_t b_l = b_h + TILE32 * 4;

        uint32_t ah[4][4], al[4][4], bh[4][2], bl[4][2];
        #pragma unroll
        for (int i = 0; i < 4; i++) {
            LDSM4(ah[i], a_h + (uint32_t)(i * 16 * S32) * 4);
            LDSM4(al[i], a_l + (uint32_t)(i * 16 * S32) * 4);
        }
        #pragma unroll
        for (int jp = 0; jp < 2; jp++) {
            uint32_t t[4];
            LDSM4(t, b_h + (uint32_t)(jp * 16 * S32) * 4);
            bh[jp * 2][0] = t[0]; bh[jp * 2][1] = t[1];
            bh[jp * 2 + 1][0] = t[2]; bh[jp * 2 + 1][1] = t[3];
            LDSM4(t, b_l + (uint32_t)(jp * 16 * S32) * 4);
            bl[jp * 2][0] = t[0]; bl[jp * 2][1] = t[1];
            bl[jp * 2 + 1][0] = t[2]; bl[jp * 2 + 1][1] = t[3];
        }
        #pragma unroll
        for (int j = 0; j < 4; j++) {
            if (j >= jcnt) break;
            #pragma unroll
            for (int i = 0; i < 4; i++) {
                mma_bf16(acc[i][j], ah[i], bh[j][0], bh[j][1]);
                mma_bf16(acc[i][j], ah[i], bl[j][0], bl[j][1]);
                mma_bf16(acc[i][j], al[i], bh[j][0], bh[j][1]);
            }
        }
    };

    loadG(0); storeS(0);
    __syncthreads();
    for (int c = 0; c < nc; c++) {
        if (c + 1 < nc) loadG(c + 1);
        compute(c & 1);
        if (c + 1 < nc) storeS((c + 1) & 1);
        __syncthreads();
    }

    // ---- C store epilogue ----
    #pragma unroll
    for (int i = 0; i < 4; i++) {
        int row = m0 + wr * 64 + i * 16 + tg;
        #pragma unroll
        for (int j = 0; j < 4; j++) {
            int col = n0 + wc * 32 + j * 8 + tig * 2;
            if (col >= ncols) continue;
            #pragma unroll
            for (int half = 0; half < 2; half++) {
                int r = row + half * 8;
                if (r >= Nrows) continue;
                float v0 = acc[i][j][half * 2 + 0];
                float v1 = acc[i][j][half * 2 + 1];
                if (bias) { v0 += bias[col]; v1 += bias[col + 1]; }
                if (act == 1) {
                    v0 = 0.5f * v0 * (1.0f + erff(v0 * 0.70710678118654752f));
                    v1 = 0.5f * v1 * (1.0f + erff(v1 * 0.70710678118654752f));
                }
                *(float2*)&C[(size_t)r * ncols + col] = make_float2(v0, v1);
            }
        }
    }

    // ---- fused node-attention partial dots ----
    if (as_out) {
        const int head = (H == 8) ? ((n0 >> 5) + wc) : 0;
        #pragma unroll
        for (int i = 0; i < 4; i++) {
            float s1 = 0.f, d1 = 0.f, s2 = 0.f, d2 = 0.f;
            #pragma unroll
            for (int j = 0; j < 4; j++) {
                int col = n0 + wc * 32 + j * 8 + tig * 2;
                float a0 = att_s[col], a1 = att_s[col + 1];
                float b0 = att_d[col], b1 = att_d[col + 1];
                s1 += acc[i][j][0] * a0 + acc[i][j][1] * a1;
                d1 += acc[i][j][0] * b0 + acc[i][j][1] * b1;
                s2 += acc[i][j][2] * a0 + acc[i][j][3] * a1;
                d2 += acc[i][j][2] * b0 + acc[i][j][3] * b1;
            }
            s1 += __shfl_xor_sync(0xffffffffu, s1, 1); s1 += __shfl_xor_sync(0xffffffffu, s1, 2);
            d1 += __shfl_xor_sync(0xffffffffu, d1, 1); d1 += __shfl_xor_sync(0xffffffffu, d1, 2);
            s2 += __shfl_xor_sync(0xffffffffu, s2, 1); s2 += __shfl_xor_sync(0xffffffffu, s2, 2);
            d2 += __shfl_xor_sync(0xffffffffu, d2, 1); d2 += __shfl_xor_sync(0xffffffffu, d2, 2);
            if (tig == 0) {
                int r1 = m0 + wr * 64 + i * 16 + tg;
                int r2 = r1 + 8;
                if (r1 < Nrows) {
                    atomicAdd(&as_out[r1 * H + head], s1);
                    atomicAdd(&ad_out[r1 * H + head], d1);
                }
                if (r2 < Nrows) {
                    atomicAdd(&as_out[r2 * H + head], s2);
                    atomicAdd(&ad_out[r2 * H + head], d2);
                }
            }
        }
    }
}

// ---------------- batched weight transpose (all 5 at once) -------------------
__global__ void transpose_all_k(const float* __restrict__ W1, const float* __restrict__ W2,
                                const float* __restrict__ W3, const float* __restrict__ f1,
                                const float* __restrict__ f2)
{
    __shared__ float t[32][33];
    int z = blockIdx.z;
    const float* W = (z == 0) ? W1 : (z == 1) ? W2 : (z == 2) ? W3 : (z == 3) ? f1 : f2;
    int K = (z == 0) ? 128 : 256;
    int M = (z == 4) ? 32 : 256;
    float* Bt = g_btall + z * 65536;
    int m0 = blockIdx.x * 32, k0 = blockIdx.y * 32;
    if (m0 >= M || k0 >= K) return;
    for (int i = threadIdx.y; i < 32; i += 8) {
        int k = k0 + i, m = m0 + threadIdx.x;
        t[i][threadIdx.x] = (k < K && m < M) ? W[(size_t)k * M + m] : 0.f;
    }
    __syncthreads();
    for (int i = threadIdx.y; i < 32; i += 8) {
        int m = m0 + i, k = k0 + threadIdx.x;
        if (m < M && k < K) Bt[(size_t)m * K + k] = t[threadIdx.x][i];
    }
}

// ---------------- batched Ve ---------------------------------------------------
__global__ void ve_all_k(const float* __restrict__ We1, const float* __restrict__ ae1,
                         const float* __restrict__ We2, const float* __restrict__ ae2,
                         const float* __restrict__ We3, const float* __restrict__ ae3)
{
    int tid = threadIdx.x;
    const float* We; const float* ae; int H, base, loc;
    if (tid < 40)      { We = We1; ae = ae1; H = 8; base = 0;  loc = tid; }
    else if (tid < 80) { We = We2; ae = ae2; H = 8; base = 40; loc = tid - 40; }
    else if (tid < 85) { We = We3; ae = ae3; H = 1; base = 80; loc = tid - 80; }
    else return;
    int d = loc / H, h = loc % H;
    int C = 256 / H;
    float s = 0.0f;
    for (int c = 0; c < C; c++) s += We[d * 256 + h * C + c] * ae[h * C + c];
    g_VeAll[base + loc] = s;
}

// ---------------- zero attention buffers --------------------------------------
__global__ void zero_att_k()
{
    int i = blockIdx.x * blockDim.x + threadIdx.x;
    if (i < NN * 2) {
        ((float4*)g_as)[i] = make_float4(0.f, 0.f, 0.f, 0.f);
        ((float4*)g_ad)[i] = make_float4(0.f, 0.f, 0.f, 0.f);
    }
}

// ---------------- init: deg + pool zero ----------------------------------------
__global__ void init_k()
{
    int i = blockIdx.x * blockDim.x + threadIdx.x;
    if (i < NN) g_deg[i] = 0;
    if (i < GG * 32) g_pool[i] = 0.0f;
    if (i < GG)      g_cnt[i]  = 0.0f;
}

// ---------------- CSR build -----------------------------------------------------
__global__ void hist_k(const int* __restrict__ dst)
{
    int e = blockIdx.x * blockDim.x + threadIdx.x;
    if (e < EE) atomicAdd(&g_deg[dst[e]], 1);
}
__global__ void scan1_k()
{
    __shared__ int s[512];
    int tid = threadIdx.x;
    int i = blockIdx.x * 512 + tid;
    int v = (i < NN) ? g_deg[i] : 0;
    s[tid] = v;
    __syncthreads();
    for (int off = 1; off < 512; off <<= 1) {
        int t = (tid >= off) ? s[tid - off] : 0;
        __syncthreads();
        s[tid] += t;
        __syncthreads();
    }
    if (i < NN) g_rs[i] = s[tid] - v;
    if (tid == 511) g_part[blockIdx.x] = s[511];
}
__global__ void scan2_k(int nb)
{
    __shared__ int s[128];
    int tid = threadIdx.x;
    int v = (tid < nb) ? g_part[tid] : 0;
    s[tid] = v;
    __syncthreads();
    for (int off = 1; off < 128; off <<= 1) {
        int t = (tid >= off) ? s[tid - off] : 0;
        __syncthreads();
        s[tid] += t;
        __syncthreads();
    }
    if (tid < nb) g_part[tid] = s[tid] - v;
}
__global__ void scan3_k()
{
    int i = blockIdx.x * blockDim.x + threadIdx.x;
    if (i >= NN) return;
    int r = g_rs[i] + g_part[i >> 9];
    g_rs[i] = r;
    g_wp[i] = r;
}
__global__ void scatter_k(const int* __restrict__ src, const int* __restrict__ dst,
                          const float* __restrict__ ea)
{
    int e = blockIdx.x * blockDim.x + threadIdx.x;
    if (e >= EE) return;
    int d = dst[e];
    int pos = atomicAdd(&g_wp[d], 1);
    g_csrc[pos] = src[e];
    #pragma unroll
    for (int i = 0; i < 5; i++) g_cea[(size_t)pos * 5 + i] = ea[(size_t)e * 5 + i];
}

// ---------------- fused single-pass edge softmax + aggregation ---------------
template <int H>
__global__ void __launch_bounds__(256)
gat_edge_k(const float* __restrict__ as_, const float* __restrict__ ad_,
           const float* __restrict__ hfeat, const float* __restrict__ bias,
           float* __restrict__ outf, int veBase)
{
    int w = (blockIdx.x * blockDim.x + threadIdx.x) >> 5;
    if (w >= NN) return;
    int lane = threadIdx.x & 31;
    const int head = (H == 8) ? (lane >> 2) : 0;
    const int tig = lane & 3;
    const int col0 = lane * 8;

    float ve[5];
    #pragma unroll
    for (int i = 0; i < 5; i++) ve[i] = g_VeAll[veBase + i * H + head];
    const float adv = ad_[w * H + head];
    const int r0 = g_rs[w], dg = g_deg[w];

    float den = 0.0f;
    float acc[8];
    #pragma unroll
    for (int q = 0; q < 8; q++) acc[q] = 0.0f;

    for (int j = 0; j < dg; j += 4) {
        int jj = j + tig;
        bool valid = jj < dg;
        int je = r0 + (valid ? jj : 0);
        int sq = g_csrc[je];
        const float* ce = g_cea + (size_t)je * 5;
        float a = as_[sq * H + head] + adv;
        #pragma unroll
        for (int i = 0; i < 5; i++) a = fmaf(ce[i], ve[i], a);
        a = a > 0.0f ? a : 0.2f * a;
        float pq = valid ? __expf(a) : 0.0f;
        #pragma unroll
        for (int q = 0; q < 4; q++) {
            float p = __shfl_sync(0xffffffffu, pq, (lane & ~3) | q);
            int s   = __shfl_sync(0xffffffffu, sq, q);
            if (p != 0.0f) {
                den += p;
                const float4* hp = (const float4*)(hfeat + (size_t)s * 256 + col0);
                float4 v0 = hp[0], v1 = hp[1];
                acc[0] = fmaf(p, v0.x, acc[0]); acc[1] = fmaf(p, v0.y, acc[1]);
                acc[2] = fmaf(p, v0.z, acc[2]); acc[3] = fmaf(p, v0.w, acc[3]);
                acc[4] = fmaf(p, v1.x, acc[4]); acc[5] = fmaf(p, v1.y, acc[5]);
                acc[6] = fmaf(p, v1.z, acc[6]); acc[7] = fmaf(p, v1.w, acc[7]);
            }
        }
    }

    float inv = 1.0f / (den + 1e-16f);
    float4 o0, o1;
    float* op = (float*)&o0;
    #pragma unroll
    for (int q = 0; q < 4; q++) op[q] = elu1(acc[q] * inv + bias[col0 + q]);
    op = (float*)&o1;
    #pragma unroll
    for (int q = 0; q < 4; q++) op[q] = elu1(acc[4 + q] * inv + bias[col0 + 4 + q]);
    *(float4*)&outf[(size_t)w * 256 + col0]     = o0;
    *(float4*)&outf[(size_t)w * 256 + col0 + 4] = o1;
}

// ---------------- pooling -----------------------------------------------------
__global__ void pool_acc_k(const float* __restrict__ y, const int* __restrict__ batch, int N)
{
    int idx = blockIdx.x * blockDim.x + threadIdx.x;
    if (idx >= N * 8) return;
    int n = idx >> 3, q = idx & 7;
    int g = batch[n];
    float4 v = ((const float4*)(y + (size_t)n * 32))[q];
    atomicAdd((float4*)&g_pool[g * 32 + q * 4], v);
    if (q == 0) atomicAdd(&g_cnt[g], 1.0f);
}
__global__ void pool_fin_k(float* __restrict__ out)
{
    int t = blockIdx.x * blockDim.x + threadIdx.x;
    if (t < GG * 32) out[t] = g_pool[t] / fmaxf(g_cnt[t >> 5], 1.0f);
}

// ============================================================================
static void launch_gemm(const float* A, const float* bt, float* C,
                        int n, int K, int ncols, const float* bias, int act,
                        const float* att_s = nullptr, const float* att_d = nullptr,
                        float* as_o = nullptr, float* ad_o = nullptr, int H = 8)
{
    dim3 grid((n + 127) / 128, (ncols + 127) / 128);
    mma_gemm_k<<<grid, 256, 2 * BUF32 * sizeof(uint32_t)>>>(
        A, bt, C, n, K, ncols, bias, act, att_s, att_d, as_o, ad_o, H);
}

extern "C" void kernel_launch(void* const* d_in, const int* in_sizes, int n_in,
                              void* d_out, int out_size)
{
    const float* x     = (const float*)d_in[0];
    const int*   ei    = (const int*)  d_in[1];
    const float* ea    = (const float*)d_in[2];
    const int*   batch = (const int*)  d_in[3];
    const float* W1  = (const float*)d_in[4];
    const float* as1 = (const float*)d_in[5];
    const float* ad1 = (const float*)d_in[6];
    const float* We1 = (const float*)d_in[7];
    const float* ae1 = (const float*)d_in[8];
    const float* b1  = (const float*)d_in[9];
    const float* W2  = (const float*)d_in[10];
    const float* as2 = (const float*)d_in[11];
    const float* ad2 = (const float*)d_in[12];
    const float* We2 = (const float*)d_in[13];
    const float* ae2 = (const float*)d_in[14];
    const float* b2  = (const float*)d_in[15];
    const float* W3  = (const float*)d_in[16];
    const float* as3 = (const float*)d_in[17];
    const float* ad3 = (const float*)d_in[18];
    const float* We3 = (const float*)d_in[19];
    const float* ae3 = (const float*)d_in[20];
    const float* b3  = (const float*)d_in[21];
    const float* fcW1 = (const float*)d_in[22];
    const float* fcb1 = (const float*)d_in[23];
    const float* fcW2 = (const float*)d_in[24];
    const float* fcb2 = (const float*)d_in[25];

    const int* src = ei;
    const int* dst = ei + EE;

    float *feat, *h, *agg, *as_, *ad_, *btall;
    cudaGetSymbolAddress((void**)&feat,  g_feat);
    cudaGetSymbolAddress((void**)&h,     g_h);
    cudaGetSymbolAddress((void**)&agg,   g_agg);
    cudaGetSymbolAddress((void**)&as_,   g_as);
    cudaGetSymbolAddress((void**)&ad_,   g_ad);
    cudaGetSymbolAddress((void**)&btall, g_btall);

    cudaFuncSetAttribute(mma_gemm_k, cudaFuncAttributeMaxDynamicSharedMemorySize,
                         2 * BUF32 * sizeof(uint32_t));

    const int nb = (NN + 511) / 512;
    const int gb = (NN * 32 + 255) / 256;
    const int zb = (NN * 2 + 255) / 256;

    // launches 1-5 (ncu -s 5 skips these)
    transpose_all_k<<<dim3(8, 8, 5), dim3(32, 8)>>>(W1, W2, W3, fcW1, fcW2);   // 1
    ve_all_k<<<1, 96>>>(We1, ae1, We2, ae2, We3, ae3);                          // 2
    zero_att_k<<<zb, 256>>>();                                                  // 3
    init_k<<<(NN + 255) / 256, 256>>>();                                        // 4
    hist_k<<<(EE + 255) / 256, 256>>>(dst);                                     // 5

    // launch 6 = GEMM layer 1 (fused node-att) — ncu profiles this one
    launch_gemm(x, btall, h, NN, 128, HC, nullptr, 0, as1, ad1, as_, ad_, 8);   // 6

    // CSR tail
    scan1_k<<<nb, 512>>>();                                                     // 7
    scan2_k<<<1, 128>>>(nb);                                                    // 8
    scan3_k<<<(NN + 255) / 256, 256>>>();                                       // 9
    scatter_k<<<(EE + 255) / 256, 256>>>(src, dst, ea);                         // 10

    // layer 1 edge
    gat_edge_k<8><<<gb, 256>>>(as_, ad_, h, b1, feat, 0);                       // 11

    // layer 2
    zero_att_k<<<zb, 256>>>();                                                  // 12
    launch_gemm(feat, btall + 1 * 65536, h, NN, 256, HC, nullptr, 0,
                as2, ad2, as_, ad_, 8);                                         // 13
    gat_edge_k<8><<<gb, 256>>>(as_, ad_, h, b2, feat, 40);                      // 14

    // layer 3
    zero_att_k<<<zb, 256>>>();                                                  // 15
    launch_gemm(feat, btall + 2 * 65536, h, NN, 256, HC, nullptr, 0,
                as3, ad3, as_, ad_, 1);                                         // 16
    gat_edge_k<1><<<gb, 256>>>(as_, ad_, h, b3, feat, 80);                      // 17

    // MLP head
    launch_gemm(feat, btall + 3 * 65536, h, NN, 256, 256, fcb1, 1);             // 18
    launch_gemm(h, btall + 4 * 65536, agg, NN, 256, 32, fcb2, 0);               // 19

    // global mean pool
    pool_acc_k<<<(NN * 8 + 255) / 256, 256>>>(agg, batch, NN);                  // 20
    pool_fin_k<<<(GG * 32 + 255) / 256, 256>>>((float*)d_out);                  // 21
}

// round 10
// speedup vs baseline: 2.2395x; 1.0520x over previous
#include <cuda_runtime.h>
#include <cuda_bf16.h>
#include <math.h>
#include <stdint.h>

#define NN 50000
#define EE 400000
#define GG 64
#define HC 256

// ---------------- scratch (static device globals) ---------------------------
__device__ float g_feat [NN * HC];
__device__ float g_h    [NN * HC];
__device__ float g_as   [NN * 8];
__device__ float g_ad   [NN * 8];
__device__ float g_VeAll[96];
__device__ float g_pool2[GG * 256];
__device__ float g_cnt  [GG];
__device__ float g_btall[5 * 256 * 256];
// CSR
__device__ int   g_deg [NN];
__device__ int   g_rs  [NN];
__device__ int   g_wp  [NN];
__device__ int   g_part[128];
__device__ int   g_csrc[EE];
__device__ float g_cea [EE * 5];

// ---------------- helpers ---------------------------------------------------
__device__ __forceinline__ float elu1(float x) { return x > 0.0f ? x : expm1f(x); }
__device__ __forceinline__ float gelu1(float x) {
    return 0.5f * x * (1.0f + erff(x * 0.70710678118654752f));
}

__device__ __forceinline__ uint32_t bfpack(float lo_e, float hi_e) {
    uint32_t r;
    asm("cvt.rn.bf16x2.f32 %0, %1, %2;" : "=r"(r) : "f"(hi_e), "f"(lo_e));
    return r;
}
__device__ __forceinline__ float bfround(float x) {
    uint16_t b;
    asm("cvt.rn.bf16.f32 %0, %1;" : "=h"(b) : "f"(x));
    float r;
    asm("cvt.f32.bf16 %0, %1;" : "=f"(r) : "h"(b));
    return r;
}

__device__ __forceinline__ void mma_bf16(float* d, const uint32_t* a,
                                         uint32_t b0, uint32_t b1) {
    asm volatile(
        "mma.sync.aligned.m16n8k16.row.col.f32.bf16.bf16.f32 "
        "{%0,%1,%2,%3}, {%4,%5,%6,%7}, {%8,%9}, {%0,%1,%2,%3};"
        : "+f"(d[0]), "+f"(d[1]), "+f"(d[2]), "+f"(d[3])
        : "r"(a[0]), "r"(a[1]), "r"(a[2]), "r"(a[3]), "r"(b0), "r"(b1));
}

#define LDSM4(r, addr) \
    asm volatile("ldmatrix.sync.aligned.m8n8.x4.shared.b16 {%0,%1,%2,%3}, [%4];" \
        : "=r"((r)[0]), "=r"((r)[1]), "=r"((r)[2]), "=r"((r)[3]) : "r"(addr))

// ---------------- warp-MMA 3xBF16 GEMM, 128x128 CTA tile ---------------------
// Optional epilogues:
//  - as_out/ad_out: per-(row,head-slot) attention dots, PLAIN STORES (slot =
//    n0/32 + wc is a bijection per row; 8-slot layout, no zeroing needed).
//  - pool_out: gelu + segment-sum pooling into [G,256] (fc1+pool fusion);
//    C may be nullptr in that case.
#define S32 12
#define TILE32 (128 * S32)
#define BUF32 (4 * TILE32)

__global__ void __launch_bounds__(256, 2)
mma_gemm_k(const float* __restrict__ A, const float* __restrict__ Bt,
           float* __restrict__ C, int Nrows, int K, int ncols,
           const float* __restrict__ bias, int act,
           const float* __restrict__ att_s, const float* __restrict__ att_d,
           float* __restrict__ as_out, float* __restrict__ ad_out,
           float* __restrict__ pool_out, const int* __restrict__ batchv)
{
    extern __shared__ uint32_t sm32[];
    uint32_t sbase;
    asm("{ .reg .u64 t; cvta.to.shared.u64 t, %1; cvt.u32.u64 %0, t; }"
        : "=r"(sbase) : "l"(sm32));

    const int tid = threadIdx.x;
    const int lane = tid & 31, wid = tid >> 5;
    const int wr = wid >> 2, wc = wid & 3;
    const int tg = lane >> 2, tig = lane & 3;
    const int m0 = blockIdx.x * 128, n0 = blockIdx.y * 128;
    const int jcnt = max(0, min(4, (ncols - n0 - wc * 32 + 7) >> 3));

    const int lr = lane & 7, seg = lane >> 3;
    const uint32_t aoff = (uint32_t)((wr * 64 + lr + (seg & 1) * 8) * S32) * 4
                        + (uint32_t)(seg >> 1) * 16;
    const uint32_t boff = (uint32_t)((wc * 32 + (seg >> 1) * 8 + lr) * S32) * 4
                        + (uint32_t)(seg & 1) * 16;

    float acc[4][4][4];
    #pragma unroll
    for (int i = 0; i < 4; i++)
        #pragma unroll
        for (int j = 0; j < 4; j++)
            #pragma unroll
            for (int q = 0; q < 4; q++) acc[i][j][q] = 0.0f;

    const int nc = K / 16;
    float4 aReg[2], bReg[2];

    auto loadG = [&](int c) {
        const int k0 = c * 16;
        #pragma unroll
        for (int i = 0; i < 2; i++) {
            int idx = tid + i * 256;
            int r = idx >> 2, c4 = (idx & 3) * 4;
            int grow = m0 + r;
            aReg[i] = (grow < Nrows) ? *(const float4*)&A[(size_t)grow * K + k0 + c4]
                                     : make_float4(0.f, 0.f, 0.f, 0.f);
            int gn = n0 + r;
            bReg[i] = (gn < ncols) ? *(const float4*)&Bt[(size_t)gn * K + k0 + c4]
                                   : make_float4(0.f, 0.f, 0.f, 0.f);
        }
    };
    auto storeS = [&](int buf) {
        uint32_t* base = sm32 + buf * BUF32;
        #pragma unroll
        for (int i = 0; i < 2; i++) {
            int idx = tid + i * 256;
            int r = idx >> 2, p32 = (idx & 3) * 2;
            const float* av = (const float*)&aReg[i];
            const float* bv = (const float*)&bReg[i];
            float hx0 = bfround(av[0]), hx1 = bfround(av[1]);
            float hx2 = bfround(av[2]), hx3 = bfround(av[3]);
            uint2 ahi = make_uint2(bfpack(hx0, hx1), bfpack(hx2, hx3));
            uint2 alo = make_uint2(bfpack(av[0] - hx0, av[1] - hx1),
                                   bfpack(av[2] - hx2, av[3] - hx3));
            hx0 = bfround(bv[0]); hx1 = bfround(bv[1]);
            hx2 = bfround(bv[2]); hx3 = bfround(bv[3]);
            uint2 bhi = make_uint2(bfpack(hx0, hx1), bfpack(hx2, hx3));
            uint2 blo = make_uint2(bfpack(bv[0] - hx0, bv[1] - hx1),
                                   bfpack(bv[2] - hx2, bv[3] - hx3));
            int o = r * S32 + p32;
            *(uint2*)(base + o)              = ahi;
            *(uint2*)(base + TILE32 + o)     = alo;
            *(uint2*)(base + 2 * TILE32 + o) = bhi;
            *(uint2*)(base + 3 * TILE32 + o) = blo;
        }
    };
    auto compute = [&](int buf) {
        const uint32_t bb = sbase + (uint32_t)buf * BUF32 * 4;
        const uint32_t a_h = bb + aoff;
        const uint32_t a_l = a_h + TILE32 * 4;
        const uint32_t b_h = bb + 2 * TILE32 * 4 + boff;
        const uint32_t b_l = b_h + TILE32 * 4;

        uint32_t ah[4][4], al[4][4], bh[4][2], bl[4][2];
        #pragma unroll
        for (int i = 0; i < 4; i++) {
            LDSM4(ah[i], a_h + (uint32_t)(i * 16 * S32) * 4);
            LDSM4(al[i], a_l + (uint32_t)(i * 16 * S32) * 4);
        }
        #pragma unroll
        for (int jp = 0; jp < 2; jp++) {
            uint32_t t[4];
            LDSM4(t, b_h + (uint32_t)(jp * 16 * S32) * 4);
            bh[jp * 2][0] = t[0]; bh[jp * 2][1] = t[1];
            bh[jp * 2 + 1][0] = t[2]; bh[jp * 2 + 1][1] = t[3];
            LDSM4(t, b_l + (uint32_t)(jp * 16 * S32) * 4);
            bl[jp * 2][0] = t[0]; bl[jp * 2][1] = t[1];
            bl[jp * 2 + 1][0] = t[2]; bl[jp * 2 + 1][1] = t[3];
        }
        #pragma unroll
        for (int j = 0; j < 4; j++) {
            if (j >= jcnt) break;
            #pragma unroll
            for (int i = 0; i < 4; i++) {
                mma_bf16(acc[i][j], ah[i], bh[j][0], bh[j][1]);
                mma_bf16(acc[i][j], ah[i], bl[j][0], bl[j][1]);
                mma_bf16(acc[i][j], al[i], bh[j][0], bh[j][1]);
            }
        }
    };

    loadG(0); storeS(0);
    __syncthreads();
    for (int c = 0; c < nc; c++) {
        if (c + 1 < nc) loadG(c + 1);
        compute(c & 1);
        if (c + 1 < nc) storeS((c + 1) & 1);
        __syncthreads();
    }

    // ---- C store epilogue ----
    if (C) {
        #pragma unroll
        for (int i = 0; i < 4; i++) {
            int row = m0 + wr * 64 + i * 16 + tg;
            #pragma unroll
            for (int j = 0; j < 4; j++) {
                int col = n0 + wc * 32 + j * 8 + tig * 2;
                if (col >= ncols) continue;
                #pragma unroll
                for (int half = 0; half < 2; half++) {
                    int r = row + half * 8;
                    if (r >= Nrows) continue;
                    float v0 = acc[i][j][half * 2 + 0];
                    float v1 = acc[i][j][half * 2 + 1];
                    if (bias) { v0 += bias[col]; v1 += bias[col + 1]; }
                    if (act == 1) { v0 = gelu1(v0); v1 = gelu1(v1); }
                    *(float2*)&C[(size_t)r * ncols + col] = make_float2(v0, v1);
                }
            }
        }
    }

    // ---- fused node-attention dots (plain stores, 8-slot layout) ----
    if (as_out) {
        const int slot = (n0 >> 5) + wc;
        #pragma unroll
        for (int i = 0; i < 4; i++) {
            float s1 = 0.f, d1 = 0.f, s2 = 0.f, d2 = 0.f;
            #pragma unroll
            for (int j = 0; j < 4; j++) {
                int col = n0 + wc * 32 + j * 8 + tig * 2;
                float a0 = att_s[col], a1 = att_s[col + 1];
                float b0 = att_d[col], b1 = att_d[col + 1];
                s1 += acc[i][j][0] * a0 + acc[i][j][1] * a1;
                d1 += acc[i][j][0] * b0 + acc[i][j][1] * b1;
                s2 += acc[i][j][2] * a0 + acc[i][j][3] * a1;
                d2 += acc[i][j][2] * b0 + acc[i][j][3] * b1;
            }
            s1 += __shfl_xor_sync(0xffffffffu, s1, 1); s1 += __shfl_xor_sync(0xffffffffu, s1, 2);
            d1 += __shfl_xor_sync(0xffffffffu, d1, 1); d1 += __shfl_xor_sync(0xffffffffu, d1, 2);
            s2 += __shfl_xor_sync(0xffffffffu, s2, 1); s2 += __shfl_xor_sync(0xffffffffu, s2, 2);
            d2 += __shfl_xor_sync(0xffffffffu, d2, 1); d2 += __shfl_xor_sync(0xffffffffu, d2, 2);
            if (tig == 0) {
                int r1 = m0 + wr * 64 + i * 16 + tg;
                int r2 = r1 + 8;
                if (r1 < Nrows) { as_out[r1 * 8 + slot] = s1; ad_out[r1 * 8 + slot] = d1; }
                if (r2 < Nrows) { as_out[r2 * 8 + slot] = s2; ad_out[r2 * 8 + slot] = d2; }
            }
        }
    }

    // ---- fused gelu + segment-sum pooling (fc1 + pool) ----
    if (pool_out) {
        const int rbase = m0 + wr * 64;
        bool uniform = (rbase + 63 < Nrows) && (batchv[rbase] == batchv[rbase + 63]);
        if (uniform) {
            int g = batchv[rbase];
            #pragma unroll
            for (int j = 0; j < 4; j++) {
                #pragma unroll
                for (int qc = 0; qc < 2; qc++) {
                    int col = n0 + wc * 32 + j * 8 + tig * 2 + qc;
                    float sum = 0.f;
                    #pragma unroll
                    for (int i = 0; i < 4; i++)
                        #pragma unroll
                        for (int half = 0; half < 2; half++)
                            sum += gelu1(acc[i][j][half * 2 + qc] + bias[col]);
                    atomicAdd(&pool_out[g * 256 + col], sum);
                }
            }
        } else {
            #pragma unroll
            for (int i = 0; i < 4; i++)
                #pragma unroll
                for (int j = 0; j < 4; j++)
                    #pragma unroll
                    for (int q = 0; q < 4; q++) {
                        int r = rbase + i * 16 + tg + (q >> 1) * 8;
                        if (r >= Nrows) continue;
                        int col = n0 + wc * 32 + j * 8 + tig * 2 + (q & 1);
                        float v = gelu1(acc[i][j][q] + bias[col]);
                        atomicAdd(&pool_out[batchv[r] * 256 + col], v);
                    }
        }
    }
}

// ---------------- batched weight transpose (all 5 at once) -------------------
__global__ void transpose_all_k(const float* __restrict__ W1, const float* __restrict__ W2,
                                const float* __restrict__ W3, const float* __restrict__ f1,
                                const float* __restrict__ f2)
{
    __shared__ float t[32][33];
    int z = blockIdx.z;
    const float* W = (z == 0) ? W1 : (z == 1) ? W2 : (z == 2) ? W3 : (z == 3) ? f1 : f2;
    int K = (z == 0) ? 128 : 256;
    int M = (z == 4) ? 32 : 256;
    float* Bt = g_btall + z * 65536;
    int m0 = blockIdx.x * 32, k0 = blockIdx.y * 32;
    if (m0 >= M || k0 >= K) return;
    for (int i = threadIdx.y; i < 32; i += 8) {
        int k = k0 + i, m = m0 + threadIdx.x;
        t[i][threadIdx.x] = (k < K && m < M) ? W[(size_t)k * M + m] : 0.f;
    }
    __syncthreads();
    for (int i = threadIdx.y; i < 32; i += 8) {
        int m = m0 + i, k = k0 + threadIdx.x;
        if (m < M && k < K) Bt[(size_t)m * K + k] = t[threadIdx.x][i];
    }
}

// ---------------- batched Ve ---------------------------------------------------
__global__ void ve_all_k(const float* __restrict__ We1, const float* __restrict__ ae1,
                         const float* __restrict__ We2, const float* __restrict__ ae2,
                         const float* __restrict__ We3, const float* __restrict__ ae3)
{
    int tid = threadIdx.x;
    const float* We; const float* ae; int H, base, loc;
    if (tid < 40)      { We = We1; ae = ae1; H = 8; base = 0;  loc = tid; }
    else if (tid < 80) { We = We2; ae = ae2; H = 8; base = 40; loc = tid - 40; }
    else if (tid < 85) { We = We3; ae = ae3; H = 1; base = 80; loc = tid - 80; }
    else return;
    int d = loc / H, h = loc % H;
    int C = 256 / H;
    float s = 0.0f;
    for (int c = 0; c < C; c++) s += We[d * 256 + h * C + c] * ae[h * C + c];
    g_VeAll[base + loc] = s;
}

// ---------------- init: deg + cnt + pool2 zero ---------------------------------
__global__ void init_k()
{
    int i = blockIdx.x * blockDim.x + threadIdx.x;
    if (i < NN) g_deg[i] = 0;
    if (i < GG * 256) g_pool2[i] = 0.0f;
    if (i < GG)       g_cnt[i]  = 0.0f;
}

// ---------------- CSR build + graph counts --------------------------------------
__global__ void hist_k(const int* __restrict__ dst, const int* __restrict__ batch)
{
    int e = blockIdx.x * blockDim.x + threadIdx.x;
    if (e < EE) atomicAdd(&g_deg[dst[e]], 1);
    if (e < NN) atomicAdd(&g_cnt[batch[e]], 1.0f);
}
__global__ void scan1_k()
{
    __shared__ int s[512];
    int tid = threadIdx.x;
    int i = blockIdx.x * 512 + tid;
    int v = (i < NN) ? g_deg[i] : 0;
    s[tid] = v;
    __syncthreads();
    for (int off = 1; off < 512; off <<= 1) {
        int t = (tid >= off) ? s[tid - off] : 0;
        __syncthreads();
        s[tid] += t;
        __syncthreads();
    }
    if (i < NN) g_rs[i] = s[tid] - v;
    if (tid == 511) g_part[blockIdx.x] = s[511];
}
__global__ void scan2_k(int nb)
{
    __shared__ int s[128];
    int tid = threadIdx.x;
    int v = (tid < nb) ? g_part[tid] : 0;
    s[tid] = v;
    __syncthreads();
    for (int off = 1; off < 128; off <<= 1) {
        int t = (tid >= off) ? s[tid - off] : 0;
        __syncthreads();
        s[tid] += t;
        __syncthreads();
    }
    if (tid < nb) g_part[tid] = s[tid] - v;
}
__global__ void scan3_k()
{
    int i = blockIdx.x * blockDim.x + threadIdx.x;
    if (i >= NN) return;
    int r = g_rs[i] + g_part[i >> 9];
    g_rs[i] = r;
    g_wp[i] = r;
}
__global__ void scatter_k(const int* __restrict__ src, const int* __restrict__ dst,
                          const float* __restrict__ ea)
{
    int e = blockIdx.x * blockDim.x + threadIdx.x;
    if (e >= EE) return;
    int d = dst[e];
    int pos = atomicAdd(&g_wp[d], 1);
    g_csrc[pos] = src[e];
    #pragma unroll
    for (int i = 0; i < 5; i++) g_cea[(size_t)pos * 5 + i] = ea[(size_t)e * 5 + i];
}

// ---------------- fused single-pass edge softmax + aggregation ---------------
// as_/ad_ are 8-slot per node; H=8 reads slot=head, H=1 sums all 8 slots.
template <int H>
__global__ void __launch_bounds__(256)
gat_edge_k(const float* __restrict__ as_, const float* __restrict__ ad_,
           const float* __restrict__ hfeat, const float* __restrict__ bias,
           float* __restrict__ outf, int veBase)
{
    int w = (blockIdx.x * blockDim.x + threadIdx.x) >> 5;
    if (w >= NN) return;
    int lane = threadIdx.x & 31;
    const int head = (H == 8) ? (lane >> 2) : 0;
    const int tig = lane & 3;
    const int col0 = lane * 8;

    float ve[5];
    #pragma unroll
    for (int i = 0; i < 5; i++) ve[i] = g_VeAll[veBase + i * H + head];

    float adv;
    if (H == 1) {
        float4 a0 = *(const float4*)&ad_[w * 8];
        float4 a1 = *(const float4*)&ad_[w * 8 + 4];
        adv = a0.x + a0.y + a0.z + a0.w + a1.x + a1.y + a1.z + a1.w;
    } else {
        adv = ad_[w * 8 + head];
    }
    const int r0 = g_rs[w], dg = g_deg[w];

    float den = 0.0f;
    float acc[8];
    #pragma unroll
    for (int q = 0; q < 8; q++) acc[q] = 0.0f;

    for (int j = 0; j < dg; j += 4) {
        int jj = j + tig;
        bool valid = jj < dg;
        int je = r0 + (valid ? jj : 0);
        int sq = g_csrc[je];
        const float* ce = g_cea + (size_t)je * 5;
        float asv;
        if (H == 1) {
            float4 a0 = *(const float4*)&as_[sq * 8];
            float4 a1 = *(const float4*)&as_[sq * 8 + 4];
            asv = a0.x + a0.y + a0.z + a0.w + a1.x + a1.y + a1.z + a1.w;
        } else {
            asv = as_[sq * 8 + head];
        }
        float a = asv + adv;
        #pragma unroll
        for (int i = 0; i < 5; i++) a = fmaf(ce[i], ve[i], a);
        a = a > 0.0f ? a : 0.2f * a;
        float pq = valid ? __expf(a) : 0.0f;
        #pragma unroll
        for (int q = 0; q < 4; q++) {
            float p = __shfl_sync(0xffffffffu, pq, (lane & ~3) | q);
            int s   = __shfl_sync(0xffffffffu, sq, q);
            if (p != 0.0f) {
                den += p;
                const float4* hp = (const float4*)(hfeat + (size_t)s * 256 + col0);
                float4 v0 = hp[0], v1 = hp[1];
                acc[0] = fmaf(p, v0.x, acc[0]); acc[1] = fmaf(p, v0.y, acc[1]);
                acc[2] = fmaf(p, v0.z, acc[2]); acc[3] = fmaf(p, v0.w, acc[3]);
                acc[4] = fmaf(p, v1.x, acc[4]); acc[5] = fmaf(p, v1.y, acc[5]);
                acc[6] = fmaf(p, v1.z, acc[6]); acc[7] = fmaf(p, v1.w, acc[7]);
            }
        }
    }

    float inv = 1.0f / (den + 1e-16f);
    float4 o0, o1;
    float* op = (float*)&o0;
    #pragma unroll
    for (int q = 0; q < 4; q++) op[q] = elu1(acc[q] * inv + bias[col0 + q]);
    op = (float*)&o1;
    #pragma unroll
    for (int q = 0; q < 4; q++) op[q] = elu1(acc[4 + q] * inv + bias[col0 + 4 + q]);
    *(float4*)&outf[(size_t)w * 256 + col0]     = o0;
    *(float4*)&outf[(size_t)w * 256 + col0 + 4] = o1;
}

// ---------------- final: out[g] = (pool2[g]/cnt[g]) @ fc2^T + b ----------------
__global__ void pool_fin2_k(const float* __restrict__ fc2t,
                            const float* __restrict__ fcb2,
                            float* __restrict__ out)
{
    __shared__ float v[256];
    int g = blockIdx.x, t = threadIdx.x;
    float inv = 1.0f / fmaxf(g_cnt[g], 1.0f);
    v[t] = g_pool2[g * 256 + t] * inv;
    __syncthreads();
    if (t < 32) {
        float s = fcb2[t];
        const float* wrow = fc2t + t * 256;
        #pragma unroll 8
        for (int k = 0; k < 256; k++) s = fmaf(v[k], wrow[k], s);
        out[g * 32 + t] = s;
    }
}

// ============================================================================
static void launch_gemm(const float* A, const float* bt, float* C,
                        int n, int K, int ncols, const float* bias, int act,
                        const float* att_s = nullptr, const float* att_d = nullptr,
                        float* as_o = nullptr, float* ad_o = nullptr,
                        float* pool_o = nullptr, const int* batchv = nullptr)
{
    dim3 grid((n + 127) / 128, (ncols + 127) / 128);
    mma_gemm_k<<<grid, 256, 2 * BUF32 * sizeof(uint32_t)>>>(
        A, bt, C, n, K, ncols, bias, act, att_s, att_d, as_o, ad_o, pool_o, batchv);
}

extern "C" void kernel_launch(void* const* d_in, const int* in_sizes, int n_in,
                              void* d_out, int out_size)
{
    const float* x     = (const float*)d_in[0];
    const int*   ei    = (const int*)  d_in[1];
    const float* ea    = (const float*)d_in[2];
    const int*   batch = (const int*)  d_in[3];
    const float* W1  = (const float*)d_in[4];
    const float* as1 = (const float*)d_in[5];
    const float* ad1 = (const float*)d_in[6];
    const float* We1 = (const float*)d_in[7];
    const float* ae1 = (const float*)d_in[8];
    const float* b1  = (const float*)d_in[9];
    const float* W2  = (const float*)d_in[10];
    const float* as2 = (const float*)d_in[11];
    const float* ad2 = (const float*)d_in[12];
    const float* We2 = (const float*)d_in[13];
    const float* ae2 = (const float*)d_in[14];
    const float* b2  = (const float*)d_in[15];
    const float* W3  = (const float*)d_in[16];
    const float* as3 = (const float*)d_in[17];
    const float* ad3 = (const float*)d_in[18];
    const float* We3 = (const float*)d_in[19];
    const float* ae3 = (const float*)d_in[20];
    const float* b3  = (const float*)d_in[21];
    const float* fcW1 = (const float*)d_in[22];
    const float* fcb1 = (const float*)d_in[23];
    const float* fcW2 = (const float*)d_in[24];
    const float* fcb2 = (const float*)d_in[25];

    const int* src = ei;
    const int* dst = ei + EE;

    float *feat, *h, *as_, *ad_, *btall, *pool2;
    cudaGetSymbolAddress((void**)&feat,  g_feat);
    cudaGetSymbolAddress((void**)&h,     g_h);
    cudaGetSymbolAddress((void**)&as_,   g_as);
    cudaGetSymbolAddress((void**)&ad_,   g_ad);
    cudaGetSymbolAddress((void**)&btall, g_btall);
    cudaGetSymbolAddress((void**)&pool2, g_pool2);

    cudaFuncSetAttribute(mma_gemm_k, cudaFuncAttributeMaxDynamicSharedMemorySize,
                         2 * BUF32 * sizeof(uint32_t));

    const int nb = (NN + 511) / 512;
    const int gb = (NN * 32 + 255) / 256;

    transpose_all_k<<<dim3(8, 8, 5), dim3(32, 8)>>>(W1, W2, W3, fcW1, fcW2);
    ve_all_k<<<1, 96>>>(We1, ae1, We2, ae2, We3, ae3);
    init_k<<<(NN + 255) / 256, 256>>>();
    hist_k<<<(EE + 255) / 256, 256>>>(dst, batch);

    // layer 1 GEMM (fused node-att, plain stores — no zeroing needed)
    launch_gemm(x, btall, h, NN, 128, HC, nullptr, 0, as1, ad1, as_, ad_);

    // CSR tail
    scan1_k<<<nb, 512>>>();
    scan2_k<<<1, 128>>>(nb);
    scan3_k<<<(NN + 255) / 256, 256>>>();
    scatter_k<<<(EE + 255) / 256, 256>>>(src, dst, ea);

    gat_edge_k<8><<<gb, 256>>>(as_, ad_, h, b1, feat, 0);

    // layer 2
    launch_gemm(feat, btall + 1 * 65536, h, NN, 256, HC, nullptr, 0, as2, ad2, as_, ad_);
    gat_edge_k<8><<<gb, 256>>>(as_, ad_, h, b2, feat, 40);

    // layer 3 (H=1: 8 partial slots, summed in edge kernel)
    launch_gemm(feat, btall + 2 * 65536, h, NN, 256, HC, nullptr, 0, as3, ad3, as_, ad_);
    gat_edge_k<1><<<gb, 256>>>(as_, ad_, h, b3, feat, 80);

    // fc1 + gelu + pooling fused (no C output); then tiny (pool/cnt)@fc2
    launch_gemm(feat, btall + 3 * 65536, nullptr, NN, 256, 256, fcb1, 1,
                nullptr, nullptr, nullptr, nullptr, pool2, batch);
    pool_fin2_k<<<GG, 256>>>(btall + 4 * 65536, fcb2, (float*)d_out);
}

// round 11
// speedup vs baseline: 2.3635x; 1.0553x over previous
#include <cuda_runtime.h>
#include <cuda_bf16.h>
#include <math.h>
#include <stdint.h>

#define NN 50000
#define EE 400000
#define GG 64
#define HC 256

// ---------------- scratch (static device globals) ---------------------------
__device__ float g_feat [NN * HC];
__device__ float g_h    [NN * HC];
__device__ float g_as   [NN * 8];
__device__ float g_ad   [NN * 8];
__device__ float g_VeAll[96];
__device__ float g_pool2[GG * 256];
__device__ float g_btall[5 * 256 * 256];
// CSR
__device__ int   g_deg [NN];
__device__ int   g_rs  [NN];
__device__ int   g_wp  [NN];
__device__ int   g_part[128];
__device__ int   g_csrc[EE];
__device__ float g_cea [EE * 5];

// ---------------- helpers ---------------------------------------------------
__device__ __forceinline__ float elu1(float x) { return x > 0.0f ? x : expm1f(x); }
__device__ __forceinline__ float gelu1(float x) {
    return 0.5f * x * (1.0f + erff(x * 0.70710678118654752f));
}

__device__ __forceinline__ uint32_t bfpack(float lo_e, float hi_e) {
    uint32_t r;
    asm("cvt.rn.bf16x2.f32 %0, %1, %2;" : "=r"(r) : "f"(hi_e), "f"(lo_e));
    return r;
}
__device__ __forceinline__ float bfround(float x) {
    uint16_t b;
    asm("cvt.rn.bf16.f32 %0, %1;" : "=h"(b) : "f"(x));
    float r;
    asm("cvt.f32.bf16 %0, %1;" : "=f"(r) : "h"(b));
    return r;
}

__device__ __forceinline__ void mma_bf16(float* d, const uint32_t* a,
                                         uint32_t b0, uint32_t b1) {
    asm volatile(
        "mma.sync.aligned.m16n8k16.row.col.f32.bf16.bf16.f32 "
        "{%0,%1,%2,%3}, {%4,%5,%6,%7}, {%8,%9}, {%0,%1,%2,%3};"
        : "+f"(d[0]), "+f"(d[1]), "+f"(d[2]), "+f"(d[3])
        : "r"(a[0]), "r"(a[1]), "r"(a[2]), "r"(a[3]), "r"(b0), "r"(b1));
}

#define LDSM4(r, addr) \
    asm volatile("ldmatrix.sync.aligned.m8n8.x4.shared.b16 {%0,%1,%2,%3}, [%4];" \
        : "=r"((r)[0]), "=r"((r)[1]), "=r"((r)[2]), "=r"((r)[3]) : "r"(addr))

// ---------------- warp-MMA 3xBF16 GEMM, 128x128 CTA tile ---------------------
#define S32 12
#define TILE32 (128 * S32)
#define BUF32 (4 * TILE32)

__global__ void __launch_bounds__(256, 2)
mma_gemm_k(const float* __restrict__ A, const float* __restrict__ Bt,
           float* __restrict__ C, int Nrows, int K, int ncols,
           const float* __restrict__ bias, int act,
           const float* __restrict__ att_s, const float* __restrict__ att_d,
           float* __restrict__ as_out, float* __restrict__ ad_out,
           float* __restrict__ pool_out, const int* __restrict__ batchv)
{
    extern __shared__ uint32_t sm32[];
    uint32_t sbase;
    asm("{ .reg .u64 t; cvta.to.shared.u64 t, %1; cvt.u32.u64 %0, t; }"
        : "=r"(sbase) : "l"(sm32));

    const int tid = threadIdx.x;
    const int lane = tid & 31, wid = tid >> 5;
    const int wr = wid >> 2, wc = wid & 3;
    const int tg = lane >> 2, tig = lane & 3;
    const int m0 = blockIdx.x * 128, n0 = blockIdx.y * 128;
    const int jcnt = max(0, min(4, (ncols - n0 - wc * 32 + 7) >> 3));

    const int lr = lane & 7, seg = lane >> 3;
    const uint32_t aoff = (uint32_t)((wr * 64 + lr + (seg & 1) * 8) * S32) * 4
                        + (uint32_t)(seg >> 1) * 16;
    const uint32_t boff = (uint32_t)((wc * 32 + (seg >> 1) * 8 + lr) * S32) * 4
                        + (uint32_t)(seg & 1) * 16;

    float acc[4][4][4];
    #pragma unroll
    for (int i = 0; i < 4; i++)
        #pragma unroll
        for (int j = 0; j < 4; j++)
            #pragma unroll
            for (int q = 0; q < 4; q++) acc[i][j][q] = 0.0f;

    const int nc = K / 16;
    float4 aReg[2], bReg[2];

    auto loadG = [&](int c) {
        const int k0 = c * 16;
        #pragma unroll
        for (int i = 0; i < 2; i++) {
            int idx = tid + i * 256;
            int r = idx >> 2, c4 = (idx & 3) * 4;
            int grow = m0 + r;
            aReg[i] = (grow < Nrows) ? *(const float4*)&A[(size_t)grow * K + k0 + c4]
                                     : make_float4(0.f, 0.f, 0.f, 0.f);
            int gn = n0 + r;
            bReg[i] = (gn < ncols) ? *(const float4*)&Bt[(size_t)gn * K + k0 + c4]
                                   : make_float4(0.f, 0.f, 0.f, 0.f);
        }
    };
    auto storeS = [&](int buf) {
        uint32_t* base = sm32 + buf * BUF32;
        #pragma unroll
        for (int i = 0; i < 2; i++) {
            int idx = tid + i * 256;
            int r = idx >> 2, p32 = (idx & 3) * 2;
            const float* av = (const float*)&aReg[i];
            const float* bv = (const float*)&bReg[i];
            float hx0 = bfround(av[0]), hx1 = bfround(av[1]);
            float hx2 = bfround(av[2]), hx3 = bfround(av[3]);
            uint2 ahi = make_uint2(bfpack(hx0, hx1), bfpack(hx2, hx3));
            uint2 alo = make_uint2(bfpack(av[0] - hx0, av[1] - hx1),
                                   bfpack(av[2] - hx2, av[3] - hx3));
            hx0 = bfround(bv[0]); hx1 = bfround(bv[1]);
            hx2 = bfround(bv[2]); hx3 = bfround(bv[3]);
            uint2 bhi = make_uint2(bfpack(hx0, hx1), bfpack(hx2, hx3));
            uint2 blo = make_uint2(bfpack(bv[0] - hx0, bv[1] - hx1),
                                   bfpack(bv[2] - hx2, bv[3] - hx3));
            int o = r * S32 + p32;
            *(uint2*)(base + o)              = ahi;
            *(uint2*)(base + TILE32 + o)     = alo;
            *(uint2*)(base + 2 * TILE32 + o) = bhi;
            *(uint2*)(base + 3 * TILE32 + o) = blo;
        }
    };
    auto compute = [&](int buf) {
        const uint32_t bb = sbase + (uint32_t)buf * BUF32 * 4;
        const uint32_t a_h = bb + aoff;
        const uint32_t a_l = a_h + TILE32 * 4;
        const uint32_t b_h = bb + 2 * TILE32 * 4 + boff;
        const uint32_t b_l = b_h + TILE32 * 4;

        uint32_t ah[4][4], al[4][4], bh[4][2], bl[4][2];
        #pragma unroll
        for (int i = 0; i < 4; i++) {
            LDSM4(ah[i], a_h + (uint32_t)(i * 16 * S32) * 4);
            LDSM4(al[i], a_l + (uint32_t)(i * 16 * S32) * 4);
        }
        #pragma unroll
        for (int jp = 0; jp < 2; jp++) {
            uint32_t t[4];
            LDSM4(t, b_h + (uint32_t)(jp * 16 * S32) * 4);
            bh[jp * 2][0] = t[0]; bh[jp * 2][1] = t[1];
            bh[jp * 2 + 1][0] = t[2]; bh[jp * 2 + 1][1] = t[3];
            LDSM4(t, b_l + (uint32_t)(jp * 16 * S32) * 4);
            bl[jp * 2][0] = t[0]; bl[jp * 2][1] = t[1];
            bl[jp * 2 + 1][0] = t[2]; bl[jp * 2 + 1][1] = t[3];
        }
        #pragma unroll
        for (int j = 0; j < 4; j++) {
            if (j >= jcnt) break;
            #pragma unroll
            for (int i = 0; i < 4; i++) {
                mma_bf16(acc[i][j], ah[i], bh[j][0], bh[j][1]);
                mma_bf16(acc[i][j], ah[i], bl[j][0], bl[j][1]);
                mma_bf16(acc[i][j], al[i], bh[j][0], bh[j][1]);
            }
        }
    };

    loadG(0); storeS(0);
    __syncthreads();
    for (int c = 0; c < nc; c++) {
        if (c + 1 < nc) loadG(c + 1);
        compute(c & 1);
        if (c + 1 < nc) storeS((c + 1) & 1);
        __syncthreads();
    }

    // ---- C store epilogue ----
    if (C) {
        #pragma unroll
        for (int i = 0; i < 4; i++) {
            int row = m0 + wr * 64 + i * 16 + tg;
            #pragma unroll
            for (int j = 0; j < 4; j++) {
                int col = n0 + wc * 32 + j * 8 + tig * 2;
                if (col >= ncols) continue;
                #pragma unroll
                for (int half = 0; half < 2; half++) {
                    int r = row + half * 8;
                    if (r >= Nrows) continue;
                    float v0 = acc[i][j][half * 2 + 0];
                    float v1 = acc[i][j][half * 2 + 1];
                    if (bias) { v0 += bias[col]; v1 += bias[col + 1]; }
                    if (act == 1) { v0 = gelu1(v0); v1 = gelu1(v1); }
                    *(float2*)&C[(size_t)r * ncols + col] = make_float2(v0, v1);
                }
            }
        }
    }

    // ---- fused node-attention dots (plain stores, 8-slot layout) ----
    if (as_out) {
        const int slot = (n0 >> 5) + wc;
        #pragma unroll
        for (int i = 0; i < 4; i++) {
            float s1 = 0.f, d1 = 0.f, s2 = 0.f, d2 = 0.f;
            #pragma unroll
            for (int j = 0; j < 4; j++) {
                int col = n0 + wc * 32 + j * 8 + tig * 2;
                float a0 = att_s[col], a1 = att_s[col + 1];
                float b0 = att_d[col], b1 = att_d[col + 1];
                s1 += acc[i][j][0] * a0 + acc[i][j][1] * a1;
                d1 += acc[i][j][0] * b0 + acc[i][j][1] * b1;
                s2 += acc[i][j][2] * a0 + acc[i][j][3] * a1;
                d2 += acc[i][j][2] * b0 + acc[i][j][3] * b1;
            }
            s1 += __shfl_xor_sync(0xffffffffu, s1, 1); s1 += __shfl_xor_sync(0xffffffffu, s1, 2);
            d1 += __shfl_xor_sync(0xffffffffu, d1, 1); d1 += __shfl_xor_sync(0xffffffffu, d1, 2);
            s2 += __shfl_xor_sync(0xffffffffu, s2, 1); s2 += __shfl_xor_sync(0xffffffffu, s2, 2);
            d2 += __shfl_xor_sync(0xffffffffu, d2, 1); d2 += __shfl_xor_sync(0xffffffffu, d2, 2);
            if (tig == 0) {
                int r1 = m0 + wr * 64 + i * 16 + tg;
                int r2 = r1 + 8;
                if (r1 < Nrows) { as_out[r1 * 8 + slot] = s1; ad_out[r1 * 8 + slot] = d1; }
                if (r2 < Nrows) { as_out[r2 * 8 + slot] = s2; ad_out[r2 * 8 + slot] = d2; }
            }
        }
    }

    // ---- fused gelu + segment-sum pooling (fc1 + pool) ----
    if (pool_out) {
        const int rbase = m0 + wr * 64;
        bool uniform = (rbase + 63 < Nrows) && (batchv[rbase] == batchv[rbase + 63]);
        if (uniform) {
            int g = batchv[rbase];
            #pragma unroll
            for (int j = 0; j < 4; j++) {
                #pragma unroll
                for (int qc = 0; qc < 2; qc++) {
                    int col = n0 + wc * 32 + j * 8 + tig * 2 + qc;
                    float sum = 0.f;
                    #pragma unroll
                    for (int i = 0; i < 4; i++)
                        #pragma unroll
                        for (int half = 0; half < 2; half++)
                            sum += gelu1(acc[i][j][half * 2 + qc] + bias[col]);
                    atomicAdd(&pool_out[g * 256 + col], sum);
                }
            }
        } else {
            #pragma unroll
            for (int i = 0; i < 4; i++)
                #pragma unroll
                for (int j = 0; j < 4; j++)
                    #pragma unroll
                    for (int q = 0; q < 4; q++) {
                        int r = rbase + i * 16 + tg + (q >> 1) * 8;
                        if (r >= Nrows) continue;
                        int col = n0 + wc * 32 + j * 8 + tig * 2 + (q & 1);
                        float v = gelu1(acc[i][j][q] + bias[col]);
                        atomicAdd(&pool_out[batchv[r] * 256 + col], v);
                    }
        }
    }
}

// ---------------- batched weight transpose (all 5 at once) -------------------
__global__ void transpose_all_k(const float* __restrict__ W1, const float* __restrict__ W2,
                                const float* __restrict__ W3, const float* __restrict__ f1,
                                const float* __restrict__ f2)
{
    __shared__ float t[32][33];
    int z = blockIdx.z;
    const float* W = (z == 0) ? W1 : (z == 1) ? W2 : (z == 2) ? W3 : (z == 3) ? f1 : f2;
    int K = (z == 0) ? 128 : 256;
    int M = (z == 4) ? 32 : 256;
    float* Bt = g_btall + z * 65536;
    int m0 = blockIdx.x * 32, k0 = blockIdx.y * 32;
    if (m0 >= M || k0 >= K) return;
    for (int i = threadIdx.y; i < 32; i += 8) {
        int k = k0 + i, m = m0 + threadIdx.x;
        t[i][threadIdx.x] = (k < K && m < M) ? W[(size_t)k * M + m] : 0.f;
    }
    __syncthreads();
    for (int i = threadIdx.y; i < 32; i += 8) {
        int m = m0 + i, k = k0 + threadIdx.x;
        if (m < M && k < K) Bt[(size_t)m * K + k] = t[threadIdx.x][i];
    }
}

// ---------------- batched Ve ---------------------------------------------------
__global__ void ve_all_k(const float* __restrict__ We1, const float* __restrict__ ae1,
                         const float* __restrict__ We2, const float* __restrict__ ae2,
                         const float* __restrict__ We3, const float* __restrict__ ae3)
{
    int tid = threadIdx.x;
    const float* We; const float* ae; int H, base, loc;
    if (tid < 40)      { We = We1; ae = ae1; H = 8; base = 0;  loc = tid; }
    else if (tid < 80) { We = We2; ae = ae2; H = 8; base = 40; loc = tid - 40; }
    else if (tid < 85) { We = We3; ae = ae3; H = 1; base = 80; loc = tid - 80; }
    else return;
    int d = loc / H, h = loc % H;
    int C = 256 / H;
    float s = 0.0f;
    for (int c = 0; c < C; c++) s += We[d * 256 + h * C + c] * ae[h * C + c];
    g_VeAll[base + loc] = s;
}

// ---------------- init: deg + pool2 zero ----------------------------------------
__global__ void init_k()
{
    int i = blockIdx.x * blockDim.x + threadIdx.x;
    if (i < NN) g_deg[i] = 0;
    if (i < GG * 256) g_pool2[i] = 0.0f;
}

// ---------------- CSR build ------------------------------------------------------
__global__ void hist_k(const int* __restrict__ dst)
{
    int e = blockIdx.x * blockDim.x + threadIdx.x;
    if (e < EE) atomicAdd(&g_deg[dst[e]], 1);
}
__global__ void scan1_k()
{
    __shared__ int s[512];
    int tid = threadIdx.x;
    int i = blockIdx.x * 512 + tid;
    int v = (i < NN) ? g_deg[i] : 0;
    s[tid] = v;
    __syncthreads();
    for (int off = 1; off < 512; off <<= 1) {
        int t = (tid >= off) ? s[tid - off] : 0;
        __syncthreads();
        s[tid] += t;
        __syncthreads();
    }
    if (i < NN) g_rs[i] = s[tid] - v;
    if (tid == 511) g_part[blockIdx.x] = s[511];
}
__global__ void scan2_k(int nb)
{
    __shared__ int s[128];
    int tid = threadIdx.x;
    int v = (tid < nb) ? g_part[tid] : 0;
    s[tid] = v;
    __syncthreads();
    for (int off = 1; off < 128; off <<= 1) {
        int t = (tid >= off) ? s[tid - off] : 0;
        __syncthreads();
        s[tid] += t;
        __syncthreads();
    }
    if (tid < nb) g_part[tid] = s[tid] - v;
}
__global__ void scan3_k()
{
    int i = blockIdx.x * blockDim.x + threadIdx.x;
    if (i >= NN) return;
    int r = g_rs[i] + g_part[i >> 9];
    g_rs[i] = r;
    g_wp[i] = r;
}
__global__ void scatter_k(const int* __restrict__ src, const int* __restrict__ dst,
                          const float* __restrict__ ea)
{
    int e = blockIdx.x * blockDim.x + threadIdx.x;
    if (e >= EE) return;
    int d = dst[e];
    int pos = atomicAdd(&g_wp[d], 1);
    g_csrc[pos] = src[e];
    #pragma unroll
    for (int i = 0; i < 5; i++) g_cea[(size_t)pos * 5 + i] = ea[(size_t)e * 5 + i];
}

// ---------------- fused single-pass edge softmax + aggregation ---------------
template <int H>
__global__ void __launch_bounds__(256)
gat_edge_k(const float* __restrict__ as_, const float* __restrict__ ad_,
           const float* __restrict__ hfeat, const float* __restrict__ bias,
           float* __restrict__ outf, int veBase)
{
    int w = (blockIdx.x * blockDim.x + threadIdx.x) >> 5;
    if (w >= NN) return;
    int lane = threadIdx.x & 31;
    const int head = (H == 8) ? (lane >> 2) : 0;
    const int tig = lane & 3;
    const int col0 = lane * 8;

    float ve[5];
    #pragma unroll
    for (int i = 0; i < 5; i++) ve[i] = g_VeAll[veBase + i * H + head];

    float adv;
    if (H == 1) {
        float4 a0 = *(const float4*)&ad_[w * 8];
        float4 a1 = *(const float4*)&ad_[w * 8 + 4];
        adv = a0.x + a0.y + a0.z + a0.w + a1.x + a1.y + a1.z + a1.w;
    } else {
        adv = ad_[w * 8 + head];
    }
    const int r0 = g_rs[w], dg = g_deg[w];

    float den = 0.0f;
    float acc[8];
    #pragma unroll
    for (int q = 0; q < 8; q++) acc[q] = 0.0f;

    for (int j = 0; j < dg; j += 4) {
        int jj = j + tig;
        bool valid = jj < dg;
        int je = r0 + (valid ? jj : 0);
        int sq = g_csrc[je];
        const float* ce = g_cea + (size_t)je * 5;
        float asv;
        if (H == 1) {
            float4 a0 = *(const float4*)&as_[sq * 8];
            float4 a1 = *(const float4*)&as_[sq * 8 + 4];
            asv = a0.x + a0.y + a0.z + a0.w + a1.x + a1.y + a1.z + a1.w;
        } else {
            asv = as_[sq * 8 + head];
        }
        float a = asv + adv;
        #pragma unroll
        for (int i = 0; i < 5; i++) a = fmaf(ce[i], ve[i], a);
        a = a > 0.0f ? a : 0.2f * a;
        float pq = valid ? __expf(a) : 0.0f;
        #pragma unroll
        for (int q = 0; q < 4; q++) {
            float p = __shfl_sync(0xffffffffu, pq, (lane & ~3) | q);
            int s   = __shfl_sync(0xffffffffu, sq, q);
            if (p != 0.0f) {
                den += p;
                const float4* hp = (const float4*)(hfeat + (size_t)s * 256 + col0);
                float4 v0 = hp[0], v1 = hp[1];
                acc[0] = fmaf(p, v0.x, acc[0]); acc[1] = fmaf(p, v0.y, acc[1]);
                acc[2] = fmaf(p, v0.z, acc[2]); acc[3] = fmaf(p, v0.w, acc[3]);
                acc[4] = fmaf(p, v1.x, acc[4]); acc[5] = fmaf(p, v1.y, acc[5]);
                acc[6] = fmaf(p, v1.z, acc[6]); acc[7] = fmaf(p, v1.w, acc[7]);
            }
        }
    }

    float inv = 1.0f / (den + 1e-16f);
    float4 o0, o1;
    float* op = (float*)&o0;
    #pragma unroll
    for (int q = 0; q < 4; q++) op[q] = elu1(acc[q] * inv + bias[col0 + q]);
    op = (float*)&o1;
    #pragma unroll
    for (int q = 0; q < 4; q++) op[q] = elu1(acc[4 + q] * inv + bias[col0 + 4 + q]);
    *(float4*)&outf[(size_t)w * 256 + col0]     = o0;
    *(float4*)&outf[(size_t)w * 256 + col0 + 4] = o1;
}

// ---------------- final: out[g] = (pool2[g]/cnt[g]) @ fc2^T + b ----------------
// cnt via binary search in sorted batch (no atomics anywhere).
__global__ void pool_fin2_k(const int* __restrict__ batch,
                            const float* __restrict__ fc2t,
                            const float* __restrict__ fcb2,
                            float* __restrict__ out)
{
    __shared__ float v[256];
    __shared__ float sinv;
    int g = blockIdx.x, t = threadIdx.x;
    if (t == 0) {
        int a = 0, b = NN;
        while (a < b) { int m = (a + b) >> 1; if (batch[m] < g) a = m + 1; else b = m; }
        int lo = a;
        a = lo; b = NN;
        while (a < b) { int m = (a + b) >> 1; if (batch[m] < g + 1) a = m + 1; else b = m; }
        sinv = 1.0f / fmaxf((float)(a - lo), 1.0f);
    }
    __syncthreads();
    v[t] = g_pool2[g * 256 + t] * sinv;
    __syncthreads();
    if (t < 32) {
        float s = fcb2[t];
        const float* wrow = fc2t + t * 256;
        #pragma unroll 8
        for (int k = 0; k < 256; k++) s = fmaf(v[k], wrow[k], s);
        out[g * 32 + t] = s;
    }
}

// ============================================================================
static void launch_gemm(const float* A, const float* bt, float* C,
                        int n, int K, int ncols, const float* bias, int act,
                        const float* att_s = nullptr, const float* att_d = nullptr,
                        float* as_o = nullptr, float* ad_o = nullptr,
                        float* pool_o = nullptr, const int* batchv = nullptr)
{
    dim3 grid((n + 127) / 128, (ncols + 127) / 128);
    mma_gemm_k<<<grid, 256, 2 * BUF32 * sizeof(uint32_t)>>>(
        A, bt, C, n, K, ncols, bias, act, att_s, att_d, as_o, ad_o, pool_o, batchv);
}

extern "C" void kernel_launch(void* const* d_in, const int* in_sizes, int n_in,
                              void* d_out, int out_size)
{
    const float* x     = (const float*)d_in[0];
    const int*   ei    = (const int*)  d_in[1];
    const float* ea    = (const float*)d_in[2];
    const int*   batch = (const int*)  d_in[3];
    const float* W1  = (const float*)d_in[4];
    const float* as1 = (const float*)d_in[5];
    const float* ad1 = (const float*)d_in[6];
    const float* We1 = (const float*)d_in[7];
    const float* ae1 = (const float*)d_in[8];
    const float* b1  = (const float*)d_in[9];
    const float* W2  = (const float*)d_in[10];
    const float* as2 = (const float*)d_in[11];
    const float* ad2 = (const float*)d_in[12];
    const float* We2 = (const float*)d_in[13];
    const float* ae2 = (const float*)d_in[14];
    const float* b2  = (const float*)d_in[15];
    const float* W3  = (const float*)d_in[16];
    const float* as3 = (const float*)d_in[17];
    const float* ad3 = (const float*)d_in[18];
    const float* We3 = (const float*)d_in[19];
    const float* ae3 = (const float*)d_in[20];
    const float* b3  = (const float*)d_in[21];
    const float* fcW1 = (const float*)d_in[22];
    const float* fcb1 = (const float*)d_in[23];
    const float* fcW2 = (const float*)d_in[24];
    const float* fcb2 = (const float*)d_in[25];

    const int* src = ei;
    const int* dst = ei + EE;

    float *feat, *h, *as_, *ad_, *btall, *pool2;
    cudaGetSymbolAddress((void**)&feat,  g_feat);
    cudaGetSymbolAddress((void**)&h,     g_h);
    cudaGetSymbolAddress((void**)&as_,   g_as);
    cudaGetSymbolAddress((void**)&ad_,   g_ad);
    cudaGetSymbolAddress((void**)&btall, g_btall);
    cudaGetSymbolAddress((void**)&pool2, g_pool2);

    cudaFuncSetAttribute(mma_gemm_k, cudaFuncAttributeMaxDynamicSharedMemorySize,
                         2 * BUF32 * sizeof(uint32_t));

    const int nb = (NN + 511) / 512;
    const int gb = (NN * 32 + 255) / 256;

    transpose_all_k<<<dim3(8, 8, 5), dim3(32, 8)>>>(W1, W2, W3, fcW1, fcW2);
    ve_all_k<<<1, 96>>>(We1, ae1, We2, ae2, We3, ae3);
    init_k<<<(NN + 255) / 256, 256>>>();
    hist_k<<<(EE + 255) / 256, 256>>>(dst);

    // layer 1 GEMM (fused node-att)
    launch_gemm(x, btall, h, NN, 128, HC, nullptr, 0, as1, ad1, as_, ad_);

    // CSR tail
    scan1_k<<<nb, 512>>>();
    scan2_k<<<1, 128>>>(nb);
    scan3_k<<<(NN + 255) / 256, 256>>>();
    scatter_k<<<(EE + 255) / 256, 256>>>(src, dst, ea);

    gat_edge_k<8><<<gb, 256>>>(as_, ad_, h, b1, feat, 0);

    // layer 2
    launch_gemm(feat, btall + 1 * 65536, h, NN, 256, HC, nullptr, 0, as2, ad2, as_, ad_);
    gat_edge_k<8><<<gb, 256>>>(as_, ad_, h, b2, feat, 40);

    // layer 3 (H=1: 8 partial slots, summed in edge kernel)
    launch_gemm(feat, btall + 2 * 65536, h, NN, 256, HC, nullptr, 0, as3, ad3, as_, ad_);
    gat_edge_k<1><<<gb, 256>>>(as_, ad_, h, b3, feat, 80);

    // fc1 + gelu + pooling fused; then tiny (pool/cnt)@fc2 with bsearch counts
    launch_gemm(feat, btall + 3 * 65536, nullptr, NN, 256, 256, fcb1, 1,
                nullptr, nullptr, nullptr, nullptr, pool2, batch);
    pool_fin2_k<<<GG, 256>>>(batch, btall + 4 * 65536, fcb2, (float*)d_out);
}